// round 1
// baseline (speedup 1.0000x reference)
#include <cuda_runtime.h>
#include <cuda_bf16.h>
#include <math.h>
#include <float.h>

// Problem constants
#define HIDDEN    2048
#define NUM_HEADS 16
#define NUM_KV    8
#define HEAD_DIM  128
#define Q_SIZE    (NUM_HEADS * HEAD_DIM)        // 2048
#define KV_SIZE   (NUM_KV * HEAD_DIM)           // 1024
#define QKV_COLS  (Q_SIZE + 2 * KV_SIZE)        // 4096
#define SCALE     0.08838834764831845f          // 128^-0.5
#define RMS_EPS   1e-6f

#define MAX_T 4096

// Scratch (static device globals — no runtime allocation allowed)
__device__ float g_qkv[(size_t)MAX_T * QKV_COLS];   // 64 MB
__device__ float g_attn[(size_t)MAX_T * Q_SIZE];    // 32 MB

// ---------------------------------------------------------------------------
// GEMM: C[M,N] = A[M,K] * B[N,K]^T   (fp32, tiled 64x64x16, 4x4 microtiles)
// Assumes M%64==0, N%64==0, K%16==0.
// ---------------------------------------------------------------------------
#define GBM 64
#define GBN 64
#define GBK 16

__global__ __launch_bounds__(256) void gemm_nt(
    const float* __restrict__ A, const float* __restrict__ B,
    float* __restrict__ C, int M, int N, int K)
{
    __shared__ float As[GBK][GBM + 4];
    __shared__ float Bs[GBK][GBN + 4];

    const int tid = threadIdx.x;
    const int bm = blockIdx.y * GBM;
    const int bn = blockIdx.x * GBN;
    const int ty = tid >> 4;       // 0..15
    const int tx = tid & 15;       // 0..15

    // Loader mapping: each thread loads one float4 of A and B per k-block
    const int lr = tid >> 2;           // 0..63
    const int lc = (tid & 3) * 4;      // 0,4,8,12

    float acc[4][4] = {};

    for (int k0 = 0; k0 < K; k0 += GBK) {
        float4 a4 = *(const float4*)&A[(size_t)(bm + lr) * K + k0 + lc];
        float4 b4 = *(const float4*)&B[(size_t)(bn + lr) * K + k0 + lc];
        __syncthreads();   // prior iteration finished reading smem
        As[lc + 0][lr] = a4.x; As[lc + 1][lr] = a4.y;
        As[lc + 2][lr] = a4.z; As[lc + 3][lr] = a4.w;
        Bs[lc + 0][lr] = b4.x; Bs[lc + 1][lr] = b4.y;
        Bs[lc + 2][lr] = b4.z; Bs[lc + 3][lr] = b4.w;
        __syncthreads();

        #pragma unroll
        for (int kk = 0; kk < GBK; kk++) {
            float4 av = *(const float4*)&As[kk][ty * 4];
            float4 bv = *(const float4*)&Bs[kk][tx * 4];
            float a[4] = {av.x, av.y, av.z, av.w};
            float b[4] = {bv.x, bv.y, bv.z, bv.w};
            #pragma unroll
            for (int i = 0; i < 4; i++)
                #pragma unroll
                for (int j = 0; j < 4; j++)
                    acc[i][j] += a[i] * b[j];
        }
    }

    #pragma unroll
    for (int i = 0; i < 4; i++) {
        float4 out = make_float4(acc[i][0], acc[i][1], acc[i][2], acc[i][3]);
        *(float4*)&C[(size_t)(bm + ty * 4 + i) * N + bn + tx * 4] = out;
    }
}

// ---------------------------------------------------------------------------
// RMSNorm + RoPE applied in-place to Q and K heads inside the QKV buffer.
// One warp per (token, head); 24 heads/token (16 Q + 8 K). V untouched.
// Angles computed in fp64, then sincos(double) — accuracy headroom.
// ---------------------------------------------------------------------------
__global__ __launch_bounds__(256) void normrope_kernel(
    float* __restrict__ qkv,
    const float* __restrict__ qw, const float* __restrict__ kw,
    const int* __restrict__ positions, int T)
{
    const int warp = (blockIdx.x * blockDim.x + threadIdx.x) >> 5;
    const int lane = threadIdx.x & 31;
    if (warp >= T * 24) return;
    const int t = warp / 24;
    const int h = warp % 24;   // 0..15 = Q heads, 16..23 = K heads (contiguous!)

    float* x = qkv + (size_t)t * QKV_COLS + h * HEAD_DIM;
    const float* nw = (h < 16) ? qw : kw;

    float v0 = x[lane], v1 = x[lane + 32], v2 = x[lane + 64], v3 = x[lane + 96];
    float ss = v0 * v0 + v1 * v1 + v2 * v2 + v3 * v3;
    #pragma unroll
    for (int o = 16; o; o >>= 1) ss += __shfl_xor_sync(0xffffffffu, ss, o);
    const float rn = rsqrtf(ss * (1.0f / HEAD_DIM) + RMS_EPS);

    float n0 = v0 * rn * nw[lane];
    float n1 = v1 * rn * nw[lane + 32];
    float n2 = v2 * rn * nw[lane + 64];
    float n3 = v3 * rn * nw[lane + 96];

    // RoPE: pair (j, j+64). This lane owns pairs j=lane -> (n0,n2)
    // and j=lane+32 -> (n1,n3).
    const double pos = (double)positions[t];
    const double LOG_THETA = 13.815510557964274;   // ln(1e6)
    double f0 = exp(-((double)(2 * lane) / 128.0) * LOG_THETA);
    double f1 = exp(-((double)(2 * (lane + 32)) / 128.0) * LOG_THETA);
    double s0d, c0d, s1d, c1d;
    sincos(pos * f0, &s0d, &c0d);
    sincos(pos * f1, &s1d, &c1d);
    float c0 = (float)c0d, s0 = (float)s0d, c1 = (float)c1d, s1 = (float)s1d;

    x[lane]      = n0 * c0 - n2 * s0;
    x[lane + 64] = n2 * c0 + n0 * s0;
    x[lane + 32] = n1 * c1 - n3 * s1;
    x[lane + 96] = n3 * c1 + n1 * s1;
}

// ---------------------------------------------------------------------------
// Flash-style causal attention (fp32 online softmax).
// Grid: (T/64, NUM_HEADS). 256 threads. BM=BN=64, D=128.
// ---------------------------------------------------------------------------
#define ABM 64
#define ABN 64
#define ADS 132        // padded fp32 stride for 128-wide tiles
#define ASS 68         // padded stride for 64-wide score tile

__global__ __launch_bounds__(256) void attn_kernel(
    const float* __restrict__ qkv, float* __restrict__ attn_out, int T)
{
    extern __shared__ float sm[];
    float* Qs  = sm;                       // ABM * ADS
    float* Ks  = Qs  + ABM * ADS;          // ABM * ADS
    float* Vs  = Ks  + ABM * ADS;          // ABM * ADS
    float* Ss  = Vs  + ABM * ADS;          // ABM * ASS
    float* m_s = Ss  + ABM * ASS;          // ABM
    float* l_s = m_s + ABM;                // ABM
    float* a_s = l_s + ABM;                // ABM

    const int tid  = threadIdx.x;
    const int qb   = blockIdx.x;
    const int head = blockIdx.y;
    const int kvh  = head >> 1;            // rep = NUM_HEADS / NUM_KV = 2

    const int ty = tid >> 4, tx = tid & 15;   // S microtile mapping
    const int rg = tid >> 4, cg = tid & 15;   // PV mapping: 4 rows x 8 cols

    // Load Q tile (rows qb*64..): qkv[row][head*128 + d]
    for (int idx = tid; idx < ABM * 32; idx += 256) {
        int r = idx >> 5, cw = (idx & 31) << 2;
        float4 q4 = *(const float4*)&qkv[(size_t)(qb * ABM + r) * QKV_COLS
                                         + head * HEAD_DIM + cw];
        *(float4*)&Qs[r * ADS + cw] = q4;
    }
    if (tid < ABM) { m_s[tid] = -1e30f; l_s[tid] = 0.0f; }

    float o[4][8] = {};

    for (int kb = 0; kb <= qb; kb++) {
        __syncthreads();   // prior PV done with Vs/Ss; Q/m/l init visible on iter 0
        // Load K and V tiles for kv rows kb*64..
        for (int idx = tid; idx < ABM * 32; idx += 256) {
            int r = idx >> 5, cw = (idx & 31) << 2;
            const float* base = qkv + (size_t)(kb * ABN + r) * QKV_COLS;
            float4 k4 = *(const float4*)(base + Q_SIZE + kvh * HEAD_DIM + cw);
            float4 v4 = *(const float4*)(base + Q_SIZE + KV_SIZE + kvh * HEAD_DIM + cw);
            *(float4*)&Ks[r * ADS + cw] = k4;
            *(float4*)&Vs[r * ADS + cw] = v4;
        }
        __syncthreads();

        // S = Q K^T (64x64), 4x4 per thread
        float acc[4][4] = {};
        #pragma unroll 4
        for (int kk = 0; kk < HEAD_DIM; kk += 4) {
            float4 qa[4], kv[4];
            #pragma unroll
            for (int i = 0; i < 4; i++)
                qa[i] = *(const float4*)&Qs[(ty * 4 + i) * ADS + kk];
            #pragma unroll
            for (int j = 0; j < 4; j++)
                kv[j] = *(const float4*)&Ks[(tx * 4 + j) * ADS + kk];
            #pragma unroll
            for (int i = 0; i < 4; i++)
                #pragma unroll
                for (int j = 0; j < 4; j++)
                    acc[i][j] += qa[i].x * kv[j].x + qa[i].y * kv[j].y
                               + qa[i].z * kv[j].z + qa[i].w * kv[j].w;
        }

        // Scale + causal mask + stage to smem
        #pragma unroll
        for (int i = 0; i < 4; i++) {
            int gr = qb * ABM + ty * 4 + i;
            #pragma unroll
            for (int j = 0; j < 4; j++) {
                int gc = kb * ABN + tx * 4 + j;
                float s = acc[i][j] * SCALE;
                Ss[(ty * 4 + i) * ASS + tx * 4 + j] = (gc <= gr) ? s : -1e30f;
            }
        }
        __syncthreads();

        // Online softmax per row (64 threads)
        if (tid < ABM) {
            const int row = tid;
            float rm = m_s[row];
            #pragma unroll 8
            for (int j = 0; j < ABN; j++) rm = fmaxf(rm, Ss[row * ASS + j]);
            const float alpha = __expf(m_s[row] - rm);
            float sum = 0.0f;
            #pragma unroll 8
            for (int j = 0; j < ABN; j++) {
                float p = __expf(Ss[row * ASS + j] - rm);
                Ss[row * ASS + j] = p;
                sum += p;
            }
            m_s[row] = rm;
            l_s[row] = l_s[row] * alpha + sum;
            a_s[row] = alpha;
        }
        __syncthreads();

        // O = O*alpha + P @ V  (each thread: 4 rows x 8 cols)
        #pragma unroll
        for (int i = 0; i < 4; i++) {
            float al = a_s[rg * 4 + i];
            #pragma unroll
            for (int j = 0; j < 8; j++) o[i][j] *= al;
        }
        #pragma unroll 2
        for (int kk = 0; kk < ABN; kk++) {
            float p[4];
            #pragma unroll
            for (int i = 0; i < 4; i++) p[i] = Ss[(rg * 4 + i) * ASS + kk];
            float4 va = *(const float4*)&Vs[kk * ADS + cg * 8];
            float4 vb = *(const float4*)&Vs[kk * ADS + cg * 8 + 4];
            #pragma unroll
            for (int i = 0; i < 4; i++) {
                o[i][0] += p[i] * va.x; o[i][1] += p[i] * va.y;
                o[i][2] += p[i] * va.z; o[i][3] += p[i] * va.w;
                o[i][4] += p[i] * vb.x; o[i][5] += p[i] * vb.y;
                o[i][6] += p[i] * vb.z; o[i][7] += p[i] * vb.w;
            }
        }
    }

    // Normalize and write out: attn_out[row][head*128 + col]
    #pragma unroll
    for (int i = 0; i < 4; i++) {
        const float inv = 1.0f / l_s[rg * 4 + i];
        const int gr = qb * ABM + rg * 4 + i;
        float4 w0 = make_float4(o[i][0] * inv, o[i][1] * inv, o[i][2] * inv, o[i][3] * inv);
        float4 w1 = make_float4(o[i][4] * inv, o[i][5] * inv, o[i][6] * inv, o[i][7] * inv);
        *(float4*)&attn_out[(size_t)gr * Q_SIZE + head * HEAD_DIM + cg * 8]     = w0;
        *(float4*)&attn_out[(size_t)gr * Q_SIZE + head * HEAD_DIM + cg * 8 + 4] = w1;
    }
}

// ---------------------------------------------------------------------------
// Launch
// ---------------------------------------------------------------------------
extern "C" void kernel_launch(void* const* d_in, const int* in_sizes, int n_in,
                              void* d_out, int out_size)
{
    const float* hidden = (const float*)d_in[0];   // [T, 2048]
    const float* qkv_w  = (const float*)d_in[1];   // [4096, 2048]
    const float* q_nw   = (const float*)d_in[2];   // [128]
    const float* k_nw   = (const float*)d_in[3];   // [128]
    const float* o_w    = (const float*)d_in[4];   // [2048, 2048]
    const int*   pos    = (const int*)d_in[5];     // [T]
    float* out = (float*)d_out;                    // [T, 2048]

    const int T = in_sizes[0] / HIDDEN;

    float* qkv;  cudaGetSymbolAddress((void**)&qkv,  g_qkv);
    float* attn; cudaGetSymbolAddress((void**)&attn, g_attn);

    // Attention dynamic smem
    const int attn_smem = (ABM * ADS * 3 + ABM * ASS + 3 * ABM) * (int)sizeof(float);
    cudaFuncSetAttribute(attn_kernel, cudaFuncAttributeMaxDynamicSharedMemorySize,
                         attn_smem);

    // 1) QKV projection: g_qkv[T,4096] = hidden @ qkv_w^T
    {
        dim3 grid(QKV_COLS / GBN, T / GBM);
        gemm_nt<<<grid, 256>>>(hidden, qkv_w, qkv, T, QKV_COLS, HIDDEN);
    }

    // 2) RMSNorm + RoPE in place on Q and K heads
    {
        int warps = T * 24;
        int blocks = (warps + 7) / 8;
        normrope_kernel<<<blocks, 256>>>(qkv, q_nw, k_nw, pos, T);
    }

    // 3) Causal attention -> g_attn[T, 2048]
    {
        dim3 grid(T / ABM, NUM_HEADS);
        attn_kernel<<<grid, 256, attn_smem>>>(qkv, attn, T);
    }

    // 4) Output projection: out[T,2048] = attn @ o_w^T
    {
        dim3 grid(HIDDEN / GBN, T / GBM);
        gemm_nt<<<grid, 256>>>(attn, o_w, out, T, HIDDEN, HIDDEN);
    }
}

// round 3
// speedup vs baseline: 1.7165x; 1.7165x over previous
#include <cuda_runtime.h>
#include <cuda_bf16.h>
#include <math.h>
#include <float.h>
#include <cstdint>

// Problem constants
#define HIDDEN    2048
#define NUM_HEADS 16
#define NUM_KV    8
#define HEAD_DIM  128
#define Q_SIZE    (NUM_HEADS * HEAD_DIM)        // 2048
#define KV_SIZE   (NUM_KV * HEAD_DIM)           // 1024
#define QKV_COLS  (Q_SIZE + 2 * KV_SIZE)        // 4096
#define SCALE     0.08838834764831845f          // 128^-0.5
#define RMS_EPS   1e-6f

#define MAX_T 4096

// Scratch (static device globals — no runtime allocation allowed)
__device__ float g_qkv[(size_t)MAX_T * QKV_COLS];   // 64 MB
__device__ float g_attn[(size_t)MAX_T * Q_SIZE];    // 32 MB

// ===========================================================================
// Helpers
// ===========================================================================
__device__ __forceinline__ uint32_t pack_bf2(__nv_bfloat16 a, __nv_bfloat16 b) {
    __nv_bfloat162 t = __halves2bfloat162(a, b);
    return *reinterpret_cast<uint32_t*>(&t);
}
__device__ __forceinline__ void split_bf(float x, __nv_bfloat16& h, __nv_bfloat16& l) {
    h = __float2bfloat16(x);
    l = __float2bfloat16(x - __bfloat162float(h));
}

// warp mma: D(16x8,f32) += A(16x16,bf16) * B(16x8,bf16)   [row.col]
__device__ __forceinline__ void mma_bf16(float* d, const uint32_t* a,
                                         uint32_t b0, uint32_t b1) {
    asm volatile(
        "mma.sync.aligned.m16n8k16.row.col.f32.bf16.bf16.f32 "
        "{%0,%1,%2,%3}, {%4,%5,%6,%7}, {%8,%9}, {%0,%1,%2,%3};"
        : "+f"(d[0]), "+f"(d[1]), "+f"(d[2]), "+f"(d[3])
        : "r"(a[0]), "r"(a[1]), "r"(a[2]), "r"(a[3]), "r"(b0), "r"(b1));
}

// ---------------------------------------------------------------------------
// SIMT fp32 GEMM (unchanged, proven): C[M,N] = A[M,K] * B[N,K]^T
// ---------------------------------------------------------------------------
#define GBM 64
#define GBN 64
#define GBK 16

__global__ __launch_bounds__(256) void gemm_nt(
    const float* __restrict__ A, const float* __restrict__ B,
    float* __restrict__ C, int M, int N, int K)
{
    __shared__ float As[GBK][GBM + 4];
    __shared__ float Bs[GBK][GBN + 4];

    const int tid = threadIdx.x;
    const int bm = blockIdx.y * GBM;
    const int bn = blockIdx.x * GBN;
    const int ty = tid >> 4;
    const int tx = tid & 15;
    const int lr = tid >> 2;
    const int lc = (tid & 3) * 4;

    float acc[4][4] = {};

    for (int k0 = 0; k0 < K; k0 += GBK) {
        float4 a4 = *(const float4*)&A[(size_t)(bm + lr) * K + k0 + lc];
        float4 b4 = *(const float4*)&B[(size_t)(bn + lr) * K + k0 + lc];
        __syncthreads();
        As[lc + 0][lr] = a4.x; As[lc + 1][lr] = a4.y;
        As[lc + 2][lr] = a4.z; As[lc + 3][lr] = a4.w;
        Bs[lc + 0][lr] = b4.x; Bs[lc + 1][lr] = b4.y;
        Bs[lc + 2][lr] = b4.z; Bs[lc + 3][lr] = b4.w;
        __syncthreads();

        #pragma unroll
        for (int kk = 0; kk < GBK; kk++) {
            float4 av = *(const float4*)&As[kk][ty * 4];
            float4 bv = *(const float4*)&Bs[kk][tx * 4];
            float a[4] = {av.x, av.y, av.z, av.w};
            float b[4] = {bv.x, bv.y, bv.z, bv.w};
            #pragma unroll
            for (int i = 0; i < 4; i++)
                #pragma unroll
                for (int j = 0; j < 4; j++)
                    acc[i][j] += a[i] * b[j];
        }
    }

    #pragma unroll
    for (int i = 0; i < 4; i++) {
        float4 out = make_float4(acc[i][0], acc[i][1], acc[i][2], acc[i][3]);
        *(float4*)&C[(size_t)(bm + ty * 4 + i) * N + bn + tx * 4] = out;
    }
}

// ---------------------------------------------------------------------------
// RMSNorm + RoPE (unchanged)
// ---------------------------------------------------------------------------
__global__ __launch_bounds__(256) void normrope_kernel(
    float* __restrict__ qkv,
    const float* __restrict__ qw, const float* __restrict__ kw,
    const int* __restrict__ positions, int T)
{
    const int warp = (blockIdx.x * blockDim.x + threadIdx.x) >> 5;
    const int lane = threadIdx.x & 31;
    if (warp >= T * 24) return;
    const int t = warp / 24;
    const int h = warp % 24;

    float* x = qkv + (size_t)t * QKV_COLS + h * HEAD_DIM;
    const float* nw = (h < 16) ? qw : kw;

    float v0 = x[lane], v1 = x[lane + 32], v2 = x[lane + 64], v3 = x[lane + 96];
    float ss = v0 * v0 + v1 * v1 + v2 * v2 + v3 * v3;
    #pragma unroll
    for (int o = 16; o; o >>= 1) ss += __shfl_xor_sync(0xffffffffu, ss, o);
    const float rn = rsqrtf(ss * (1.0f / HEAD_DIM) + RMS_EPS);

    float n0 = v0 * rn * nw[lane];
    float n1 = v1 * rn * nw[lane + 32];
    float n2 = v2 * rn * nw[lane + 64];
    float n3 = v3 * rn * nw[lane + 96];

    const double pos = (double)positions[t];
    const double LOG_THETA = 13.815510557964274;
    double f0 = exp(-((double)(2 * lane) / 128.0) * LOG_THETA);
    double f1 = exp(-((double)(2 * (lane + 32)) / 128.0) * LOG_THETA);
    double s0d, c0d, s1d, c1d;
    sincos(pos * f0, &s0d, &c0d);
    sincos(pos * f1, &s1d, &c1d);
    float c0 = (float)c0d, s0 = (float)s0d, c1 = (float)c1d, s1 = (float)s1d;

    x[lane]      = n0 * c0 - n2 * s0;
    x[lane + 64] = n2 * c0 + n0 * s0;
    x[lane + 32] = n1 * c1 - n3 * s1;
    x[lane + 96] = n3 * c1 + n1 * s1;
}

// ---------------------------------------------------------------------------
// HMMA flash attention (mma.sync bf16 + hi/lo split, fp32 accum).
// CTA = (head, 128 q rows), 256 threads, 8 warps x 16 q rows each.
// Smem: K tile (K-major) hi/lo + V tile (transposed, d-major) hi/lo.
// ---------------------------------------------------------------------------
#define SSTR 136                       // bf16 elements per smem row (128 + 8 pad)
#define TILE_B (128 * SSTR * 2)        // 34816 bytes per tile buffer
#define KHO 0
#define KLO (KHO + TILE_B)
#define VHO (KLO + TILE_B)
#define VLO (VHO + TILE_B)
#define ATT_SMEM (VLO + TILE_B)        // 139264 bytes

__global__ __launch_bounds__(256, 1) void attn_mma(
    const float* __restrict__ qkv, float* __restrict__ attn_out, int T)
{
    extern __shared__ char sm[];
    const int tid  = threadIdx.x;
    const int lane = tid & 31;
    const int wid  = tid >> 5;
    const int gid  = lane >> 2;       // 0..7
    const int tq   = lane & 3;        // 0..3

    const int qb   = (gridDim.x - 1) - blockIdx.x;   // big blocks first
    const int head = blockIdx.y;
    const int kvh  = head >> 1;
    const int q0   = qb * 128;
    const int wrow = wid * 16;        // warp's q-row base within block

    // ---- Stage Q tile into K buffers, build persistent Q fragments ----
    for (int i = tid; i < 128 * 32; i += 256) {
        int r = i >> 5, c = (i & 31) << 2;
        float4 v = *(const float4*)&qkv[(size_t)(q0 + r) * QKV_COLS
                                        + head * HEAD_DIM + c];
        __nv_bfloat16 h0, h1, h2, h3, l0, l1, l2, l3;
        split_bf(v.x, h0, l0); split_bf(v.y, h1, l1);
        split_bf(v.z, h2, l2); split_bf(v.w, h3, l3);
        uint32_t off = (uint32_t)(r * SSTR + c) * 2;
        uint2 uh; uh.x = pack_bf2(h0, h1); uh.y = pack_bf2(h2, h3);
        uint2 ul; ul.x = pack_bf2(l0, l1); ul.y = pack_bf2(l2, l3);
        *(uint2*)(sm + KHO + off) = uh;
        *(uint2*)(sm + KLO + off) = ul;
    }
    __syncthreads();

    uint32_t qh[8][4], ql[8][4];
    {
        const int r0 = wrow + gid;
        #pragma unroll
        for (int kt = 0; kt < 8; kt++) {
            int c0 = kt * 16 + tq * 2;
            qh[kt][0] = *(const uint32_t*)(sm + KHO + (uint32_t)(r0 * SSTR + c0) * 2);
            qh[kt][1] = *(const uint32_t*)(sm + KHO + (uint32_t)((r0 + 8) * SSTR + c0) * 2);
            qh[kt][2] = *(const uint32_t*)(sm + KHO + (uint32_t)(r0 * SSTR + c0 + 8) * 2);
            qh[kt][3] = *(const uint32_t*)(sm + KHO + (uint32_t)((r0 + 8) * SSTR + c0 + 8) * 2);
            ql[kt][0] = *(const uint32_t*)(sm + KLO + (uint32_t)(r0 * SSTR + c0) * 2);
            ql[kt][1] = *(const uint32_t*)(sm + KLO + (uint32_t)((r0 + 8) * SSTR + c0) * 2);
            ql[kt][2] = *(const uint32_t*)(sm + KLO + (uint32_t)(r0 * SSTR + c0 + 8) * 2);
            ql[kt][3] = *(const uint32_t*)(sm + KLO + (uint32_t)((r0 + 8) * SSTR + c0 + 8) * 2);
        }
    }

    const int grow0 = q0 + wrow + gid;
    const int grow1 = grow0 + 8;

    float m0 = -1e30f, m1 = -1e30f, l0s = 0.0f, l1s = 0.0f;
    float o[16][4] = {};

    const int iters = qb + 1;
    for (int it = 0; it < iters; it++) {
        const int k0 = it * 128;
        __syncthreads();   // everyone done reading smem from previous phase

        // ---- Stage K tile [kv][d] hi/lo ----
        for (int i = tid; i < 128 * 32; i += 256) {
            int r = i >> 5, c = (i & 31) << 2;
            float4 v = *(const float4*)&qkv[(size_t)(k0 + r) * QKV_COLS
                                            + Q_SIZE + kvh * HEAD_DIM + c];
            __nv_bfloat16 h0, h1, h2, h3, l0, l1, l2, l3;
            split_bf(v.x, h0, l0); split_bf(v.y, h1, l1);
            split_bf(v.z, h2, l2); split_bf(v.w, h3, l3);
            uint32_t off = (uint32_t)(r * SSTR + c) * 2;
            uint2 uh; uh.x = pack_bf2(h0, h1); uh.y = pack_bf2(h2, h3);
            uint2 ul; ul.x = pack_bf2(l0, l1); ul.y = pack_bf2(l2, l3);
            *(uint2*)(sm + KHO + off) = uh;
            *(uint2*)(sm + KLO + off) = ul;
        }
        // ---- Stage V transposed: Vt[d][kv] hi/lo ----
        for (int i = tid; i < 128 * 64; i += 256) {
            int d = i & 127, kv = (i >> 7) << 1;
            const float* base = &qkv[(size_t)(k0 + kv) * QKV_COLS
                                     + Q_SIZE + KV_SIZE + kvh * HEAD_DIM + d];
            float a = base[0];
            float b = base[QKV_COLS];
            __nv_bfloat16 ha, la, hb, lb;
            split_bf(a, ha, la); split_bf(b, hb, lb);
            uint32_t off = (uint32_t)(d * SSTR + kv) * 2;
            *(uint32_t*)(sm + VHO + off) = pack_bf2(ha, hb);
            *(uint32_t*)(sm + VLO + off) = pack_bf2(la, lb);
        }
        __syncthreads();

        // ---- S = Q K^T (warp: 16 x 128), 3 split combos ----
        float s[16][4];
        #pragma unroll
        for (int nt = 0; nt < 16; nt++)
            #pragma unroll
            for (int c = 0; c < 4; c++) s[nt][c] = 0.0f;

        #pragma unroll
        for (int kt = 0; kt < 8; kt++) {
            #pragma unroll
            for (int nt = 0; nt < 16; nt++) {
                uint32_t rowb = (uint32_t)((nt * 8 + gid) * SSTR + kt * 16 + tq * 2) * 2;
                uint32_t bh0 = *(const uint32_t*)(sm + KHO + rowb);
                uint32_t bh1 = *(const uint32_t*)(sm + KHO + rowb + 16);
                uint32_t bl0 = *(const uint32_t*)(sm + KLO + rowb);
                uint32_t bl1 = *(const uint32_t*)(sm + KLO + rowb + 16);
                mma_bf16(s[nt], qh[kt], bh0, bh1);
                mma_bf16(s[nt], qh[kt], bl0, bl1);
                mma_bf16(s[nt], ql[kt], bh0, bh1);
            }
        }

        // ---- scale + causal mask + online softmax ----
        const bool diag = (it == qb);
        float mx0 = m0, mx1 = m1;
        #pragma unroll
        for (int nt = 0; nt < 16; nt++) {
            int colb = k0 + nt * 8 + tq * 2;
            #pragma unroll
            for (int c = 0; c < 2; c++) {
                float v0 = s[nt][c] * SCALE;
                float v1 = s[nt][c + 2] * SCALE;
                if (diag && (colb + c > grow0)) v0 = -1e30f;
                if (diag && (colb + c > grow1)) v1 = -1e30f;
                s[nt][c] = v0; s[nt][c + 2] = v1;
                mx0 = fmaxf(mx0, v0); mx1 = fmaxf(mx1, v1);
            }
        }
        mx0 = fmaxf(mx0, __shfl_xor_sync(0xffffffffu, mx0, 1));
        mx0 = fmaxf(mx0, __shfl_xor_sync(0xffffffffu, mx0, 2));
        mx1 = fmaxf(mx1, __shfl_xor_sync(0xffffffffu, mx1, 1));
        mx1 = fmaxf(mx1, __shfl_xor_sync(0xffffffffu, mx1, 2));

        const float a0 = __expf(m0 - mx0);
        const float a1 = __expf(m1 - mx1);
        m0 = mx0; m1 = mx1;

        float sum0 = 0.0f, sum1 = 0.0f;
        #pragma unroll
        for (int nt = 0; nt < 16; nt++) {
            #pragma unroll
            for (int c = 0; c < 2; c++) {
                float p0 = __expf(s[nt][c] - m0);
                float p1 = __expf(s[nt][c + 2] - m1);
                s[nt][c] = p0; s[nt][c + 2] = p1;
                sum0 += p0; sum1 += p1;
            }
        }
        sum0 += __shfl_xor_sync(0xffffffffu, sum0, 1);
        sum0 += __shfl_xor_sync(0xffffffffu, sum0, 2);
        sum1 += __shfl_xor_sync(0xffffffffu, sum1, 1);
        sum1 += __shfl_xor_sync(0xffffffffu, sum1, 2);
        l0s = l0s * a0 + sum0;
        l1s = l1s * a1 + sum1;

        #pragma unroll
        for (int nt = 0; nt < 16; nt++) {
            o[nt][0] *= a0; o[nt][1] *= a0;
            o[nt][2] *= a1; o[nt][3] *= a1;
        }

        // ---- O += P @ V  (P built in-register from S fragments) ----
        #pragma unroll
        for (int kt = 0; kt < 8; kt++) {
            uint32_t ph[4], pl[4];
            {
                __nv_bfloat16 h00, l00, h01, l01, h10, l10, h11, l11;
                split_bf(s[2 * kt][0], h00, l00); split_bf(s[2 * kt][1], h01, l01);
                split_bf(s[2 * kt][2], h10, l10); split_bf(s[2 * kt][3], h11, l11);
                ph[0] = pack_bf2(h00, h01); pl[0] = pack_bf2(l00, l01);
                ph[1] = pack_bf2(h10, h11); pl[1] = pack_bf2(l10, l11);
                split_bf(s[2 * kt + 1][0], h00, l00); split_bf(s[2 * kt + 1][1], h01, l01);
                split_bf(s[2 * kt + 1][2], h10, l10); split_bf(s[2 * kt + 1][3], h11, l11);
                ph[2] = pack_bf2(h00, h01); pl[2] = pack_bf2(l00, l01);
                ph[3] = pack_bf2(h10, h11); pl[3] = pack_bf2(l10, l11);
            }
            #pragma unroll
            for (int nt = 0; nt < 16; nt++) {
                uint32_t rowb = (uint32_t)((nt * 8 + gid) * SSTR + kt * 16 + tq * 2) * 2;
                uint32_t vh0 = *(const uint32_t*)(sm + VHO + rowb);
                uint32_t vh1 = *(const uint32_t*)(sm + VHO + rowb + 16);
                uint32_t vl0 = *(const uint32_t*)(sm + VLO + rowb);
                uint32_t vl1 = *(const uint32_t*)(sm + VLO + rowb + 16);
                mma_bf16(o[nt], ph, vh0, vh1);
                mma_bf16(o[nt], ph, vl0, vl1);
                mma_bf16(o[nt], pl, vh0, vh1);
            }
        }
    }

    // ---- Epilogue: normalize + store ----
    const float inv0 = 1.0f / l0s;
    const float inv1 = 1.0f / l1s;
    #pragma unroll
    for (int nt = 0; nt < 16; nt++) {
        int dcol = head * HEAD_DIM + nt * 8 + tq * 2;
        float2 w0 = make_float2(o[nt][0] * inv0, o[nt][1] * inv0);
        float2 w1 = make_float2(o[nt][2] * inv1, o[nt][3] * inv1);
        *(float2*)&attn_out[(size_t)grow0 * Q_SIZE + dcol] = w0;
        *(float2*)&attn_out[(size_t)grow1 * Q_SIZE + dcol] = w1;
    }
}

// ---------------------------------------------------------------------------
// Launch
// ---------------------------------------------------------------------------
extern "C" void kernel_launch(void* const* d_in, const int* in_sizes, int n_in,
                              void* d_out, int out_size)
{
    const float* hidden = (const float*)d_in[0];
    const float* qkv_w  = (const float*)d_in[1];
    const float* q_nw   = (const float*)d_in[2];
    const float* k_nw   = (const float*)d_in[3];
    const float* o_w    = (const float*)d_in[4];
    const int*   pos    = (const int*)d_in[5];
    float* out = (float*)d_out;

    const int T = in_sizes[0] / HIDDEN;

    float* qkv;  cudaGetSymbolAddress((void**)&qkv,  g_qkv);
    float* attn; cudaGetSymbolAddress((void**)&attn, g_attn);

    cudaFuncSetAttribute(attn_mma, cudaFuncAttributeMaxDynamicSharedMemorySize,
                         ATT_SMEM);

    // 1) QKV projection
    {
        dim3 grid(QKV_COLS / GBN, T / GBM);
        gemm_nt<<<grid, 256>>>(hidden, qkv_w, qkv, T, QKV_COLS, HIDDEN);
    }
    // 2) RMSNorm + RoPE
    {
        int warps = T * 24;
        int blocks = (warps + 7) / 8;
        normrope_kernel<<<blocks, 256>>>(qkv, q_nw, k_nw, pos, T);
    }
    // 3) Attention (HMMA flash)
    {
        dim3 grid(T / 128, NUM_HEADS);
        attn_mma<<<grid, 256, ATT_SMEM>>>(qkv, attn, T);
    }
    // 4) Output projection
    {
        dim3 grid(HIDDEN / GBN, T / GBM);
        gemm_nt<<<grid, 256>>>(attn, o_w, out, T, HIDDEN, HIDDEN);
    }
}

// round 4
// speedup vs baseline: 2.7142x; 1.5812x over previous
#include <cuda_runtime.h>
#include <cuda_bf16.h>
#include <math.h>
#include <float.h>
#include <cstdint>

// Problem constants
#define HIDDEN    2048
#define NUM_HEADS 16
#define NUM_KV    8
#define HEAD_DIM  128
#define Q_SIZE    (NUM_HEADS * HEAD_DIM)        // 2048
#define KV_SIZE   (NUM_KV * HEAD_DIM)           // 1024
#define QKV_COLS  (Q_SIZE + 2 * KV_SIZE)        // 4096
#define SCALE     0.08838834764831845f          // 128^-0.5
#define RMS_EPS   1e-6f

#define MAX_T 4096

// Scratch (static device globals — no runtime allocation allowed)
__device__ float g_qkv[(size_t)MAX_T * QKV_COLS];                  // 64 MB
__device__ __nv_bfloat16 g_hid_h[(size_t)MAX_T * HIDDEN];          // 16 MB
__device__ __nv_bfloat16 g_hid_l[(size_t)MAX_T * HIDDEN];
__device__ __nv_bfloat16 g_w1_h[(size_t)QKV_COLS * HIDDEN];        // 16 MB
__device__ __nv_bfloat16 g_w1_l[(size_t)QKV_COLS * HIDDEN];
__device__ __nv_bfloat16 g_w2_h[(size_t)HIDDEN * Q_SIZE];          // 8 MB
__device__ __nv_bfloat16 g_w2_l[(size_t)HIDDEN * Q_SIZE];
__device__ __nv_bfloat16 g_at_h[(size_t)MAX_T * Q_SIZE];           // 16 MB
__device__ __nv_bfloat16 g_at_l[(size_t)MAX_T * Q_SIZE];

// ===========================================================================
// Helpers
// ===========================================================================
__device__ __forceinline__ uint32_t pack_bf2(__nv_bfloat16 a, __nv_bfloat16 b) {
    __nv_bfloat162 t = __halves2bfloat162(a, b);
    return *reinterpret_cast<uint32_t*>(&t);
}
__device__ __forceinline__ void split_bf(float x, __nv_bfloat16& h, __nv_bfloat16& l) {
    h = __float2bfloat16(x);
    l = __float2bfloat16(x - __bfloat162float(h));
}

// warp mma: D(16x8,f32) += A(16x16,bf16) * B(16x8,bf16)   [row.col]
__device__ __forceinline__ void mma_bf16(float* d, const uint32_t* a,
                                         uint32_t b0, uint32_t b1) {
    asm volatile(
        "mma.sync.aligned.m16n8k16.row.col.f32.bf16.bf16.f32 "
        "{%0,%1,%2,%3}, {%4,%5,%6,%7}, {%8,%9}, {%0,%1,%2,%3};"
        : "+f"(d[0]), "+f"(d[1]), "+f"(d[2]), "+f"(d[3])
        : "r"(a[0]), "r"(a[1]), "r"(a[2]), "r"(a[3]), "r"(b0), "r"(b1));
}

// ---------------------------------------------------------------------------
// Split fp32 -> bf16 hi/lo (elementwise)
// ---------------------------------------------------------------------------
__global__ __launch_bounds__(256) void split_kernel(
    const float* __restrict__ src, __nv_bfloat16* __restrict__ h,
    __nv_bfloat16* __restrict__ l, int n4)
{
    int i = blockIdx.x * blockDim.x + threadIdx.x;
    if (i >= n4) return;
    float4 v = ((const float4*)src)[i];
    __nv_bfloat16 h0, h1, h2, h3, l0, l1, l2, l3;
    split_bf(v.x, h0, l0); split_bf(v.y, h1, l1);
    split_bf(v.z, h2, l2); split_bf(v.w, h3, l3);
    uint2 uh; uh.x = pack_bf2(h0, h1); uh.y = pack_bf2(h2, h3);
    uint2 ul; ul.x = pack_bf2(l0, l1); ul.y = pack_bf2(l2, l3);
    ((uint2*)h)[i] = uh;
    ((uint2*)l)[i] = ul;
}

// ---------------------------------------------------------------------------
// HMMA GEMM with 2-term bf16 split: C[M,N] = A[M,K] * B[N,K]^T  (fp32 out)
// C = Ah*Bh + Ah*Bl + Al*Bh.  BM=128, BN=128, BK=32, 256 threads (8 warps,
// warp tile 32x64). Scalar-LDS fragment loads (mapping proven in attn_mma).
// ---------------------------------------------------------------------------
#define XBM 128
#define XBN 128
#define XBK 32
#define XSTR 40   // smem row stride in bf16 elems (32 + 8 pad)

__global__ __launch_bounds__(256) void gemm_bf16s(
    const __nv_bfloat16* __restrict__ Ah, const __nv_bfloat16* __restrict__ Al,
    const __nv_bfloat16* __restrict__ Bh, const __nv_bfloat16* __restrict__ Bl,
    float* __restrict__ C, int M, int N, int K)
{
    __shared__ __nv_bfloat16 sAh[XBM * XSTR];
    __shared__ __nv_bfloat16 sAl[XBM * XSTR];
    __shared__ __nv_bfloat16 sBh[XBN * XSTR];
    __shared__ __nv_bfloat16 sBl[XBN * XSTR];

    const int tid  = threadIdx.x;
    const int lane = tid & 31;
    const int wid  = tid >> 5;
    const int gid  = lane >> 2;
    const int tq   = lane & 3;
    const int wm   = (wid & 3) * 32;   // warp row base
    const int wn   = (wid >> 2) * 64;  // warp col base

    const int bm = blockIdx.y * XBM;
    const int bn = blockIdx.x * XBN;

    // Staging: each thread owns 2 uint4 per buffer (512 uint4 = 128x32 bf16)
    const int r0 = tid >> 2;                 // row for idx = tid
    const int c0 = (tid & 3) * 8;            // col (bf16 elems)
    const int r1 = (tid + 256) >> 2;
    const int c1 = ((tid + 256) & 3) * 8;

    uint4 pAh0, pAh1, pAl0, pAl1, pBh0, pBh1, pBl0, pBl1;

    #define LOAD_STAGE(k0) do { \
        pAh0 = *(const uint4*)&Ah[(size_t)(bm + r0) * K + (k0) + c0]; \
        pAh1 = *(const uint4*)&Ah[(size_t)(bm + r1) * K + (k0) + c1]; \
        pAl0 = *(const uint4*)&Al[(size_t)(bm + r0) * K + (k0) + c0]; \
        pAl1 = *(const uint4*)&Al[(size_t)(bm + r1) * K + (k0) + c1]; \
        pBh0 = *(const uint4*)&Bh[(size_t)(bn + r0) * K + (k0) + c0]; \
        pBh1 = *(const uint4*)&Bh[(size_t)(bn + r1) * K + (k0) + c1]; \
        pBl0 = *(const uint4*)&Bl[(size_t)(bn + r0) * K + (k0) + c0]; \
        pBl1 = *(const uint4*)&Bl[(size_t)(bn + r1) * K + (k0) + c1]; \
    } while (0)

    #define STORE_STAGE() do { \
        *(uint4*)&sAh[r0 * XSTR + c0] = pAh0; *(uint4*)&sAh[r1 * XSTR + c1] = pAh1; \
        *(uint4*)&sAl[r0 * XSTR + c0] = pAl0; *(uint4*)&sAl[r1 * XSTR + c1] = pAl1; \
        *(uint4*)&sBh[r0 * XSTR + c0] = pBh0; *(uint4*)&sBh[r1 * XSTR + c1] = pBh1; \
        *(uint4*)&sBl[r0 * XSTR + c0] = pBl0; *(uint4*)&sBl[r1 * XSTR + c1] = pBl1; \
    } while (0)

    float acc[2][8][4] = {};

    LOAD_STAGE(0);

    for (int k0 = 0; k0 < K; k0 += XBK) {
        __syncthreads();            // previous compute done with smem
        STORE_STAGE();
        __syncthreads();
        if (k0 + XBK < K) LOAD_STAGE(k0 + XBK);   // prefetch next under compute

        #pragma unroll
        for (int kk = 0; kk < XBK; kk += 16) {
            // A fragments (hi/lo) for 2 m-tiles
            uint32_t ah[2][4], al[2][4];
            #pragma unroll
            for (int mt = 0; mt < 2; mt++) {
                int ra = wm + mt * 16 + gid;
                int ca = kk + tq * 2;
                ah[mt][0] = *(const uint32_t*)&sAh[ra * XSTR + ca];
                ah[mt][1] = *(const uint32_t*)&sAh[(ra + 8) * XSTR + ca];
                ah[mt][2] = *(const uint32_t*)&sAh[ra * XSTR + ca + 8];
                ah[mt][3] = *(const uint32_t*)&sAh[(ra + 8) * XSTR + ca + 8];
                al[mt][0] = *(const uint32_t*)&sAl[ra * XSTR + ca];
                al[mt][1] = *(const uint32_t*)&sAl[(ra + 8) * XSTR + ca];
                al[mt][2] = *(const uint32_t*)&sAl[ra * XSTR + ca + 8];
                al[mt][3] = *(const uint32_t*)&sAl[(ra + 8) * XSTR + ca + 8];
            }
            #pragma unroll
            for (int nt = 0; nt < 8; nt++) {
                int rb = wn + nt * 8 + gid;
                int cb = kk + tq * 2;
                uint32_t bh0 = *(const uint32_t*)&sBh[rb * XSTR + cb];
                uint32_t bh1 = *(const uint32_t*)&sBh[rb * XSTR + cb + 8];
                uint32_t bl0 = *(const uint32_t*)&sBl[rb * XSTR + cb];
                uint32_t bl1 = *(const uint32_t*)&sBl[rb * XSTR + cb + 8];
                #pragma unroll
                for (int mt = 0; mt < 2; mt++) {
                    mma_bf16(acc[mt][nt], ah[mt], bh0, bh1);
                    mma_bf16(acc[mt][nt], ah[mt], bl0, bl1);
                    mma_bf16(acc[mt][nt], al[mt], bh0, bh1);
                }
            }
        }
    }

    // Epilogue (mapping proven in attn_mma)
    #pragma unroll
    for (int mt = 0; mt < 2; mt++) {
        int row = bm + wm + mt * 16 + gid;
        #pragma unroll
        for (int nt = 0; nt < 8; nt++) {
            int col = bn + wn + nt * 8 + tq * 2;
            *(float2*)&C[(size_t)row * N + col] =
                make_float2(acc[mt][nt][0], acc[mt][nt][1]);
            *(float2*)&C[(size_t)(row + 8) * N + col] =
                make_float2(acc[mt][nt][2], acc[mt][nt][3]);
        }
    }
}

// ---------------------------------------------------------------------------
// RMSNorm + RoPE (unchanged)
// ---------------------------------------------------------------------------
__global__ __launch_bounds__(256) void normrope_kernel(
    float* __restrict__ qkv,
    const float* __restrict__ qw, const float* __restrict__ kw,
    const int* __restrict__ positions, int T)
{
    const int warp = (blockIdx.x * blockDim.x + threadIdx.x) >> 5;
    const int lane = threadIdx.x & 31;
    if (warp >= T * 24) return;
    const int t = warp / 24;
    const int h = warp % 24;

    float* x = qkv + (size_t)t * QKV_COLS + h * HEAD_DIM;
    const float* nw = (h < 16) ? qw : kw;

    float v0 = x[lane], v1 = x[lane + 32], v2 = x[lane + 64], v3 = x[lane + 96];
    float ss = v0 * v0 + v1 * v1 + v2 * v2 + v3 * v3;
    #pragma unroll
    for (int o = 16; o; o >>= 1) ss += __shfl_xor_sync(0xffffffffu, ss, o);
    const float rn = rsqrtf(ss * (1.0f / HEAD_DIM) + RMS_EPS);

    float n0 = v0 * rn * nw[lane];
    float n1 = v1 * rn * nw[lane + 32];
    float n2 = v2 * rn * nw[lane + 64];
    float n3 = v3 * rn * nw[lane + 96];

    const double pos = (double)positions[t];
    const double LOG_THETA = 13.815510557964274;
    double f0 = exp(-((double)(2 * lane) / 128.0) * LOG_THETA);
    double f1 = exp(-((double)(2 * (lane + 32)) / 128.0) * LOG_THETA);
    double s0d, c0d, s1d, c1d;
    sincos(pos * f0, &s0d, &c0d);
    sincos(pos * f1, &s1d, &c1d);
    float c0 = (float)c0d, s0 = (float)s0d, c1 = (float)c1d, s1 = (float)s1d;

    x[lane]      = n0 * c0 - n2 * s0;
    x[lane + 64] = n2 * c0 + n0 * s0;
    x[lane + 32] = n1 * c1 - n3 * s1;
    x[lane + 96] = n3 * c1 + n1 * s1;
}

// ---------------------------------------------------------------------------
// HMMA flash attention (unchanged mainloop; epilogue now emits bf16 hi/lo)
// ---------------------------------------------------------------------------
#define SSTR 136
#define TILE_B (128 * SSTR * 2)
#define KHO 0
#define KLO (KHO + TILE_B)
#define VHO (KLO + TILE_B)
#define VLO (VHO + TILE_B)
#define ATT_SMEM (VLO + TILE_B)

__global__ __launch_bounds__(256, 1) void attn_mma(
    const float* __restrict__ qkv,
    __nv_bfloat16* __restrict__ attn_h, __nv_bfloat16* __restrict__ attn_l,
    int T)
{
    extern __shared__ char sm[];
    const int tid  = threadIdx.x;
    const int lane = tid & 31;
    const int wid  = tid >> 5;
    const int gid  = lane >> 2;
    const int tq   = lane & 3;

    const int qb   = (gridDim.x - 1) - blockIdx.x;
    const int head = blockIdx.y;
    const int kvh  = head >> 1;
    const int q0   = qb * 128;
    const int wrow = wid * 16;

    for (int i = tid; i < 128 * 32; i += 256) {
        int r = i >> 5, c = (i & 31) << 2;
        float4 v = *(const float4*)&qkv[(size_t)(q0 + r) * QKV_COLS
                                        + head * HEAD_DIM + c];
        __nv_bfloat16 h0, h1, h2, h3, l0, l1, l2, l3;
        split_bf(v.x, h0, l0); split_bf(v.y, h1, l1);
        split_bf(v.z, h2, l2); split_bf(v.w, h3, l3);
        uint32_t off = (uint32_t)(r * SSTR + c) * 2;
        uint2 uh; uh.x = pack_bf2(h0, h1); uh.y = pack_bf2(h2, h3);
        uint2 ul; ul.x = pack_bf2(l0, l1); ul.y = pack_bf2(l2, l3);
        *(uint2*)(sm + KHO + off) = uh;
        *(uint2*)(sm + KLO + off) = ul;
    }
    __syncthreads();

    uint32_t qh[8][4], ql[8][4];
    {
        const int r0 = wrow + gid;
        #pragma unroll
        for (int kt = 0; kt < 8; kt++) {
            int c0 = kt * 16 + tq * 2;
            qh[kt][0] = *(const uint32_t*)(sm + KHO + (uint32_t)(r0 * SSTR + c0) * 2);
            qh[kt][1] = *(const uint32_t*)(sm + KHO + (uint32_t)((r0 + 8) * SSTR + c0) * 2);
            qh[kt][2] = *(const uint32_t*)(sm + KHO + (uint32_t)(r0 * SSTR + c0 + 8) * 2);
            qh[kt][3] = *(const uint32_t*)(sm + KHO + (uint32_t)((r0 + 8) * SSTR + c0 + 8) * 2);
            ql[kt][0] = *(const uint32_t*)(sm + KLO + (uint32_t)(r0 * SSTR + c0) * 2);
            ql[kt][1] = *(const uint32_t*)(sm + KLO + (uint32_t)((r0 + 8) * SSTR + c0) * 2);
            ql[kt][2] = *(const uint32_t*)(sm + KLO + (uint32_t)(r0 * SSTR + c0 + 8) * 2);
            ql[kt][3] = *(const uint32_t*)(sm + KLO + (uint32_t)((r0 + 8) * SSTR + c0 + 8) * 2);
        }
    }

    const int grow0 = q0 + wrow + gid;
    const int grow1 = grow0 + 8;

    float m0 = -1e30f, m1 = -1e30f, l0s = 0.0f, l1s = 0.0f;
    float o[16][4] = {};

    const int iters = qb + 1;
    for (int it = 0; it < iters; it++) {
        const int k0 = it * 128;
        __syncthreads();

        for (int i = tid; i < 128 * 32; i += 256) {
            int r = i >> 5, c = (i & 31) << 2;
            float4 v = *(const float4*)&qkv[(size_t)(k0 + r) * QKV_COLS
                                            + Q_SIZE + kvh * HEAD_DIM + c];
            __nv_bfloat16 h0, h1, h2, h3, l0, l1, l2, l3;
            split_bf(v.x, h0, l0); split_bf(v.y, h1, l1);
            split_bf(v.z, h2, l2); split_bf(v.w, h3, l3);
            uint32_t off = (uint32_t)(r * SSTR + c) * 2;
            uint2 uh; uh.x = pack_bf2(h0, h1); uh.y = pack_bf2(h2, h3);
            uint2 ul; ul.x = pack_bf2(l0, l1); ul.y = pack_bf2(l2, l3);
            *(uint2*)(sm + KHO + off) = uh;
            *(uint2*)(sm + KLO + off) = ul;
        }
        for (int i = tid; i < 128 * 64; i += 256) {
            int d = i & 127, kv = (i >> 7) << 1;
            const float* base = &qkv[(size_t)(k0 + kv) * QKV_COLS
                                     + Q_SIZE + KV_SIZE + kvh * HEAD_DIM + d];
            float a = base[0];
            float b = base[QKV_COLS];
            __nv_bfloat16 ha, la, hb, lb;
            split_bf(a, ha, la); split_bf(b, hb, lb);
            uint32_t off = (uint32_t)(d * SSTR + kv) * 2;
            *(uint32_t*)(sm + VHO + off) = pack_bf2(ha, hb);
            *(uint32_t*)(sm + VLO + off) = pack_bf2(la, lb);
        }
        __syncthreads();

        float s[16][4];
        #pragma unroll
        for (int nt = 0; nt < 16; nt++)
            #pragma unroll
            for (int c = 0; c < 4; c++) s[nt][c] = 0.0f;

        #pragma unroll
        for (int kt = 0; kt < 8; kt++) {
            #pragma unroll
            for (int nt = 0; nt < 16; nt++) {
                uint32_t rowb = (uint32_t)((nt * 8 + gid) * SSTR + kt * 16 + tq * 2) * 2;
                uint32_t bh0 = *(const uint32_t*)(sm + KHO + rowb);
                uint32_t bh1 = *(const uint32_t*)(sm + KHO + rowb + 16);
                uint32_t bl0 = *(const uint32_t*)(sm + KLO + rowb);
                uint32_t bl1 = *(const uint32_t*)(sm + KLO + rowb + 16);
                mma_bf16(s[nt], qh[kt], bh0, bh1);
                mma_bf16(s[nt], qh[kt], bl0, bl1);
                mma_bf16(s[nt], ql[kt], bh0, bh1);
            }
        }

        const bool diag = (it == qb);
        float mx0 = m0, mx1 = m1;
        #pragma unroll
        for (int nt = 0; nt < 16; nt++) {
            int colb = k0 + nt * 8 + tq * 2;
            #pragma unroll
            for (int c = 0; c < 2; c++) {
                float v0 = s[nt][c] * SCALE;
                float v1 = s[nt][c + 2] * SCALE;
                if (diag && (colb + c > grow0)) v0 = -1e30f;
                if (diag && (colb + c > grow1)) v1 = -1e30f;
                s[nt][c] = v0; s[nt][c + 2] = v1;
                mx0 = fmaxf(mx0, v0); mx1 = fmaxf(mx1, v1);
            }
        }
        mx0 = fmaxf(mx0, __shfl_xor_sync(0xffffffffu, mx0, 1));
        mx0 = fmaxf(mx0, __shfl_xor_sync(0xffffffffu, mx0, 2));
        mx1 = fmaxf(mx1, __shfl_xor_sync(0xffffffffu, mx1, 1));
        mx1 = fmaxf(mx1, __shfl_xor_sync(0xffffffffu, mx1, 2));

        const float a0 = __expf(m0 - mx0);
        const float a1 = __expf(m1 - mx1);
        m0 = mx0; m1 = mx1;

        float sum0 = 0.0f, sum1 = 0.0f;
        #pragma unroll
        for (int nt = 0; nt < 16; nt++) {
            #pragma unroll
            for (int c = 0; c < 2; c++) {
                float p0 = __expf(s[nt][c] - m0);
                float p1 = __expf(s[nt][c + 2] - m1);
                s[nt][c] = p0; s[nt][c + 2] = p1;
                sum0 += p0; sum1 += p1;
            }
        }
        sum0 += __shfl_xor_sync(0xffffffffu, sum0, 1);
        sum0 += __shfl_xor_sync(0xffffffffu, sum0, 2);
        sum1 += __shfl_xor_sync(0xffffffffu, sum1, 1);
        sum1 += __shfl_xor_sync(0xffffffffu, sum1, 2);
        l0s = l0s * a0 + sum0;
        l1s = l1s * a1 + sum1;

        #pragma unroll
        for (int nt = 0; nt < 16; nt++) {
            o[nt][0] *= a0; o[nt][1] *= a0;
            o[nt][2] *= a1; o[nt][3] *= a1;
        }

        #pragma unroll
        for (int kt = 0; kt < 8; kt++) {
            uint32_t ph[4], pl[4];
            {
                __nv_bfloat16 h00, l00, h01, l01, h10, l10, h11, l11;
                split_bf(s[2 * kt][0], h00, l00); split_bf(s[2 * kt][1], h01, l01);
                split_bf(s[2 * kt][2], h10, l10); split_bf(s[2 * kt][3], h11, l11);
                ph[0] = pack_bf2(h00, h01); pl[0] = pack_bf2(l00, l01);
                ph[1] = pack_bf2(h10, h11); pl[1] = pack_bf2(l10, l11);
                split_bf(s[2 * kt + 1][0], h00, l00); split_bf(s[2 * kt + 1][1], h01, l01);
                split_bf(s[2 * kt + 1][2], h10, l10); split_bf(s[2 * kt + 1][3], h11, l11);
                ph[2] = pack_bf2(h00, h01); pl[2] = pack_bf2(l00, l01);
                ph[3] = pack_bf2(h10, h11); pl[3] = pack_bf2(l10, l11);
            }
            #pragma unroll
            for (int nt = 0; nt < 16; nt++) {
                uint32_t rowb = (uint32_t)((nt * 8 + gid) * SSTR + kt * 16 + tq * 2) * 2;
                uint32_t vh0 = *(const uint32_t*)(sm + VHO + rowb);
                uint32_t vh1 = *(const uint32_t*)(sm + VHO + rowb + 16);
                uint32_t vl0 = *(const uint32_t*)(sm + VLO + rowb);
                uint32_t vl1 = *(const uint32_t*)(sm + VLO + rowb + 16);
                mma_bf16(o[nt], ph, vh0, vh1);
                mma_bf16(o[nt], ph, vl0, vl1);
                mma_bf16(o[nt], pl, vh0, vh1);
            }
        }
    }

    // ---- Epilogue: normalize, split hi/lo, store bf16 ----
    const float inv0 = 1.0f / l0s;
    const float inv1 = 1.0f / l1s;
    #pragma unroll
    for (int nt = 0; nt < 16; nt++) {
        int dcol = head * HEAD_DIM + nt * 8 + tq * 2;
        float w00 = o[nt][0] * inv0, w01 = o[nt][1] * inv0;
        float w10 = o[nt][2] * inv1, w11 = o[nt][3] * inv1;
        __nv_bfloat16 h0, l0, h1, l1;
        split_bf(w00, h0, l0); split_bf(w01, h1, l1);
        *(uint32_t*)&attn_h[(size_t)grow0 * Q_SIZE + dcol] = pack_bf2(h0, h1);
        *(uint32_t*)&attn_l[(size_t)grow0 * Q_SIZE + dcol] = pack_bf2(l0, l1);
        split_bf(w10, h0, l0); split_bf(w11, h1, l1);
        *(uint32_t*)&attn_h[(size_t)grow1 * Q_SIZE + dcol] = pack_bf2(h0, h1);
        *(uint32_t*)&attn_l[(size_t)grow1 * Q_SIZE + dcol] = pack_bf2(l0, l1);
    }
}

// ---------------------------------------------------------------------------
// Launch
// ---------------------------------------------------------------------------
extern "C" void kernel_launch(void* const* d_in, const int* in_sizes, int n_in,
                              void* d_out, int out_size)
{
    const float* hidden = (const float*)d_in[0];
    const float* qkv_w  = (const float*)d_in[1];
    const float* q_nw   = (const float*)d_in[2];
    const float* k_nw   = (const float*)d_in[3];
    const float* o_w    = (const float*)d_in[4];
    const int*   pos    = (const int*)d_in[5];
    float* out = (float*)d_out;

    const int T = in_sizes[0] / HIDDEN;

    float* qkv;  cudaGetSymbolAddress((void**)&qkv,  g_qkv);
    __nv_bfloat16 *hid_h, *hid_l, *w1_h, *w1_l, *w2_h, *w2_l, *at_h, *at_l;
    cudaGetSymbolAddress((void**)&hid_h, g_hid_h);
    cudaGetSymbolAddress((void**)&hid_l, g_hid_l);
    cudaGetSymbolAddress((void**)&w1_h,  g_w1_h);
    cudaGetSymbolAddress((void**)&w1_l,  g_w1_l);
    cudaGetSymbolAddress((void**)&w2_h,  g_w2_h);
    cudaGetSymbolAddress((void**)&w2_l,  g_w2_l);
    cudaGetSymbolAddress((void**)&at_h,  g_at_h);
    cudaGetSymbolAddress((void**)&at_l,  g_at_l);

    cudaFuncSetAttribute(attn_mma, cudaFuncAttributeMaxDynamicSharedMemorySize,
                         ATT_SMEM);

    // 0) Split inputs to bf16 hi/lo
    {
        int n4 = T * HIDDEN / 4;
        split_kernel<<<(n4 + 255) / 256, 256>>>(hidden, hid_h, hid_l, n4);
        n4 = QKV_COLS * HIDDEN / 4;
        split_kernel<<<(n4 + 255) / 256, 256>>>(qkv_w, w1_h, w1_l, n4);
        n4 = HIDDEN * Q_SIZE / 4;
        split_kernel<<<(n4 + 255) / 256, 256>>>(o_w, w2_h, w2_l, n4);
    }
    // 1) QKV projection (HMMA): g_qkv = hidden @ qkv_w^T
    {
        dim3 grid(QKV_COLS / XBN, T / XBM);
        gemm_bf16s<<<grid, 256>>>(hid_h, hid_l, w1_h, w1_l, qkv, T, QKV_COLS, HIDDEN);
    }
    // 2) RMSNorm + RoPE
    {
        int warps = T * 24;
        int blocks = (warps + 7) / 8;
        normrope_kernel<<<blocks, 256>>>(qkv, q_nw, k_nw, pos, T);
    }
    // 3) Attention (HMMA flash) -> bf16 hi/lo
    {
        dim3 grid(T / 128, NUM_HEADS);
        attn_mma<<<grid, 256, ATT_SMEM>>>(qkv, at_h, at_l, T);
    }
    // 4) Output projection (HMMA): out = attn @ o_w^T
    {
        dim3 grid(HIDDEN / XBN, T / XBM);
        gemm_bf16s<<<grid, 256>>>(at_h, at_l, w2_h, w2_l, out, T, HIDDEN, HIDDEN);
    }
}

// round 5
// speedup vs baseline: 3.3098x; 1.2194x over previous
#include <cuda_runtime.h>
#include <cuda_bf16.h>
#include <math.h>
#include <float.h>
#include <cstdint>

// Problem constants
#define HIDDEN    2048
#define NUM_HEADS 16
#define NUM_KV    8
#define HEAD_DIM  128
#define Q_SIZE    (NUM_HEADS * HEAD_DIM)        // 2048
#define KV_SIZE   (NUM_KV * HEAD_DIM)           // 1024
#define QKV_COLS  (Q_SIZE + 2 * KV_SIZE)        // 4096
#define SCALE     0.08838834764831845f          // 128^-0.5
#define RMS_EPS   1e-6f

#define MAX_T 4096

// Scratch (static device globals — no runtime allocation allowed)
__device__ float g_qkv[(size_t)MAX_T * QKV_COLS];                  // 64 MB
__device__ __nv_bfloat16 g_hid_h[(size_t)MAX_T * HIDDEN];
__device__ __nv_bfloat16 g_hid_l[(size_t)MAX_T * HIDDEN];
__device__ __nv_bfloat16 g_w1_h[(size_t)QKV_COLS * HIDDEN];
__device__ __nv_bfloat16 g_w1_l[(size_t)QKV_COLS * HIDDEN];
__device__ __nv_bfloat16 g_w2_h[(size_t)HIDDEN * Q_SIZE];
__device__ __nv_bfloat16 g_w2_l[(size_t)HIDDEN * Q_SIZE];
__device__ __nv_bfloat16 g_at_h[(size_t)MAX_T * Q_SIZE];
__device__ __nv_bfloat16 g_at_l[(size_t)MAX_T * Q_SIZE];
// Split Q/K/V for attention
__device__ __nv_bfloat16 g_q_h[(size_t)MAX_T * Q_SIZE];
__device__ __nv_bfloat16 g_q_l[(size_t)MAX_T * Q_SIZE];
__device__ __nv_bfloat16 g_k_h[(size_t)NUM_KV * MAX_T * HEAD_DIM];
__device__ __nv_bfloat16 g_k_l[(size_t)NUM_KV * MAX_T * HEAD_DIM];
__device__ __nv_bfloat16 g_v_h[(size_t)NUM_KV * HEAD_DIM * MAX_T];  // transposed [kvh][d][t]
__device__ __nv_bfloat16 g_v_l[(size_t)NUM_KV * HEAD_DIM * MAX_T];

// ===========================================================================
// Helpers
// ===========================================================================
__device__ __forceinline__ uint32_t smem_to_u32(const void* p) {
    uint32_t a;
    asm("{ .reg .u64 t; cvta.to.shared.u64 t, %1; cvt.u32.u64 %0, t; }"
        : "=r"(a) : "l"(p));
    return a;
}
__device__ __forceinline__ uint32_t pack_bf2(__nv_bfloat16 a, __nv_bfloat16 b) {
    __nv_bfloat162 t = __halves2bfloat162(a, b);
    return *reinterpret_cast<uint32_t*>(&t);
}
__device__ __forceinline__ void split_bf(float x, __nv_bfloat16& h, __nv_bfloat16& l) {
    h = __float2bfloat16(x);
    l = __float2bfloat16(x - __bfloat162float(h));
}

// warp mma: D(16x8,f32) += A(16x16,bf16) * B(16x8,bf16)   [row.col]
__device__ __forceinline__ void mma_bf16(float* d, const uint32_t* a,
                                         uint32_t b0, uint32_t b1) {
    asm volatile(
        "mma.sync.aligned.m16n8k16.row.col.f32.bf16.bf16.f32 "
        "{%0,%1,%2,%3}, {%4,%5,%6,%7}, {%8,%9}, {%0,%1,%2,%3};"
        : "+f"(d[0]), "+f"(d[1]), "+f"(d[2]), "+f"(d[3])
        : "r"(a[0]), "r"(a[1]), "r"(a[2]), "r"(a[3]), "r"(b0), "r"(b1));
}

#define CP_ASYNC16(dst, src) \
    asm volatile("cp.async.cg.shared.global [%0], [%1], 16;" \
        :: "r"(dst), "l"(src))
#define CP_COMMIT() asm volatile("cp.async.commit_group;")
#define CP_WAIT(n)  asm volatile("cp.async.wait_group %0;" :: "n"(n))

// ---------------------------------------------------------------------------
// Split fp32 -> bf16 hi/lo (elementwise, same layout)
// ---------------------------------------------------------------------------
__global__ __launch_bounds__(256) void split_kernel(
    const float* __restrict__ src, __nv_bfloat16* __restrict__ h,
    __nv_bfloat16* __restrict__ l, int n4)
{
    int i = blockIdx.x * blockDim.x + threadIdx.x;
    if (i >= n4) return;
    float4 v = ((const float4*)src)[i];
    __nv_bfloat16 h0, h1, h2, h3, l0, l1, l2, l3;
    split_bf(v.x, h0, l0); split_bf(v.y, h1, l1);
    split_bf(v.z, h2, l2); split_bf(v.w, h3, l3);
    uint2 uh; uh.x = pack_bf2(h0, h1); uh.y = pack_bf2(h2, h3);
    uint2 ul; ul.x = pack_bf2(l0, l1); ul.y = pack_bf2(l2, l3);
    ((uint2*)h)[i] = uh;
    ((uint2*)l)[i] = ul;
}

// Split Q part of qkv -> g_q_h/l [T][2048]
__global__ __launch_bounds__(256) void split_q_kernel(
    const float* __restrict__ qkv, __nv_bfloat16* __restrict__ qh,
    __nv_bfloat16* __restrict__ ql, int T)
{
    int i = blockIdx.x * blockDim.x + threadIdx.x;   // over T*512
    if (i >= T * 512) return;
    int t = i >> 9, c4 = i & 511;
    float4 v = *(const float4*)&qkv[(size_t)t * QKV_COLS + c4 * 4];
    __nv_bfloat16 h0, h1, h2, h3, l0, l1, l2, l3;
    split_bf(v.x, h0, l0); split_bf(v.y, h1, l1);
    split_bf(v.z, h2, l2); split_bf(v.w, h3, l3);
    uint2 uh; uh.x = pack_bf2(h0, h1); uh.y = pack_bf2(h2, h3);
    uint2 ul; ul.x = pack_bf2(l0, l1); ul.y = pack_bf2(l2, l3);
    size_t o = (size_t)t * Q_SIZE + c4 * 4;
    *(uint2*)&qh[o] = uh;
    *(uint2*)&ql[o] = ul;
}

// Split K part -> g_k_h/l [kvh][t][d]
__global__ __launch_bounds__(256) void split_k_kernel(
    const float* __restrict__ qkv, __nv_bfloat16* __restrict__ kh,
    __nv_bfloat16* __restrict__ kl, int T)
{
    int i = blockIdx.x * blockDim.x + threadIdx.x;   // over T*256
    if (i >= T * 256) return;
    int t = i >> 8, c4 = i & 255;
    int d = c4 * 4;                // 0..1023
    int kvh = d >> 7, dd = d & 127;
    float4 v = *(const float4*)&qkv[(size_t)t * QKV_COLS + Q_SIZE + d];
    __nv_bfloat16 h0, h1, h2, h3, l0, l1, l2, l3;
    split_bf(v.x, h0, l0); split_bf(v.y, h1, l1);
    split_bf(v.z, h2, l2); split_bf(v.w, h3, l3);
    uint2 uh; uh.x = pack_bf2(h0, h1); uh.y = pack_bf2(h2, h3);
    uint2 ul; ul.x = pack_bf2(l0, l1); ul.y = pack_bf2(l2, l3);
    size_t o = (size_t)kvh * T * HEAD_DIM + (size_t)t * HEAD_DIM + dd;
    *(uint2*)&kh[o] = uh;
    *(uint2*)&kl[o] = ul;
}

// Transpose + split V -> g_v_h/l [kvh][d][t]
__global__ void vtrans_kernel(
    const float* __restrict__ qkv, __nv_bfloat16* __restrict__ vh,
    __nv_bfloat16* __restrict__ vl, int T)
{
    __shared__ float tile[32][33];
    const int kvh = blockIdx.z;
    const int d0 = blockIdx.y * 32;
    const int t0 = blockIdx.x * 32;
    for (int j = threadIdx.y; j < 32; j += 8) {
        tile[j][threadIdx.x] = qkv[(size_t)(t0 + j) * QKV_COLS + Q_SIZE + KV_SIZE
                                   + kvh * HEAD_DIM + d0 + threadIdx.x];
    }
    __syncthreads();
    for (int j = threadIdx.y; j < 32; j += 8) {
        float v = tile[threadIdx.x][j];
        __nv_bfloat16 h, l;
        split_bf(v, h, l);
        size_t o = (size_t)kvh * HEAD_DIM * T + (size_t)(d0 + j) * T + t0 + threadIdx.x;
        vh[o] = h;
        vl[o] = l;
    }
}

// ---------------------------------------------------------------------------
// HMMA GEMM, 2-term bf16 split, cp.async double-buffered.
// C[M,N] = A[M,K] * B[N,K]^T = Ah*Bh + Ah*Bl + Al*Bh.
// BM=BN=128, BK=32, 256 threads (8 warps, 32x64 warp tiles), 2 CTAs/SM.
// ---------------------------------------------------------------------------
#define XBM 128
#define XBN 128
#define XBK 32
#define XSTR 40                      // smem row stride (bf16 elems)
#define STAGE_E (XBM * XSTR)         // 5120 elems per buffer
#define GEMM_SMEM (8 * STAGE_E * 2)  // 81920 bytes (2 stages x 4 buffers)

__global__ __launch_bounds__(256, 2) void gemm_bf16s(
    const __nv_bfloat16* __restrict__ Ah, const __nv_bfloat16* __restrict__ Al,
    const __nv_bfloat16* __restrict__ Bh, const __nv_bfloat16* __restrict__ Bl,
    float* __restrict__ C, int M, int N, int K)
{
    extern __shared__ __nv_bfloat16 smg[];
    const uint32_t smb = smem_to_u32(smg);

    const int tid  = threadIdx.x;
    const int lane = tid & 31;
    const int wid  = tid >> 5;
    const int gid  = lane >> 2;
    const int tq   = lane & 3;
    const int wm   = (wid & 3) * 32;
    const int wn   = (wid >> 2) * 64;

    const int bm = blockIdx.y * XBM;
    const int bn = blockIdx.x * XBN;

    #define G_ISSUE(stage, k0) do { \
        uint32_t sb0 = smb + (uint32_t)(stage) * 4 * STAGE_E * 2; \
        _Pragma("unroll") \
        for (int j = 0; j < 2; j++) { \
            int id = tid + j * 256; \
            int r = id >> 2, c = (id & 3) * 8; \
            size_t aoff = (size_t)(bm + r) * K + (k0) + c; \
            size_t boff = (size_t)(bn + r) * K + (k0) + c; \
            uint32_t doff = (uint32_t)(r * XSTR + c) * 2; \
            CP_ASYNC16(sb0 + doff, Ah + aoff); \
            CP_ASYNC16(sb0 + STAGE_E * 2 + doff, Al + aoff); \
            CP_ASYNC16(sb0 + 2 * STAGE_E * 2 + doff, Bh + boff); \
            CP_ASYNC16(sb0 + 3 * STAGE_E * 2 + doff, Bl + boff); \
        } \
    } while (0)

    float acc[2][8][4] = {};

    G_ISSUE(0, 0);
    CP_COMMIT();

    int stage = 0;
    for (int k0 = 0; k0 < K; k0 += XBK, stage ^= 1) {
        if (k0 + XBK < K) {
            G_ISSUE(stage ^ 1, k0 + XBK);
            CP_COMMIT();
            CP_WAIT(1);
        } else {
            CP_WAIT(0);
        }
        __syncthreads();

        const __nv_bfloat16* sAh = smg + stage * 4 * STAGE_E;
        const __nv_bfloat16* sAl = sAh + STAGE_E;
        const __nv_bfloat16* sBh = sAl + STAGE_E;
        const __nv_bfloat16* sBl = sBh + STAGE_E;

        #pragma unroll
        for (int kk = 0; kk < XBK; kk += 16) {
            uint32_t ah[2][4], al[2][4];
            #pragma unroll
            for (int mt = 0; mt < 2; mt++) {
                int ra = wm + mt * 16 + gid;
                int ca = kk + tq * 2;
                ah[mt][0] = *(const uint32_t*)&sAh[ra * XSTR + ca];
                ah[mt][1] = *(const uint32_t*)&sAh[(ra + 8) * XSTR + ca];
                ah[mt][2] = *(const uint32_t*)&sAh[ra * XSTR + ca + 8];
                ah[mt][3] = *(const uint32_t*)&sAh[(ra + 8) * XSTR + ca + 8];
                al[mt][0] = *(const uint32_t*)&sAl[ra * XSTR + ca];
                al[mt][1] = *(const uint32_t*)&sAl[(ra + 8) * XSTR + ca];
                al[mt][2] = *(const uint32_t*)&sAl[ra * XSTR + ca + 8];
                al[mt][3] = *(const uint32_t*)&sAl[(ra + 8) * XSTR + ca + 8];
            }
            #pragma unroll
            for (int nt = 0; nt < 8; nt++) {
                int rb = wn + nt * 8 + gid;
                int cb = kk + tq * 2;
                uint32_t bh0 = *(const uint32_t*)&sBh[rb * XSTR + cb];
                uint32_t bh1 = *(const uint32_t*)&sBh[rb * XSTR + cb + 8];
                uint32_t bl0 = *(const uint32_t*)&sBl[rb * XSTR + cb];
                uint32_t bl1 = *(const uint32_t*)&sBl[rb * XSTR + cb + 8];
                #pragma unroll
                for (int mt = 0; mt < 2; mt++) {
                    mma_bf16(acc[mt][nt], ah[mt], bh0, bh1);
                    mma_bf16(acc[mt][nt], ah[mt], bl0, bl1);
                    mma_bf16(acc[mt][nt], al[mt], bh0, bh1);
                }
            }
        }
        __syncthreads();    // all reads done before this stage is overwritten
    }

    #pragma unroll
    for (int mt = 0; mt < 2; mt++) {
        int row = bm + wm + mt * 16 + gid;
        #pragma unroll
        for (int nt = 0; nt < 8; nt++) {
            int col = bn + wn + nt * 8 + tq * 2;
            *(float2*)&C[(size_t)row * N + col] =
                make_float2(acc[mt][nt][0], acc[mt][nt][1]);
            *(float2*)&C[(size_t)(row + 8) * N + col] =
                make_float2(acc[mt][nt][2], acc[mt][nt][3]);
        }
    }
}

// ---------------------------------------------------------------------------
// RMSNorm + RoPE (unchanged)
// ---------------------------------------------------------------------------
__global__ __launch_bounds__(256) void normrope_kernel(
    float* __restrict__ qkv,
    const float* __restrict__ qw, const float* __restrict__ kw,
    const int* __restrict__ positions, int T)
{
    const int warp = (blockIdx.x * blockDim.x + threadIdx.x) >> 5;
    const int lane = threadIdx.x & 31;
    if (warp >= T * 24) return;
    const int t = warp / 24;
    const int h = warp % 24;

    float* x = qkv + (size_t)t * QKV_COLS + h * HEAD_DIM;
    const float* nw = (h < 16) ? qw : kw;

    float v0 = x[lane], v1 = x[lane + 32], v2 = x[lane + 64], v3 = x[lane + 96];
    float ss = v0 * v0 + v1 * v1 + v2 * v2 + v3 * v3;
    #pragma unroll
    for (int o = 16; o; o >>= 1) ss += __shfl_xor_sync(0xffffffffu, ss, o);
    const float rn = rsqrtf(ss * (1.0f / HEAD_DIM) + RMS_EPS);

    float n0 = v0 * rn * nw[lane];
    float n1 = v1 * rn * nw[lane + 32];
    float n2 = v2 * rn * nw[lane + 64];
    float n3 = v3 * rn * nw[lane + 96];

    const double pos = (double)positions[t];
    const double LOG_THETA = 13.815510557964274;
    double f0 = exp(-((double)(2 * lane) / 128.0) * LOG_THETA);
    double f1 = exp(-((double)(2 * (lane + 32)) / 128.0) * LOG_THETA);
    double s0d, c0d, s1d, c1d;
    sincos(pos * f0, &s0d, &c0d);
    sincos(pos * f1, &s1d, &c1d);
    float c0 = (float)c0d, s0 = (float)s0d, c1 = (float)c1d, s1 = (float)s1d;

    x[lane]      = n0 * c0 - n2 * s0;
    x[lane + 64] = n2 * c0 + n0 * s0;
    x[lane + 32] = n1 * c1 - n3 * s1;
    x[lane + 96] = n3 * c1 + n1 * s1;
}

// ---------------------------------------------------------------------------
// HMMA flash attention with precomputed bf16 hi/lo Q/K/V and cp.async
// pipelining. CTA = (head, 128 q rows), 256 threads, 8 warps x 16 q rows.
// ---------------------------------------------------------------------------
#define SSTR 136
#define TILE_B (128 * SSTR * 2)      // 34816 bytes per buffer
#define QHO (0 * TILE_B)
#define QLO (1 * TILE_B)
#define KHO (2 * TILE_B)
#define KLO (3 * TILE_B)
#define VHO (4 * TILE_B)
#define VLO (5 * TILE_B)
#define ATT_SMEM (6 * TILE_B)        // 208896 bytes

__global__ __launch_bounds__(256, 1) void attn_mma(
    const __nv_bfloat16* __restrict__ qh_g, const __nv_bfloat16* __restrict__ ql_g,
    const __nv_bfloat16* __restrict__ kh_g, const __nv_bfloat16* __restrict__ kl_g,
    const __nv_bfloat16* __restrict__ vh_g, const __nv_bfloat16* __restrict__ vl_g,
    __nv_bfloat16* __restrict__ attn_h, __nv_bfloat16* __restrict__ attn_l, int T)
{
    extern __shared__ char sm[];
    const uint32_t smb = smem_to_u32(sm);
    const int tid  = threadIdx.x;
    const int lane = tid & 31;
    const int wid  = tid >> 5;
    const int gid  = lane >> 2;
    const int tq   = lane & 3;

    const int qb   = (gridDim.x - 1) - blockIdx.x;   // big blocks first
    const int head = blockIdx.y;
    const int kvh  = head >> 1;
    const int q0   = qb * 128;
    const int wrow = wid * 16;
    const int iters = qb + 1;

    const size_t kbase = (size_t)kvh * T * HEAD_DIM;
    const size_t vbase = (size_t)kvh * HEAD_DIM * T;

    // ---- Prologue: prefetch K(0) and V(0) via cp.async ----
    for (int i = tid; i < 2048; i += 256) {
        int r = i >> 4, c = (i & 15) << 3;
        uint32_t doff = (uint32_t)(r * SSTR + c) * 2;
        CP_ASYNC16(smb + KHO + doff, kh_g + kbase + (size_t)r * HEAD_DIM + c);
        CP_ASYNC16(smb + KLO + doff, kl_g + kbase + (size_t)r * HEAD_DIM + c);
    }
    CP_COMMIT();
    for (int i = tid; i < 2048; i += 256) {
        int d = i >> 4, c = (i & 15) << 3;
        uint32_t doff = (uint32_t)(d * SSTR + c) * 2;
        CP_ASYNC16(smb + VHO + doff, vh_g + vbase + (size_t)d * T + c);
        CP_ASYNC16(smb + VLO + doff, vl_g + vbase + (size_t)d * T + c);
    }
    CP_COMMIT();

    // ---- Stage Q (plain loads, overlapped with prefetch) ----
    for (int i = tid; i < 2048; i += 256) {
        int r = i >> 4, c = (i & 15) << 3;
        uint32_t doff = (uint32_t)(r * SSTR + c) * 2;
        size_t o = (size_t)(q0 + r) * Q_SIZE + head * HEAD_DIM + c;
        *(uint4*)(sm + QHO + doff) = *(const uint4*)&qh_g[o];
        *(uint4*)(sm + QLO + doff) = *(const uint4*)&ql_g[o];
    }
    __syncthreads();

    // ---- Persistent Q fragments ----
    uint32_t qh[8][4], ql[8][4];
    {
        const int r0 = wrow + gid;
        #pragma unroll
        for (int kt = 0; kt < 8; kt++) {
            int c0 = kt * 16 + tq * 2;
            qh[kt][0] = *(const uint32_t*)(sm + QHO + (uint32_t)(r0 * SSTR + c0) * 2);
            qh[kt][1] = *(const uint32_t*)(sm + QHO + (uint32_t)((r0 + 8) * SSTR + c0) * 2);
            qh[kt][2] = *(const uint32_t*)(sm + QHO + (uint32_t)(r0 * SSTR + c0 + 8) * 2);
            qh[kt][3] = *(const uint32_t*)(sm + QHO + (uint32_t)((r0 + 8) * SSTR + c0 + 8) * 2);
            ql[kt][0] = *(const uint32_t*)(sm + QLO + (uint32_t)(r0 * SSTR + c0) * 2);
            ql[kt][1] = *(const uint32_t*)(sm + QLO + (uint32_t)((r0 + 8) * SSTR + c0) * 2);
            ql[kt][2] = *(const uint32_t*)(sm + QLO + (uint32_t)(r0 * SSTR + c0 + 8) * 2);
            ql[kt][3] = *(const uint32_t*)(sm + QLO + (uint32_t)((r0 + 8) * SSTR + c0 + 8) * 2);
        }
    }

    const int grow0 = q0 + wrow + gid;
    const int grow1 = grow0 + 8;

    float m0 = -1e30f, m1 = -1e30f, l0s = 0.0f, l1s = 0.0f;
    float o[16][4] = {};

    for (int it = 0; it < iters; it++) {
        const int k0 = it * 128;

        // K(it) ready (pending: K(it), V(it))
        CP_WAIT(1);
        __syncthreads();

        // ---- S = Q K^T ----
        float s[16][4];
        #pragma unroll
        for (int nt = 0; nt < 16; nt++)
            #pragma unroll
            for (int c = 0; c < 4; c++) s[nt][c] = 0.0f;

        #pragma unroll
        for (int kt = 0; kt < 8; kt++) {
            #pragma unroll
            for (int nt = 0; nt < 16; nt++) {
                uint32_t rowb = (uint32_t)((nt * 8 + gid) * SSTR + kt * 16 + tq * 2) * 2;
                uint32_t bh0 = *(const uint32_t*)(sm + KHO + rowb);
                uint32_t bh1 = *(const uint32_t*)(sm + KHO + rowb + 16);
                uint32_t bl0 = *(const uint32_t*)(sm + KLO + rowb);
                uint32_t bl1 = *(const uint32_t*)(sm + KLO + rowb + 16);
                mma_bf16(s[nt], qh[kt], bh0, bh1);
                mma_bf16(s[nt], qh[kt], bl0, bl1);
                mma_bf16(s[nt], ql[kt], bh0, bh1);
            }
        }
        __syncthreads();   // all warps done reading K smem

        // ---- Prefetch K(it+1) (overlaps softmax + PV) ----
        if (it + 1 < iters) {
            const size_t ko = kbase + (size_t)(it + 1) * 128 * HEAD_DIM;
            for (int i = tid; i < 2048; i += 256) {
                int r = i >> 4, c = (i & 15) << 3;
                uint32_t doff = (uint32_t)(r * SSTR + c) * 2;
                CP_ASYNC16(smb + KHO + doff, kh_g + ko + (size_t)r * HEAD_DIM + c);
                CP_ASYNC16(smb + KLO + doff, kl_g + ko + (size_t)r * HEAD_DIM + c);
            }
        }
        CP_COMMIT();

        // ---- scale + causal mask + online softmax ----
        const bool diag = (it == qb);
        float mx0 = m0, mx1 = m1;
        #pragma unroll
        for (int nt = 0; nt < 16; nt++) {
            int colb = k0 + nt * 8 + tq * 2;
            #pragma unroll
            for (int c = 0; c < 2; c++) {
                float v0 = s[nt][c] * SCALE;
                float v1 = s[nt][c + 2] * SCALE;
                if (diag && (colb + c > grow0)) v0 = -1e30f;
                if (diag && (colb + c > grow1)) v1 = -1e30f;
                s[nt][c] = v0; s[nt][c + 2] = v1;
                mx0 = fmaxf(mx0, v0); mx1 = fmaxf(mx1, v1);
            }
        }
        mx0 = fmaxf(mx0, __shfl_xor_sync(0xffffffffu, mx0, 1));
        mx0 = fmaxf(mx0, __shfl_xor_sync(0xffffffffu, mx0, 2));
        mx1 = fmaxf(mx1, __shfl_xor_sync(0xffffffffu, mx1, 1));
        mx1 = fmaxf(mx1, __shfl_xor_sync(0xffffffffu, mx1, 2));

        const float a0 = __expf(m0 - mx0);
        const float a1 = __expf(m1 - mx1);
        m0 = mx0; m1 = mx1;

        float sum0 = 0.0f, sum1 = 0.0f;
        #pragma unroll
        for (int nt = 0; nt < 16; nt++) {
            #pragma unroll
            for (int c = 0; c < 2; c++) {
                float p0 = __expf(s[nt][c] - m0);
                float p1 = __expf(s[nt][c + 2] - m1);
                s[nt][c] = p0; s[nt][c + 2] = p1;
                sum0 += p0; sum1 += p1;
            }
        }
        sum0 += __shfl_xor_sync(0xffffffffu, sum0, 1);
        sum0 += __shfl_xor_sync(0xffffffffu, sum0, 2);
        sum1 += __shfl_xor_sync(0xffffffffu, sum1, 1);
        sum1 += __shfl_xor_sync(0xffffffffu, sum1, 2);
        l0s = l0s * a0 + sum0;
        l1s = l1s * a1 + sum1;

        #pragma unroll
        for (int nt = 0; nt < 16; nt++) {
            o[nt][0] *= a0; o[nt][1] *= a0;
            o[nt][2] *= a1; o[nt][3] *= a1;
        }

        // V(it) ready (pending: V(it), K(it+1) -> wait leaves 1)
        CP_WAIT(1);
        __syncthreads();

        // ---- O += P @ V ----
        #pragma unroll
        for (int kt = 0; kt < 8; kt++) {
            uint32_t ph[4], pl[4];
            {
                __nv_bfloat16 h00, l00, h01, l01, h10, l10, h11, l11;
                split_bf(s[2 * kt][0], h00, l00); split_bf(s[2 * kt][1], h01, l01);
                split_bf(s[2 * kt][2], h10, l10); split_bf(s[2 * kt][3], h11, l11);
                ph[0] = pack_bf2(h00, h01); pl[0] = pack_bf2(l00, l01);
                ph[1] = pack_bf2(h10, h11); pl[1] = pack_bf2(l10, l11);
                split_bf(s[2 * kt + 1][0], h00, l00); split_bf(s[2 * kt + 1][1], h01, l01);
                split_bf(s[2 * kt + 1][2], h10, l10); split_bf(s[2 * kt + 1][3], h11, l11);
                ph[2] = pack_bf2(h00, h01); pl[2] = pack_bf2(l00, l01);
                ph[3] = pack_bf2(h10, h11); pl[3] = pack_bf2(l10, l11);
            }
            #pragma unroll
            for (int nt = 0; nt < 16; nt++) {
                uint32_t rowb = (uint32_t)((nt * 8 + gid) * SSTR + kt * 16 + tq * 2) * 2;
                uint32_t vh0 = *(const uint32_t*)(sm + VHO + rowb);
                uint32_t vh1 = *(const uint32_t*)(sm + VHO + rowb + 16);
                uint32_t vl0 = *(const uint32_t*)(sm + VLO + rowb);
                uint32_t vl1 = *(const uint32_t*)(sm + VLO + rowb + 16);
                mma_bf16(o[nt], ph, vh0, vh1);
                mma_bf16(o[nt], ph, vl0, vl1);
                mma_bf16(o[nt], pl, vh0, vh1);
            }
        }
        __syncthreads();   // all warps done reading V smem

        // ---- Prefetch V(it+1) (overlaps next QK) ----
        if (it + 1 < iters) {
            const int nk0 = (it + 1) * 128;
            for (int i = tid; i < 2048; i += 256) {
                int d = i >> 4, c = (i & 15) << 3;
                uint32_t doff = (uint32_t)(d * SSTR + c) * 2;
                CP_ASYNC16(smb + VHO + doff, vh_g + vbase + (size_t)d * T + nk0 + c);
                CP_ASYNC16(smb + VLO + doff, vl_g + vbase + (size_t)d * T + nk0 + c);
            }
        }
        CP_COMMIT();
    }

    // ---- Epilogue: normalize, split hi/lo, store bf16 ----
    const float inv0 = 1.0f / l0s;
    const float inv1 = 1.0f / l1s;
    #pragma unroll
    for (int nt = 0; nt < 16; nt++) {
        int dcol = head * HEAD_DIM + nt * 8 + tq * 2;
        float w00 = o[nt][0] * inv0, w01 = o[nt][1] * inv0;
        float w10 = o[nt][2] * inv1, w11 = o[nt][3] * inv1;
        __nv_bfloat16 h0, l0, h1, l1;
        split_bf(w00, h0, l0); split_bf(w01, h1, l1);
        *(uint32_t*)&attn_h[(size_t)grow0 * Q_SIZE + dcol] = pack_bf2(h0, h1);
        *(uint32_t*)&attn_l[(size_t)grow0 * Q_SIZE + dcol] = pack_bf2(l0, l1);
        split_bf(w10, h0, l0); split_bf(w11, h1, l1);
        *(uint32_t*)&attn_h[(size_t)grow1 * Q_SIZE + dcol] = pack_bf2(h0, h1);
        *(uint32_t*)&attn_l[(size_t)grow1 * Q_SIZE + dcol] = pack_bf2(l0, l1);
    }
}

// ---------------------------------------------------------------------------
// Launch
// ---------------------------------------------------------------------------
extern "C" void kernel_launch(void* const* d_in, const int* in_sizes, int n_in,
                              void* d_out, int out_size)
{
    const float* hidden = (const float*)d_in[0];
    const float* qkv_w  = (const float*)d_in[1];
    const float* q_nw   = (const float*)d_in[2];
    const float* k_nw   = (const float*)d_in[3];
    const float* o_w    = (const float*)d_in[4];
    const int*   pos    = (const int*)d_in[5];
    float* out = (float*)d_out;

    const int T = in_sizes[0] / HIDDEN;

    float* qkv;  cudaGetSymbolAddress((void**)&qkv,  g_qkv);
    __nv_bfloat16 *hid_h, *hid_l, *w1_h, *w1_l, *w2_h, *w2_l, *at_h, *at_l;
    __nv_bfloat16 *q_h, *q_l, *k_h, *k_l, *v_h, *v_l;
    cudaGetSymbolAddress((void**)&hid_h, g_hid_h);
    cudaGetSymbolAddress((void**)&hid_l, g_hid_l);
    cudaGetSymbolAddress((void**)&w1_h,  g_w1_h);
    cudaGetSymbolAddress((void**)&w1_l,  g_w1_l);
    cudaGetSymbolAddress((void**)&w2_h,  g_w2_h);
    cudaGetSymbolAddress((void**)&w2_l,  g_w2_l);
    cudaGetSymbolAddress((void**)&at_h,  g_at_h);
    cudaGetSymbolAddress((void**)&at_l,  g_at_l);
    cudaGetSymbolAddress((void**)&q_h,   g_q_h);
    cudaGetSymbolAddress((void**)&q_l,   g_q_l);
    cudaGetSymbolAddress((void**)&k_h,   g_k_h);
    cudaGetSymbolAddress((void**)&k_l,   g_k_l);
    cudaGetSymbolAddress((void**)&v_h,   g_v_h);
    cudaGetSymbolAddress((void**)&v_l,   g_v_l);

    cudaFuncSetAttribute(attn_mma, cudaFuncAttributeMaxDynamicSharedMemorySize,
                         ATT_SMEM);
    cudaFuncSetAttribute(gemm_bf16s, cudaFuncAttributeMaxDynamicSharedMemorySize,
                         GEMM_SMEM);

    // 0) Split inputs to bf16 hi/lo
    {
        int n4 = T * HIDDEN / 4;
        split_kernel<<<(n4 + 255) / 256, 256>>>(hidden, hid_h, hid_l, n4);
        n4 = QKV_COLS * HIDDEN / 4;
        split_kernel<<<(n4 + 255) / 256, 256>>>(qkv_w, w1_h, w1_l, n4);
        n4 = HIDDEN * Q_SIZE / 4;
        split_kernel<<<(n4 + 255) / 256, 256>>>(o_w, w2_h, w2_l, n4);
    }
    // 1) QKV projection (HMMA, double-buffered)
    {
        dim3 grid(QKV_COLS / XBN, T / XBM);
        gemm_bf16s<<<grid, 256, GEMM_SMEM>>>(hid_h, hid_l, w1_h, w1_l, qkv,
                                             T, QKV_COLS, HIDDEN);
    }
    // 2) RMSNorm + RoPE
    {
        int warps = T * 24;
        int blocks = (warps + 7) / 8;
        normrope_kernel<<<blocks, 256>>>(qkv, q_nw, k_nw, pos, T);
    }
    // 3) Split Q/K, transpose+split V
    {
        int n = T * 512;
        split_q_kernel<<<(n + 255) / 256, 256>>>(qkv, q_h, q_l, T);
        n = T * 256;
        split_k_kernel<<<(n + 255) / 256, 256>>>(qkv, k_h, k_l, T);
        dim3 vg(T / 32, HEAD_DIM / 32, NUM_KV);
        vtrans_kernel<<<vg, dim3(32, 8)>>>(qkv, v_h, v_l, T);
    }
    // 4) Attention (HMMA flash, cp.async pipelined)
    {
        dim3 grid(T / 128, NUM_HEADS);
        attn_mma<<<grid, 256, ATT_SMEM>>>(q_h, q_l, k_h, k_l, v_h, v_l,
                                          at_h, at_l, T);
    }
    // 5) Output projection
    {
        dim3 grid(HIDDEN / XBN, T / XBM);
        gemm_bf16s<<<grid, 256, GEMM_SMEM>>>(at_h, at_l, w2_h, w2_l, out,
                                             T, HIDDEN, HIDDEN);
    }
}

// round 6
// speedup vs baseline: 3.4219x; 1.0339x over previous
#include <cuda_runtime.h>
#include <cuda_bf16.h>
#include <math.h>
#include <float.h>
#include <cstdint>

// Problem constants
#define HIDDEN    2048
#define NUM_HEADS 16
#define NUM_KV    8
#define HEAD_DIM  128
#define Q_SIZE    (NUM_HEADS * HEAD_DIM)        // 2048
#define KV_SIZE   (NUM_KV * HEAD_DIM)           // 1024
#define QKV_COLS  (Q_SIZE + 2 * KV_SIZE)        // 4096
#define SCALE     0.08838834764831845f          // 128^-0.5
#define RMS_EPS   1e-6f

#define MAX_T 4096

// Scratch (static device globals — no runtime allocation allowed)
__device__ float g_qkv[(size_t)MAX_T * QKV_COLS];
__device__ __nv_bfloat16 g_hid_h[(size_t)MAX_T * HIDDEN];
__device__ __nv_bfloat16 g_hid_l[(size_t)MAX_T * HIDDEN];
__device__ __nv_bfloat16 g_w1_h[(size_t)QKV_COLS * HIDDEN];
__device__ __nv_bfloat16 g_w1_l[(size_t)QKV_COLS * HIDDEN];
__device__ __nv_bfloat16 g_w2_h[(size_t)HIDDEN * Q_SIZE];
__device__ __nv_bfloat16 g_w2_l[(size_t)HIDDEN * Q_SIZE];
__device__ __nv_bfloat16 g_at_h[(size_t)MAX_T * Q_SIZE];
__device__ __nv_bfloat16 g_at_l[(size_t)MAX_T * Q_SIZE];
__device__ __nv_bfloat16 g_q_h[(size_t)MAX_T * Q_SIZE];
__device__ __nv_bfloat16 g_q_l[(size_t)MAX_T * Q_SIZE];
__device__ __nv_bfloat16 g_k_h[(size_t)NUM_KV * MAX_T * HEAD_DIM];
__device__ __nv_bfloat16 g_k_l[(size_t)NUM_KV * MAX_T * HEAD_DIM];
__device__ __nv_bfloat16 g_v_h[(size_t)NUM_KV * HEAD_DIM * MAX_T];  // [kvh][d][t]
__device__ __nv_bfloat16 g_v_l[(size_t)NUM_KV * HEAD_DIM * MAX_T];

// ===========================================================================
// Helpers
// ===========================================================================
__device__ __forceinline__ uint32_t smem_to_u32(const void* p) {
    uint32_t a;
    asm("{ .reg .u64 t; cvta.to.shared.u64 t, %1; cvt.u32.u64 %0, t; }"
        : "=r"(a) : "l"(p));
    return a;
}
__device__ __forceinline__ uint32_t pack_bf2(__nv_bfloat16 a, __nv_bfloat16 b) {
    __nv_bfloat162 t = __halves2bfloat162(a, b);
    return *reinterpret_cast<uint32_t*>(&t);
}
__device__ __forceinline__ void split_bf(float x, __nv_bfloat16& h, __nv_bfloat16& l) {
    h = __float2bfloat16(x);
    l = __float2bfloat16(x - __bfloat162float(h));
}

// warp mma: D(16x8,f32) += A(16x16,bf16) * B(16x8,bf16)   [row.col]
__device__ __forceinline__ void mma_bf16(float* d, const uint32_t* a,
                                         uint32_t b0, uint32_t b1) {
    asm volatile(
        "mma.sync.aligned.m16n8k16.row.col.f32.bf16.bf16.f32 "
        "{%0,%1,%2,%3}, {%4,%5,%6,%7}, {%8,%9}, {%0,%1,%2,%3};"
        : "+f"(d[0]), "+f"(d[1]), "+f"(d[2]), "+f"(d[3])
        : "r"(a[0]), "r"(a[1]), "r"(a[2]), "r"(a[3]), "r"(b0), "r"(b1));
}

#define LDSM_X4(r0, r1, r2, r3, addr) \
    asm volatile("ldmatrix.sync.aligned.m8n8.x4.shared.b16 {%0,%1,%2,%3}, [%4];" \
        : "=r"(r0), "=r"(r1), "=r"(r2), "=r"(r3) : "r"(addr))

#define CP_ASYNC16(dst, src) \
    asm volatile("cp.async.cg.shared.global [%0], [%1], 16;" \
        :: "r"(dst), "l"(src))
#define CP_COMMIT() asm volatile("cp.async.commit_group;")
#define CP_WAIT(n)  asm volatile("cp.async.wait_group %0;" :: "n"(n))

// ---------------------------------------------------------------------------
// Split kernels
// ---------------------------------------------------------------------------
__global__ __launch_bounds__(256) void split_kernel(
    const float* __restrict__ src, __nv_bfloat16* __restrict__ h,
    __nv_bfloat16* __restrict__ l, int n4)
{
    int i = blockIdx.x * blockDim.x + threadIdx.x;
    if (i >= n4) return;
    float4 v = ((const float4*)src)[i];
    __nv_bfloat16 h0, h1, h2, h3, l0, l1, l2, l3;
    split_bf(v.x, h0, l0); split_bf(v.y, h1, l1);
    split_bf(v.z, h2, l2); split_bf(v.w, h3, l3);
    uint2 uh; uh.x = pack_bf2(h0, h1); uh.y = pack_bf2(h2, h3);
    uint2 ul; ul.x = pack_bf2(l0, l1); ul.y = pack_bf2(l2, l3);
    ((uint2*)h)[i] = uh;
    ((uint2*)l)[i] = ul;
}

__global__ __launch_bounds__(256) void split_q_kernel(
    const float* __restrict__ qkv, __nv_bfloat16* __restrict__ qh,
    __nv_bfloat16* __restrict__ ql, int T)
{
    int i = blockIdx.x * blockDim.x + threadIdx.x;
    if (i >= T * 512) return;
    int t = i >> 9, c4 = i & 511;
    float4 v = *(const float4*)&qkv[(size_t)t * QKV_COLS + c4 * 4];
    __nv_bfloat16 h0, h1, h2, h3, l0, l1, l2, l3;
    split_bf(v.x, h0, l0); split_bf(v.y, h1, l1);
    split_bf(v.z, h2, l2); split_bf(v.w, h3, l3);
    uint2 uh; uh.x = pack_bf2(h0, h1); uh.y = pack_bf2(h2, h3);
    uint2 ul; ul.x = pack_bf2(l0, l1); ul.y = pack_bf2(l2, l3);
    size_t o = (size_t)t * Q_SIZE + c4 * 4;
    *(uint2*)&qh[o] = uh;
    *(uint2*)&ql[o] = ul;
}

__global__ __launch_bounds__(256) void split_k_kernel(
    const float* __restrict__ qkv, __nv_bfloat16* __restrict__ kh,
    __nv_bfloat16* __restrict__ kl, int T)
{
    int i = blockIdx.x * blockDim.x + threadIdx.x;
    if (i >= T * 256) return;
    int t = i >> 8, c4 = i & 255;
    int d = c4 * 4;
    int kvh = d >> 7, dd = d & 127;
    float4 v = *(const float4*)&qkv[(size_t)t * QKV_COLS + Q_SIZE + d];
    __nv_bfloat16 h0, h1, h2, h3, l0, l1, l2, l3;
    split_bf(v.x, h0, l0); split_bf(v.y, h1, l1);
    split_bf(v.z, h2, l2); split_bf(v.w, h3, l3);
    uint2 uh; uh.x = pack_bf2(h0, h1); uh.y = pack_bf2(h2, h3);
    uint2 ul; ul.x = pack_bf2(l0, l1); ul.y = pack_bf2(l2, l3);
    size_t o = (size_t)kvh * T * HEAD_DIM + (size_t)t * HEAD_DIM + dd;
    *(uint2*)&kh[o] = uh;
    *(uint2*)&kl[o] = ul;
}

__global__ void vtrans_kernel(
    const float* __restrict__ qkv, __nv_bfloat16* __restrict__ vh,
    __nv_bfloat16* __restrict__ vl, int T)
{
    __shared__ float tile[32][33];
    const int kvh = blockIdx.z;
    const int d0 = blockIdx.y * 32;
    const int t0 = blockIdx.x * 32;
    for (int j = threadIdx.y; j < 32; j += 8) {
        tile[j][threadIdx.x] = qkv[(size_t)(t0 + j) * QKV_COLS + Q_SIZE + KV_SIZE
                                   + kvh * HEAD_DIM + d0 + threadIdx.x];
    }
    __syncthreads();
    for (int j = threadIdx.y; j < 32; j += 8) {
        float v = tile[threadIdx.x][j];
        __nv_bfloat16 h, l;
        split_bf(v, h, l);
        size_t o = (size_t)kvh * HEAD_DIM * T + (size_t)(d0 + j) * T + t0 + threadIdx.x;
        vh[o] = h;
        vl[o] = l;
    }
}

// ---------------------------------------------------------------------------
// HMMA GEMM, 2-term bf16 split, cp.async double-buffered, ldmatrix frags.
// C[M,N] = A[M,K] * B[N,K]^T = Ah*Bh + Ah*Bl + Al*Bh.
// ---------------------------------------------------------------------------
#define XBM 128
#define XBN 128
#define XBK 32
#define XSTR 40
#define STAGE_E (XBM * XSTR)
#define GEMM_SMEM (8 * STAGE_E * 2)   // 81920 bytes

__global__ __launch_bounds__(256, 2) void gemm_bf16s(
    const __nv_bfloat16* __restrict__ Ah, const __nv_bfloat16* __restrict__ Al,
    const __nv_bfloat16* __restrict__ Bh, const __nv_bfloat16* __restrict__ Bl,
    float* __restrict__ C, int M, int N, int K)
{
    extern __shared__ __nv_bfloat16 smg[];
    const uint32_t smb = smem_to_u32(smg);

    const int tid  = threadIdx.x;
    const int lane = tid & 31;
    const int wid  = tid >> 5;
    const int gid  = lane >> 2;
    const int tq   = lane & 3;
    const int wm   = (wid & 3) * 32;
    const int wn   = (wid >> 2) * 64;

    // ldmatrix per-lane mappings
    const int arow  = lane & 15;                         // A: m within 16
    const int acol8 = (lane >> 4) << 3;                  // A: k half
    const int brow  = ((lane >> 4) << 3) + (lane & 7);   // B: n within 16
    const int bcol8 = ((lane >> 3) & 1) << 3;            // B: k half

    const int bm = blockIdx.y * XBM;
    const int bn = blockIdx.x * XBN;

    #define G_ISSUE(stage, k0) do { \
        uint32_t sb0 = smb + (uint32_t)(stage) * 4 * STAGE_E * 2; \
        _Pragma("unroll") \
        for (int j = 0; j < 2; j++) { \
            int id = tid + j * 256; \
            int r = id >> 2, c = (id & 3) * 8; \
            size_t aoff = (size_t)(bm + r) * K + (k0) + c; \
            size_t boff = (size_t)(bn + r) * K + (k0) + c; \
            uint32_t doff = (uint32_t)(r * XSTR + c) * 2; \
            CP_ASYNC16(sb0 + doff, Ah + aoff); \
            CP_ASYNC16(sb0 + STAGE_E * 2 + doff, Al + aoff); \
            CP_ASYNC16(sb0 + 2 * STAGE_E * 2 + doff, Bh + boff); \
            CP_ASYNC16(sb0 + 3 * STAGE_E * 2 + doff, Bl + boff); \
        } \
    } while (0)

    float acc[2][8][4] = {};

    G_ISSUE(0, 0);
    CP_COMMIT();

    int stage = 0;
    for (int k0 = 0; k0 < K; k0 += XBK, stage ^= 1) {
        if (k0 + XBK < K) {
            G_ISSUE(stage ^ 1, k0 + XBK);
            CP_COMMIT();
            CP_WAIT(1);
        } else {
            CP_WAIT(0);
        }
        __syncthreads();

        const uint32_t sAh = smb + (uint32_t)stage * 4 * STAGE_E * 2;
        const uint32_t sAl = sAh + STAGE_E * 2;
        const uint32_t sBh = sAl + STAGE_E * 2;
        const uint32_t sBl = sBh + STAGE_E * 2;

        #pragma unroll
        for (int kk = 0; kk < XBK; kk += 16) {
            uint32_t ah[2][4], al[2][4];
            #pragma unroll
            for (int mt = 0; mt < 2; mt++) {
                uint32_t aoff = (uint32_t)((wm + mt * 16 + arow) * XSTR + kk + acol8) * 2;
                LDSM_X4(ah[mt][0], ah[mt][1], ah[mt][2], ah[mt][3], sAh + aoff);
                LDSM_X4(al[mt][0], al[mt][1], al[mt][2], al[mt][3], sAl + aoff);
            }
            #pragma unroll
            for (int p = 0; p < 4; p++) {
                uint32_t boff = (uint32_t)((wn + p * 16 + brow) * XSTR + kk + bcol8) * 2;
                uint32_t bh0, bh1, bh2, bh3, bl0, bl1, bl2, bl3;
                LDSM_X4(bh0, bh1, bh2, bh3, sBh + boff);
                LDSM_X4(bl0, bl1, bl2, bl3, sBl + boff);
                #pragma unroll
                for (int mt = 0; mt < 2; mt++) {
                    mma_bf16(acc[mt][2 * p], ah[mt], bh0, bh1);
                    mma_bf16(acc[mt][2 * p], ah[mt], bl0, bl1);
                    mma_bf16(acc[mt][2 * p], al[mt], bh0, bh1);
                    mma_bf16(acc[mt][2 * p + 1], ah[mt], bh2, bh3);
                    mma_bf16(acc[mt][2 * p + 1], ah[mt], bl2, bl3);
                    mma_bf16(acc[mt][2 * p + 1], al[mt], bh2, bh3);
                }
            }
        }
        __syncthreads();
    }

    #pragma unroll
    for (int mt = 0; mt < 2; mt++) {
        int row = bm + wm + mt * 16 + gid;
        #pragma unroll
        for (int nt = 0; nt < 8; nt++) {
            int col = bn + wn + nt * 8 + tq * 2;
            *(float2*)&C[(size_t)row * N + col] =
                make_float2(acc[mt][nt][0], acc[mt][nt][1]);
            *(float2*)&C[(size_t)(row + 8) * N + col] =
                make_float2(acc[mt][nt][2], acc[mt][nt][3]);
        }
    }
}

// ---------------------------------------------------------------------------
// RMSNorm + RoPE (unchanged)
// ---------------------------------------------------------------------------
__global__ __launch_bounds__(256) void normrope_kernel(
    float* __restrict__ qkv,
    const float* __restrict__ qw, const float* __restrict__ kw,
    const int* __restrict__ positions, int T)
{
    const int warp = (blockIdx.x * blockDim.x + threadIdx.x) >> 5;
    const int lane = threadIdx.x & 31;
    if (warp >= T * 24) return;
    const int t = warp / 24;
    const int h = warp % 24;

    float* x = qkv + (size_t)t * QKV_COLS + h * HEAD_DIM;
    const float* nw = (h < 16) ? qw : kw;

    float v0 = x[lane], v1 = x[lane + 32], v2 = x[lane + 64], v3 = x[lane + 96];
    float ss = v0 * v0 + v1 * v1 + v2 * v2 + v3 * v3;
    #pragma unroll
    for (int o = 16; o; o >>= 1) ss += __shfl_xor_sync(0xffffffffu, ss, o);
    const float rn = rsqrtf(ss * (1.0f / HEAD_DIM) + RMS_EPS);

    float n0 = v0 * rn * nw[lane];
    float n1 = v1 * rn * nw[lane + 32];
    float n2 = v2 * rn * nw[lane + 64];
    float n3 = v3 * rn * nw[lane + 96];

    const double pos = (double)positions[t];
    const double LOG_THETA = 13.815510557964274;
    double f0 = exp(-((double)(2 * lane) / 128.0) * LOG_THETA);
    double f1 = exp(-((double)(2 * (lane + 32)) / 128.0) * LOG_THETA);
    double s0d, c0d, s1d, c1d;
    sincos(pos * f0, &s0d, &c0d);
    sincos(pos * f1, &s1d, &c1d);
    float c0 = (float)c0d, s0 = (float)s0d, c1 = (float)c1d, s1 = (float)s1d;

    x[lane]      = n0 * c0 - n2 * s0;
    x[lane + 64] = n2 * c0 + n0 * s0;
    x[lane + 32] = n1 * c1 - n3 * s1;
    x[lane + 96] = n3 * c1 + n1 * s1;
}

// ---------------------------------------------------------------------------
// HMMA flash attention: precomputed split Q/K/V, cp.async pipelining,
// ldmatrix fragment loads.
// ---------------------------------------------------------------------------
#define SSTR 136
#define TILE_B (128 * SSTR * 2)
#define QHO (0 * TILE_B)
#define QLO (1 * TILE_B)
#define KHO (2 * TILE_B)
#define KLO (3 * TILE_B)
#define VHO (4 * TILE_B)
#define VLO (5 * TILE_B)
#define ATT_SMEM (6 * TILE_B)

__global__ __launch_bounds__(256, 1) void attn_mma(
    const __nv_bfloat16* __restrict__ qh_g, const __nv_bfloat16* __restrict__ ql_g,
    const __nv_bfloat16* __restrict__ kh_g, const __nv_bfloat16* __restrict__ kl_g,
    const __nv_bfloat16* __restrict__ vh_g, const __nv_bfloat16* __restrict__ vl_g,
    __nv_bfloat16* __restrict__ attn_h, __nv_bfloat16* __restrict__ attn_l, int T)
{
    extern __shared__ char sm[];
    const uint32_t smb = smem_to_u32(sm);
    const int tid  = threadIdx.x;
    const int lane = tid & 31;
    const int wid  = tid >> 5;
    const int gid  = lane >> 2;
    const int tq   = lane & 3;

    const int qb   = (gridDim.x - 1) - blockIdx.x;
    const int head = blockIdx.y;
    const int kvh  = head >> 1;
    const int q0   = qb * 128;
    const int wrow = wid * 16;
    const int iters = qb + 1;

    // ldmatrix per-lane mappings
    const int arow  = lane & 15;
    const int acol8 = (lane >> 4) << 3;
    const int brow  = ((lane >> 4) << 3) + (lane & 7);
    const int bcol8 = ((lane >> 3) & 1) << 3;

    const size_t kbase = (size_t)kvh * T * HEAD_DIM;
    const size_t vbase = (size_t)kvh * HEAD_DIM * T;

    // ---- Prologue: prefetch K(0), V(0) ----
    for (int i = tid; i < 2048; i += 256) {
        int r = i >> 4, c = (i & 15) << 3;
        uint32_t doff = (uint32_t)(r * SSTR + c) * 2;
        CP_ASYNC16(smb + KHO + doff, kh_g + kbase + (size_t)r * HEAD_DIM + c);
        CP_ASYNC16(smb + KLO + doff, kl_g + kbase + (size_t)r * HEAD_DIM + c);
    }
    CP_COMMIT();
    for (int i = tid; i < 2048; i += 256) {
        int d = i >> 4, c = (i & 15) << 3;
        uint32_t doff = (uint32_t)(d * SSTR + c) * 2;
        CP_ASYNC16(smb + VHO + doff, vh_g + vbase + (size_t)d * T + c);
        CP_ASYNC16(smb + VLO + doff, vl_g + vbase + (size_t)d * T + c);
    }
    CP_COMMIT();

    // ---- Stage Q ----
    for (int i = tid; i < 2048; i += 256) {
        int r = i >> 4, c = (i & 15) << 3;
        uint32_t doff = (uint32_t)(r * SSTR + c) * 2;
        size_t o = (size_t)(q0 + r) * Q_SIZE + head * HEAD_DIM + c;
        *(uint4*)(sm + QHO + doff) = *(const uint4*)&qh_g[o];
        *(uint4*)(sm + QLO + doff) = *(const uint4*)&ql_g[o];
    }
    __syncthreads();

    // ---- Persistent Q fragments via ldmatrix ----
    uint32_t qh[8][4], ql[8][4];
    #pragma unroll
    for (int kt = 0; kt < 8; kt++) {
        uint32_t aoff = (uint32_t)((wrow + arow) * SSTR + kt * 16 + acol8) * 2;
        LDSM_X4(qh[kt][0], qh[kt][1], qh[kt][2], qh[kt][3], smb + QHO + aoff);
        LDSM_X4(ql[kt][0], ql[kt][1], ql[kt][2], ql[kt][3], smb + QLO + aoff);
    }

    const int grow0 = q0 + wrow + gid;
    const int grow1 = grow0 + 8;

    float m0 = -1e30f, m1 = -1e30f, l0s = 0.0f, l1s = 0.0f;
    float o[16][4] = {};

    for (int it = 0; it < iters; it++) {
        const int k0 = it * 128;

        CP_WAIT(1);      // K(it) ready
        __syncthreads();

        // ---- S = Q K^T ----
        float s[16][4];
        #pragma unroll
        for (int nt = 0; nt < 16; nt++)
            #pragma unroll
            for (int c = 0; c < 4; c++) s[nt][c] = 0.0f;

        #pragma unroll
        for (int kt = 0; kt < 8; kt++) {
            #pragma unroll
            for (int p = 0; p < 8; p++) {
                uint32_t boff = (uint32_t)((p * 16 + brow) * SSTR + kt * 16 + bcol8) * 2;
                uint32_t bh0, bh1, bh2, bh3, bl0, bl1, bl2, bl3;
                LDSM_X4(bh0, bh1, bh2, bh3, smb + KHO + boff);
                LDSM_X4(bl0, bl1, bl2, bl3, smb + KLO + boff);
                mma_bf16(s[2 * p], qh[kt], bh0, bh1);
                mma_bf16(s[2 * p], qh[kt], bl0, bl1);
                mma_bf16(s[2 * p], ql[kt], bh0, bh1);
                mma_bf16(s[2 * p + 1], qh[kt], bh2, bh3);
                mma_bf16(s[2 * p + 1], qh[kt], bl2, bl3);
                mma_bf16(s[2 * p + 1], ql[kt], bh2, bh3);
            }
        }
        __syncthreads();

        // ---- Prefetch K(it+1) ----
        if (it + 1 < iters) {
            const size_t ko = kbase + (size_t)(it + 1) * 128 * HEAD_DIM;
            for (int i = tid; i < 2048; i += 256) {
                int r = i >> 4, c = (i & 15) << 3;
                uint32_t doff = (uint32_t)(r * SSTR + c) * 2;
                CP_ASYNC16(smb + KHO + doff, kh_g + ko + (size_t)r * HEAD_DIM + c);
                CP_ASYNC16(smb + KLO + doff, kl_g + ko + (size_t)r * HEAD_DIM + c);
            }
        }
        CP_COMMIT();

        // ---- scale + mask + online softmax ----
        const bool diag = (it == qb);
        float mx0 = m0, mx1 = m1;
        #pragma unroll
        for (int nt = 0; nt < 16; nt++) {
            int colb = k0 + nt * 8 + tq * 2;
            #pragma unroll
            for (int c = 0; c < 2; c++) {
                float v0 = s[nt][c] * SCALE;
                float v1 = s[nt][c + 2] * SCALE;
                if (diag && (colb + c > grow0)) v0 = -1e30f;
                if (diag && (colb + c > grow1)) v1 = -1e30f;
                s[nt][c] = v0; s[nt][c + 2] = v1;
                mx0 = fmaxf(mx0, v0); mx1 = fmaxf(mx1, v1);
            }
        }
        mx0 = fmaxf(mx0, __shfl_xor_sync(0xffffffffu, mx0, 1));
        mx0 = fmaxf(mx0, __shfl_xor_sync(0xffffffffu, mx0, 2));
        mx1 = fmaxf(mx1, __shfl_xor_sync(0xffffffffu, mx1, 1));
        mx1 = fmaxf(mx1, __shfl_xor_sync(0xffffffffu, mx1, 2));

        const float a0 = __expf(m0 - mx0);
        const float a1 = __expf(m1 - mx1);
        m0 = mx0; m1 = mx1;

        float sum0 = 0.0f, sum1 = 0.0f;
        #pragma unroll
        for (int nt = 0; nt < 16; nt++) {
            #pragma unroll
            for (int c = 0; c < 2; c++) {
                float p0 = __expf(s[nt][c] - m0);
                float p1 = __expf(s[nt][c + 2] - m1);
                s[nt][c] = p0; s[nt][c + 2] = p1;
                sum0 += p0; sum1 += p1;
            }
        }
        sum0 += __shfl_xor_sync(0xffffffffu, sum0, 1);
        sum0 += __shfl_xor_sync(0xffffffffu, sum0, 2);
        sum1 += __shfl_xor_sync(0xffffffffu, sum1, 1);
        sum1 += __shfl_xor_sync(0xffffffffu, sum1, 2);
        l0s = l0s * a0 + sum0;
        l1s = l1s * a1 + sum1;

        #pragma unroll
        for (int nt = 0; nt < 16; nt++) {
            o[nt][0] *= a0; o[nt][1] *= a0;
            o[nt][2] *= a1; o[nt][3] *= a1;
        }

        CP_WAIT(1);      // V(it) ready
        __syncthreads();

        // ---- O += P @ V ----
        #pragma unroll
        for (int kt = 0; kt < 8; kt++) {
            uint32_t ph[4], pl[4];
            {
                __nv_bfloat16 h00, l00, h01, l01, h10, l10, h11, l11;
                split_bf(s[2 * kt][0], h00, l00); split_bf(s[2 * kt][1], h01, l01);
                split_bf(s[2 * kt][2], h10, l10); split_bf(s[2 * kt][3], h11, l11);
                ph[0] = pack_bf2(h00, h01); pl[0] = pack_bf2(l00, l01);
                ph[1] = pack_bf2(h10, h11); pl[1] = pack_bf2(l10, l11);
                split_bf(s[2 * kt + 1][0], h00, l00); split_bf(s[2 * kt + 1][1], h01, l01);
                split_bf(s[2 * kt + 1][2], h10, l10); split_bf(s[2 * kt + 1][3], h11, l11);
                ph[2] = pack_bf2(h00, h01); pl[2] = pack_bf2(l00, l01);
                ph[3] = pack_bf2(h10, h11); pl[3] = pack_bf2(l10, l11);
            }
            #pragma unroll
            for (int p = 0; p < 8; p++) {
                uint32_t boff = (uint32_t)((p * 16 + brow) * SSTR + kt * 16 + bcol8) * 2;
                uint32_t vh0, vh1, vh2, vh3, vl0, vl1, vl2, vl3;
                LDSM_X4(vh0, vh1, vh2, vh3, smb + VHO + boff);
                LDSM_X4(vl0, vl1, vl2, vl3, smb + VLO + boff);
                mma_bf16(o[2 * p], ph, vh0, vh1);
                mma_bf16(o[2 * p], ph, vl0, vl1);
                mma_bf16(o[2 * p], pl, vh0, vh1);
                mma_bf16(o[2 * p + 1], ph, vh2, vh3);
                mma_bf16(o[2 * p + 1], ph, vl2, vl3);
                mma_bf16(o[2 * p + 1], pl, vh2, vh3);
            }
        }
        __syncthreads();

        // ---- Prefetch V(it+1) ----
        if (it + 1 < iters) {
            const int nk0 = (it + 1) * 128;
            for (int i = tid; i < 2048; i += 256) {
                int d = i >> 4, c = (i & 15) << 3;
                uint32_t doff = (uint32_t)(d * SSTR + c) * 2;
                CP_ASYNC16(smb + VHO + doff, vh_g + vbase + (size_t)d * T + nk0 + c);
                CP_ASYNC16(smb + VLO + doff, vl_g + vbase + (size_t)d * T + nk0 + c);
            }
        }
        CP_COMMIT();
    }

    // ---- Epilogue ----
    const float inv0 = 1.0f / l0s;
    const float inv1 = 1.0f / l1s;
    #pragma unroll
    for (int nt = 0; nt < 16; nt++) {
        int dcol = head * HEAD_DIM + nt * 8 + tq * 2;
        float w00 = o[nt][0] * inv0, w01 = o[nt][1] * inv0;
        float w10 = o[nt][2] * inv1, w11 = o[nt][3] * inv1;
        __nv_bfloat16 h0, l0, h1, l1;
        split_bf(w00, h0, l0); split_bf(w01, h1, l1);
        *(uint32_t*)&attn_h[(size_t)grow0 * Q_SIZE + dcol] = pack_bf2(h0, h1);
        *(uint32_t*)&attn_l[(size_t)grow0 * Q_SIZE + dcol] = pack_bf2(l0, l1);
        split_bf(w10, h0, l0); split_bf(w11, h1, l1);
        *(uint32_t*)&attn_h[(size_t)grow1 * Q_SIZE + dcol] = pack_bf2(h0, h1);
        *(uint32_t*)&attn_l[(size_t)grow1 * Q_SIZE + dcol] = pack_bf2(l0, l1);
    }
}

// ---------------------------------------------------------------------------
// Launch
// ---------------------------------------------------------------------------
extern "C" void kernel_launch(void* const* d_in, const int* in_sizes, int n_in,
                              void* d_out, int out_size)
{
    const float* hidden = (const float*)d_in[0];
    const float* qkv_w  = (const float*)d_in[1];
    const float* q_nw   = (const float*)d_in[2];
    const float* k_nw   = (const float*)d_in[3];
    const float* o_w    = (const float*)d_in[4];
    const int*   pos    = (const int*)d_in[5];
    float* out = (float*)d_out;

    const int T = in_sizes[0] / HIDDEN;

    float* qkv;  cudaGetSymbolAddress((void**)&qkv,  g_qkv);
    __nv_bfloat16 *hid_h, *hid_l, *w1_h, *w1_l, *w2_h, *w2_l, *at_h, *at_l;
    __nv_bfloat16 *q_h, *q_l, *k_h, *k_l, *v_h, *v_l;
    cudaGetSymbolAddress((void**)&hid_h, g_hid_h);
    cudaGetSymbolAddress((void**)&hid_l, g_hid_l);
    cudaGetSymbolAddress((void**)&w1_h,  g_w1_h);
    cudaGetSymbolAddress((void**)&w1_l,  g_w1_l);
    cudaGetSymbolAddress((void**)&w2_h,  g_w2_h);
    cudaGetSymbolAddress((void**)&w2_l,  g_w2_l);
    cudaGetSymbolAddress((void**)&at_h,  g_at_h);
    cudaGetSymbolAddress((void**)&at_l,  g_at_l);
    cudaGetSymbolAddress((void**)&q_h,   g_q_h);
    cudaGetSymbolAddress((void**)&q_l,   g_q_l);
    cudaGetSymbolAddress((void**)&k_h,   g_k_h);
    cudaGetSymbolAddress((void**)&k_l,   g_k_l);
    cudaGetSymbolAddress((void**)&v_h,   g_v_h);
    cudaGetSymbolAddress((void**)&v_l,   g_v_l);

    cudaFuncSetAttribute(attn_mma, cudaFuncAttributeMaxDynamicSharedMemorySize,
                         ATT_SMEM);
    cudaFuncSetAttribute(gemm_bf16s, cudaFuncAttributeMaxDynamicSharedMemorySize,
                         GEMM_SMEM);

    // 0) Split inputs
    {
        int n4 = T * HIDDEN / 4;
        split_kernel<<<(n4 + 255) / 256, 256>>>(hidden, hid_h, hid_l, n4);
        n4 = QKV_COLS * HIDDEN / 4;
        split_kernel<<<(n4 + 255) / 256, 256>>>(qkv_w, w1_h, w1_l, n4);
        n4 = HIDDEN * Q_SIZE / 4;
        split_kernel<<<(n4 + 255) / 256, 256>>>(o_w, w2_h, w2_l, n4);
    }
    // 1) QKV projection
    {
        dim3 grid(QKV_COLS / XBN, T / XBM);
        gemm_bf16s<<<grid, 256, GEMM_SMEM>>>(hid_h, hid_l, w1_h, w1_l, qkv,
                                             T, QKV_COLS, HIDDEN);
    }
    // 2) RMSNorm + RoPE
    {
        int warps = T * 24;
        int blocks = (warps + 7) / 8;
        normrope_kernel<<<blocks, 256>>>(qkv, q_nw, k_nw, pos, T);
    }
    // 3) Split Q/K, transpose+split V
    {
        int n = T * 512;
        split_q_kernel<<<(n + 255) / 256, 256>>>(qkv, q_h, q_l, T);
        n = T * 256;
        split_k_kernel<<<(n + 255) / 256, 256>>>(qkv, k_h, k_l, T);
        dim3 vg(T / 32, HEAD_DIM / 32, NUM_KV);
        vtrans_kernel<<<vg, dim3(32, 8)>>>(qkv, v_h, v_l, T);
    }
    // 4) Attention
    {
        dim3 grid(T / 128, NUM_HEADS);
        attn_mma<<<grid, 256, ATT_SMEM>>>(q_h, q_l, k_h, k_l, v_h, v_l,
                                          at_h, at_l, T);
    }
    // 5) Output projection
    {
        dim3 grid(HIDDEN / XBN, T / XBM);
        gemm_bf16s<<<grid, 256, GEMM_SMEM>>>(at_h, at_l, w2_h, w2_l, out,
                                             T, HIDDEN, HIDDEN);
    }
}

// round 7
// speedup vs baseline: 3.6893x; 1.0782x over previous
#include <cuda_runtime.h>
#include <cuda_bf16.h>
#include <cuda_fp16.h>
#include <math.h>
#include <float.h>
#include <cstdint>

// Problem constants
#define HIDDEN    2048
#define NUM_HEADS 16
#define NUM_KV    8
#define HEAD_DIM  128
#define Q_SIZE    (NUM_HEADS * HEAD_DIM)        // 2048
#define KV_SIZE   (NUM_KV * HEAD_DIM)           // 1024
#define QKV_COLS  (Q_SIZE + 2 * KV_SIZE)        // 4096
#define SCALE     0.08838834764831845f          // 128^-0.5
#define SCALE_L2E 0.12751985675839602f          // SCALE * log2(e)
#define RMS_EPS   1e-6f

#define MAX_T 4096

// Scratch (static device globals)
__device__ float g_qkv[(size_t)MAX_T * QKV_COLS];
__device__ __nv_bfloat16 g_hid_h[(size_t)MAX_T * HIDDEN];
__device__ __nv_bfloat16 g_hid_l[(size_t)MAX_T * HIDDEN];
__device__ __nv_bfloat16 g_w1_h[(size_t)QKV_COLS * HIDDEN];
__device__ __nv_bfloat16 g_w1_l[(size_t)QKV_COLS * HIDDEN];
__device__ __nv_bfloat16 g_w2_h[(size_t)HIDDEN * Q_SIZE];
__device__ __nv_bfloat16 g_w2_l[(size_t)HIDDEN * Q_SIZE];
__device__ __nv_bfloat16 g_at_h[(size_t)MAX_T * Q_SIZE];
__device__ __nv_bfloat16 g_at_l[(size_t)MAX_T * Q_SIZE];
// fp16 split Q/K/V for attention
__device__ __half g_q_h[(size_t)MAX_T * Q_SIZE];
__device__ __half g_q_l[(size_t)MAX_T * Q_SIZE];
__device__ __half g_k_h[(size_t)NUM_KV * MAX_T * HEAD_DIM];
__device__ __half g_k_l[(size_t)NUM_KV * MAX_T * HEAD_DIM];
__device__ __half g_v_h[(size_t)NUM_KV * HEAD_DIM * MAX_T];  // [kvh][d][t]
__device__ __half g_v_l[(size_t)NUM_KV * HEAD_DIM * MAX_T];

// ===========================================================================
// Helpers
// ===========================================================================
__device__ __forceinline__ uint32_t smem_to_u32(const void* p) {
    uint32_t a;
    asm("{ .reg .u64 t; cvta.to.shared.u64 t, %1; cvt.u32.u64 %0, t; }"
        : "=r"(a) : "l"(p));
    return a;
}
__device__ __forceinline__ uint32_t pack_bf2(__nv_bfloat16 a, __nv_bfloat16 b) {
    __nv_bfloat162 t = __halves2bfloat162(a, b);
    return *reinterpret_cast<uint32_t*>(&t);
}
__device__ __forceinline__ void split_bf(float x, __nv_bfloat16& h, __nv_bfloat16& l) {
    h = __float2bfloat16(x);
    l = __float2bfloat16(x - __bfloat162float(h));
}
__device__ __forceinline__ void split_h16(float x, __half& h, __half& l) {
    h = __float2half_rn(x);
    l = __float2half_rn(x - __half2float(h));
}
__device__ __forceinline__ float ex2f(float x) {
    float r;
    asm("ex2.approx.f32 %0, %1;" : "=f"(r) : "f"(x));
    return r;
}
// pack two fp32 -> f16x2 (lo = a, hi = b)
__device__ __forceinline__ uint32_t cvt_h2(float a, float b) {
    uint32_t r;
    asm("cvt.rn.f16x2.f32 %0, %1, %2;" : "=r"(r) : "f"(b), "f"(a));
    return r;
}

// warp mma bf16: D(16x8,f32) += A(16x16) * B(16x8)
__device__ __forceinline__ void mma_bf16(float* d, const uint32_t* a,
                                         uint32_t b0, uint32_t b1) {
    asm volatile(
        "mma.sync.aligned.m16n8k16.row.col.f32.bf16.bf16.f32 "
        "{%0,%1,%2,%3}, {%4,%5,%6,%7}, {%8,%9}, {%0,%1,%2,%3};"
        : "+f"(d[0]), "+f"(d[1]), "+f"(d[2]), "+f"(d[3])
        : "r"(a[0]), "r"(a[1]), "r"(a[2]), "r"(a[3]), "r"(b0), "r"(b1));
}
// warp mma fp16
__device__ __forceinline__ void mma_f16(float* d, const uint32_t* a,
                                        uint32_t b0, uint32_t b1) {
    asm volatile(
        "mma.sync.aligned.m16n8k16.row.col.f32.f16.f16.f32 "
        "{%0,%1,%2,%3}, {%4,%5,%6,%7}, {%8,%9}, {%0,%1,%2,%3};"
        : "+f"(d[0]), "+f"(d[1]), "+f"(d[2]), "+f"(d[3])
        : "r"(a[0]), "r"(a[1]), "r"(a[2]), "r"(a[3]), "r"(b0), "r"(b1));
}

#define LDSM_X4(r0, r1, r2, r3, addr) \
    asm volatile("ldmatrix.sync.aligned.m8n8.x4.shared.b16 {%0,%1,%2,%3}, [%4];" \
        : "=r"(r0), "=r"(r1), "=r"(r2), "=r"(r3) : "r"(addr))

#define CP_ASYNC16(dst, src) \
    asm volatile("cp.async.cg.shared.global [%0], [%1], 16;" \
        :: "r"(dst), "l"(src))
#define CP_COMMIT() asm volatile("cp.async.commit_group;")
#define CP_WAIT(n)  asm volatile("cp.async.wait_group %0;" :: "n"(n))

// ---------------------------------------------------------------------------
// Split fp32 -> bf16 hi/lo (weights + hidden, for GEMMs)
// ---------------------------------------------------------------------------
__global__ __launch_bounds__(256) void split_kernel(
    const float* __restrict__ src, __nv_bfloat16* __restrict__ h,
    __nv_bfloat16* __restrict__ l, int n4)
{
    int i = blockIdx.x * blockDim.x + threadIdx.x;
    if (i >= n4) return;
    float4 v = ((const float4*)src)[i];
    __nv_bfloat16 h0, h1, h2, h3, l0, l1, l2, l3;
    split_bf(v.x, h0, l0); split_bf(v.y, h1, l1);
    split_bf(v.z, h2, l2); split_bf(v.w, h3, l3);
    uint2 uh; uh.x = pack_bf2(h0, h1); uh.y = pack_bf2(h2, h3);
    uint2 ul; ul.x = pack_bf2(l0, l1); ul.y = pack_bf2(l2, l3);
    ((uint2*)h)[i] = uh;
    ((uint2*)l)[i] = ul;
}

// ---------------------------------------------------------------------------
// Fused RMSNorm + RoPE + fp16 hi/lo split for Q and K.
// One warp per (token, head); reads raw g_qkv, writes fp16 split buffers.
// ---------------------------------------------------------------------------
__global__ __launch_bounds__(256) void normrope_split_kernel(
    const float* __restrict__ qkv,
    const float* __restrict__ qw, const float* __restrict__ kw,
    const int* __restrict__ positions,
    __half* __restrict__ qh_g, __half* __restrict__ ql_g,
    __half* __restrict__ kh_g, __half* __restrict__ kl_g, int T)
{
    const int warp = (blockIdx.x * blockDim.x + threadIdx.x) >> 5;
    const int lane = threadIdx.x & 31;
    if (warp >= T * 24) return;
    const int t = warp / 24;
    const int h = warp % 24;

    const float* x = qkv + (size_t)t * QKV_COLS + h * HEAD_DIM;
    const float* nw = (h < 16) ? qw : kw;

    float v0 = x[lane], v1 = x[lane + 32], v2 = x[lane + 64], v3 = x[lane + 96];
    float ss = v0 * v0 + v1 * v1 + v2 * v2 + v3 * v3;
    #pragma unroll
    for (int o = 16; o; o >>= 1) ss += __shfl_xor_sync(0xffffffffu, ss, o);
    const float rn = rsqrtf(ss * (1.0f / HEAD_DIM) + RMS_EPS);

    float n0 = v0 * rn * nw[lane];
    float n1 = v1 * rn * nw[lane + 32];
    float n2 = v2 * rn * nw[lane + 64];
    float n3 = v3 * rn * nw[lane + 96];

    const double pos = (double)positions[t];
    const double LOG_THETA = 13.815510557964274;
    double f0 = exp(-((double)(2 * lane) / 128.0) * LOG_THETA);
    double f1 = exp(-((double)(2 * (lane + 32)) / 128.0) * LOG_THETA);
    double s0d, c0d, s1d, c1d;
    sincos(pos * f0, &s0d, &c0d);
    sincos(pos * f1, &s1d, &c1d);
    float c0 = (float)c0d, s0 = (float)s0d, c1 = (float)c1d, s1 = (float)s1d;

    float r0 = n0 * c0 - n2 * s0;    // pos lane
    float r2 = n2 * c0 + n0 * s0;    // pos lane+64
    float r1 = n1 * c1 - n3 * s1;    // pos lane+32
    float r3 = n3 * c1 + n1 * s1;    // pos lane+96

    __half h0, l0, h1, l1, h2, l2, h3, l3;
    split_h16(r0, h0, l0); split_h16(r1, h1, l1);
    split_h16(r2, h2, l2); split_h16(r3, h3, l3);

    __half *dh, *dl;
    size_t base;
    if (h < 16) {
        base = (size_t)t * Q_SIZE + h * HEAD_DIM;
        dh = qh_g; dl = ql_g;
    } else {
        base = (size_t)(h - 16) * T * HEAD_DIM + (size_t)t * HEAD_DIM;
        dh = kh_g; dl = kl_g;
    }
    dh[base + lane] = h0;      dl[base + lane] = l0;
    dh[base + lane + 32] = h1; dl[base + lane + 32] = l1;
    dh[base + lane + 64] = h2; dl[base + lane + 64] = l2;
    dh[base + lane + 96] = h3; dl[base + lane + 96] = l3;
}

// Transpose + fp16 split V -> [kvh][d][t]
__global__ void vtrans_kernel(
    const float* __restrict__ qkv, __half* __restrict__ vh,
    __half* __restrict__ vl, int T)
{
    __shared__ float tile[32][33];
    const int kvh = blockIdx.z;
    const int d0 = blockIdx.y * 32;
    const int t0 = blockIdx.x * 32;
    for (int j = threadIdx.y; j < 32; j += 8) {
        tile[j][threadIdx.x] = qkv[(size_t)(t0 + j) * QKV_COLS + Q_SIZE + KV_SIZE
                                   + kvh * HEAD_DIM + d0 + threadIdx.x];
    }
    __syncthreads();
    for (int j = threadIdx.y; j < 32; j += 8) {
        float v = tile[threadIdx.x][j];
        __half h, l;
        split_h16(v, h, l);
        size_t o = (size_t)kvh * HEAD_DIM * T + (size_t)(d0 + j) * T + t0 + threadIdx.x;
        vh[o] = h;
        vl[o] = l;
    }
}

// ---------------------------------------------------------------------------
// HMMA GEMM (bf16 3-combo, unchanged from R6)
// ---------------------------------------------------------------------------
#define XBM 128
#define XBN 128
#define XBK 32
#define XSTR 40
#define STAGE_E (XBM * XSTR)
#define GEMM_SMEM (8 * STAGE_E * 2)

__global__ __launch_bounds__(256, 2) void gemm_bf16s(
    const __nv_bfloat16* __restrict__ Ah, const __nv_bfloat16* __restrict__ Al,
    const __nv_bfloat16* __restrict__ Bh, const __nv_bfloat16* __restrict__ Bl,
    float* __restrict__ C, int M, int N, int K)
{
    extern __shared__ __nv_bfloat16 smg[];
    const uint32_t smb = smem_to_u32(smg);

    const int tid  = threadIdx.x;
    const int lane = tid & 31;
    const int wid  = tid >> 5;
    const int gid  = lane >> 2;
    const int tq   = lane & 3;
    const int wm   = (wid & 3) * 32;
    const int wn   = (wid >> 2) * 64;

    const int arow  = lane & 15;
    const int acol8 = (lane >> 4) << 3;
    const int brow  = ((lane >> 4) << 3) + (lane & 7);
    const int bcol8 = ((lane >> 3) & 1) << 3;

    const int bm = blockIdx.y * XBM;
    const int bn = blockIdx.x * XBN;

    #define G_ISSUE(stage, k0) do { \
        uint32_t sb0 = smb + (uint32_t)(stage) * 4 * STAGE_E * 2; \
        _Pragma("unroll") \
        for (int j = 0; j < 2; j++) { \
            int id = tid + j * 256; \
            int r = id >> 2, c = (id & 3) * 8; \
            size_t aoff = (size_t)(bm + r) * K + (k0) + c; \
            size_t boff = (size_t)(bn + r) * K + (k0) + c; \
            uint32_t doff = (uint32_t)(r * XSTR + c) * 2; \
            CP_ASYNC16(sb0 + doff, Ah + aoff); \
            CP_ASYNC16(sb0 + STAGE_E * 2 + doff, Al + aoff); \
            CP_ASYNC16(sb0 + 2 * STAGE_E * 2 + doff, Bh + boff); \
            CP_ASYNC16(sb0 + 3 * STAGE_E * 2 + doff, Bl + boff); \
        } \
    } while (0)

    float acc[2][8][4] = {};

    G_ISSUE(0, 0);
    CP_COMMIT();

    int stage = 0;
    for (int k0 = 0; k0 < K; k0 += XBK, stage ^= 1) {
        if (k0 + XBK < K) {
            G_ISSUE(stage ^ 1, k0 + XBK);
            CP_COMMIT();
            CP_WAIT(1);
        } else {
            CP_WAIT(0);
        }
        __syncthreads();

        const uint32_t sAh = smb + (uint32_t)stage * 4 * STAGE_E * 2;
        const uint32_t sAl = sAh + STAGE_E * 2;
        const uint32_t sBh = sAl + STAGE_E * 2;
        const uint32_t sBl = sBh + STAGE_E * 2;

        #pragma unroll
        for (int kk = 0; kk < XBK; kk += 16) {
            uint32_t ah[2][4], al[2][4];
            #pragma unroll
            for (int mt = 0; mt < 2; mt++) {
                uint32_t aoff = (uint32_t)((wm + mt * 16 + arow) * XSTR + kk + acol8) * 2;
                LDSM_X4(ah[mt][0], ah[mt][1], ah[mt][2], ah[mt][3], sAh + aoff);
                LDSM_X4(al[mt][0], al[mt][1], al[mt][2], al[mt][3], sAl + aoff);
            }
            #pragma unroll
            for (int p = 0; p < 4; p++) {
                uint32_t boff = (uint32_t)((wn + p * 16 + brow) * XSTR + kk + bcol8) * 2;
                uint32_t bh0, bh1, bh2, bh3, bl0, bl1, bl2, bl3;
                LDSM_X4(bh0, bh1, bh2, bh3, sBh + boff);
                LDSM_X4(bl0, bl1, bl2, bl3, sBl + boff);
                #pragma unroll
                for (int mt = 0; mt < 2; mt++) {
                    mma_bf16(acc[mt][2 * p], ah[mt], bh0, bh1);
                    mma_bf16(acc[mt][2 * p], ah[mt], bl0, bl1);
                    mma_bf16(acc[mt][2 * p], al[mt], bh0, bh1);
                    mma_bf16(acc[mt][2 * p + 1], ah[mt], bh2, bh3);
                    mma_bf16(acc[mt][2 * p + 1], ah[mt], bl2, bl3);
                    mma_bf16(acc[mt][2 * p + 1], al[mt], bh2, bh3);
                }
            }
        }
        __syncthreads();
    }

    #pragma unroll
    for (int mt = 0; mt < 2; mt++) {
        int row = bm + wm + mt * 16 + gid;
        #pragma unroll
        for (int nt = 0; nt < 8; nt++) {
            int col = bn + wn + nt * 8 + tq * 2;
            *(float2*)&C[(size_t)row * N + col] =
                make_float2(acc[mt][nt][0], acc[mt][nt][1]);
            *(float2*)&C[(size_t)(row + 8) * N + col] =
                make_float2(acc[mt][nt][2], acc[mt][nt][3]);
        }
    }
}

// ---------------------------------------------------------------------------
// fp16 HMMA flash attention. QK: 3 combos (hi/lo split). PV: 2 combos
// (P single fp16 x V hi/lo). exp via raw ex2.approx with folded scale.
// ---------------------------------------------------------------------------
#define SSTR 136
#define TILE_B (128 * SSTR * 2)
#define QHO (0 * TILE_B)
#define QLO (1 * TILE_B)
#define KHO (2 * TILE_B)
#define KLO (3 * TILE_B)
#define VHO (4 * TILE_B)
#define VLO (5 * TILE_B)
#define ATT_SMEM (6 * TILE_B)

__global__ __launch_bounds__(256, 1) void attn_mma(
    const __half* __restrict__ qh_g, const __half* __restrict__ ql_g,
    const __half* __restrict__ kh_g, const __half* __restrict__ kl_g,
    const __half* __restrict__ vh_g, const __half* __restrict__ vl_g,
    __nv_bfloat16* __restrict__ attn_h, __nv_bfloat16* __restrict__ attn_l, int T)
{
    extern __shared__ char sm[];
    const uint32_t smb = smem_to_u32(sm);
    const int tid  = threadIdx.x;
    const int lane = tid & 31;
    const int wid  = tid >> 5;
    const int gid  = lane >> 2;
    const int tq   = lane & 3;

    const int qb   = (gridDim.x - 1) - blockIdx.x;
    const int head = blockIdx.y;
    const int kvh  = head >> 1;
    const int q0   = qb * 128;
    const int wrow = wid * 16;
    const int iters = qb + 1;

    const int arow  = lane & 15;
    const int acol8 = (lane >> 4) << 3;
    const int brow  = ((lane >> 4) << 3) + (lane & 7);
    const int bcol8 = ((lane >> 3) & 1) << 3;

    const size_t kbase = (size_t)kvh * T * HEAD_DIM;
    const size_t vbase = (size_t)kvh * HEAD_DIM * T;

    // ---- Prologue: prefetch K(0), V(0) ----
    for (int i = tid; i < 2048; i += 256) {
        int r = i >> 4, c = (i & 15) << 3;
        uint32_t doff = (uint32_t)(r * SSTR + c) * 2;
        CP_ASYNC16(smb + KHO + doff, kh_g + kbase + (size_t)r * HEAD_DIM + c);
        CP_ASYNC16(smb + KLO + doff, kl_g + kbase + (size_t)r * HEAD_DIM + c);
    }
    CP_COMMIT();
    for (int i = tid; i < 2048; i += 256) {
        int d = i >> 4, c = (i & 15) << 3;
        uint32_t doff = (uint32_t)(d * SSTR + c) * 2;
        CP_ASYNC16(smb + VHO + doff, vh_g + vbase + (size_t)d * T + c);
        CP_ASYNC16(smb + VLO + doff, vl_g + vbase + (size_t)d * T + c);
    }
    CP_COMMIT();

    // ---- Stage Q ----
    for (int i = tid; i < 2048; i += 256) {
        int r = i >> 4, c = (i & 15) << 3;
        uint32_t doff = (uint32_t)(r * SSTR + c) * 2;
        size_t o = (size_t)(q0 + r) * Q_SIZE + head * HEAD_DIM + c;
        *(uint4*)(sm + QHO + doff) = *(const uint4*)&qh_g[o];
        *(uint4*)(sm + QLO + doff) = *(const uint4*)&ql_g[o];
    }
    __syncthreads();

    // ---- Persistent Q fragments ----
    uint32_t qh[8][4], ql[8][4];
    #pragma unroll
    for (int kt = 0; kt < 8; kt++) {
        uint32_t aoff = (uint32_t)((wrow + arow) * SSTR + kt * 16 + acol8) * 2;
        LDSM_X4(qh[kt][0], qh[kt][1], qh[kt][2], qh[kt][3], smb + QHO + aoff);
        LDSM_X4(ql[kt][0], ql[kt][1], ql[kt][2], ql[kt][3], smb + QLO + aoff);
    }

    const int grow0 = q0 + wrow + gid;
    const int grow1 = grow0 + 8;

    float m0 = -1e30f, m1 = -1e30f, l0s = 0.0f, l1s = 0.0f;
    float o[16][4] = {};

    for (int it = 0; it < iters; it++) {
        const int k0 = it * 128;

        CP_WAIT(1);      // K(it) ready
        __syncthreads();

        // ---- S = Q K^T (fp16 3-combo) ----
        float s[16][4];
        #pragma unroll
        for (int nt = 0; nt < 16; nt++)
            #pragma unroll
            for (int c = 0; c < 4; c++) s[nt][c] = 0.0f;

        #pragma unroll
        for (int kt = 0; kt < 8; kt++) {
            #pragma unroll
            for (int p = 0; p < 8; p++) {
                uint32_t boff = (uint32_t)((p * 16 + brow) * SSTR + kt * 16 + bcol8) * 2;
                uint32_t bh0, bh1, bh2, bh3, bl0, bl1, bl2, bl3;
                LDSM_X4(bh0, bh1, bh2, bh3, smb + KHO + boff);
                LDSM_X4(bl0, bl1, bl2, bl3, smb + KLO + boff);
                mma_f16(s[2 * p], qh[kt], bh0, bh1);
                mma_f16(s[2 * p], qh[kt], bl0, bl1);
                mma_f16(s[2 * p], ql[kt], bh0, bh1);
                mma_f16(s[2 * p + 1], qh[kt], bh2, bh3);
                mma_f16(s[2 * p + 1], qh[kt], bl2, bl3);
                mma_f16(s[2 * p + 1], ql[kt], bh2, bh3);
            }
        }
        __syncthreads();

        // ---- Prefetch K(it+1) ----
        if (it + 1 < iters) {
            const size_t ko = kbase + (size_t)(it + 1) * 128 * HEAD_DIM;
            for (int i = tid; i < 2048; i += 256) {
                int r = i >> 4, c = (i & 15) << 3;
                uint32_t doff = (uint32_t)(r * SSTR + c) * 2;
                CP_ASYNC16(smb + KHO + doff, kh_g + ko + (size_t)r * HEAD_DIM + c);
                CP_ASYNC16(smb + KLO + doff, kl_g + ko + (size_t)r * HEAD_DIM + c);
            }
        }
        CP_COMMIT();

        // ---- scale (log2-domain) + mask + online softmax ----
        const bool diag = (it == qb);
        float mx0 = m0, mx1 = m1;
        #pragma unroll
        for (int nt = 0; nt < 16; nt++) {
            int colb = k0 + nt * 8 + tq * 2;
            #pragma unroll
            for (int c = 0; c < 2; c++) {
                float v0 = s[nt][c] * SCALE_L2E;
                float v1 = s[nt][c + 2] * SCALE_L2E;
                if (diag && (colb + c > grow0)) v0 = -1e30f;
                if (diag && (colb + c > grow1)) v1 = -1e30f;
                s[nt][c] = v0; s[nt][c + 2] = v1;
                mx0 = fmaxf(mx0, v0); mx1 = fmaxf(mx1, v1);
            }
        }
        mx0 = fmaxf(mx0, __shfl_xor_sync(0xffffffffu, mx0, 1));
        mx0 = fmaxf(mx0, __shfl_xor_sync(0xffffffffu, mx0, 2));
        mx1 = fmaxf(mx1, __shfl_xor_sync(0xffffffffu, mx1, 1));
        mx1 = fmaxf(mx1, __shfl_xor_sync(0xffffffffu, mx1, 2));

        const float a0 = ex2f(m0 - mx0);
        const float a1 = ex2f(m1 - mx1);
        m0 = mx0; m1 = mx1;

        float sum0 = 0.0f, sum1 = 0.0f;
        #pragma unroll
        for (int nt = 0; nt < 16; nt++) {
            #pragma unroll
            for (int c = 0; c < 2; c++) {
                float p0 = ex2f(s[nt][c] - m0);
                float p1 = ex2f(s[nt][c + 2] - m1);
                s[nt][c] = p0; s[nt][c + 2] = p1;
                sum0 += p0; sum1 += p1;
            }
        }
        sum0 += __shfl_xor_sync(0xffffffffu, sum0, 1);
        sum0 += __shfl_xor_sync(0xffffffffu, sum0, 2);
        sum1 += __shfl_xor_sync(0xffffffffu, sum1, 1);
        sum1 += __shfl_xor_sync(0xffffffffu, sum1, 2);
        l0s = l0s * a0 + sum0;
        l1s = l1s * a1 + sum1;

        #pragma unroll
        for (int nt = 0; nt < 16; nt++) {
            o[nt][0] *= a0; o[nt][1] *= a0;
            o[nt][2] *= a1; o[nt][3] *= a1;
        }

        CP_WAIT(1);      // V(it) ready
        __syncthreads();

        // ---- O += P @ V (P single fp16, V hi/lo: 2 combos) ----
        #pragma unroll
        for (int kt = 0; kt < 8; kt++) {
            uint32_t ph[4];
            ph[0] = cvt_h2(s[2 * kt][0], s[2 * kt][1]);
            ph[1] = cvt_h2(s[2 * kt][2], s[2 * kt][3]);
            ph[2] = cvt_h2(s[2 * kt + 1][0], s[2 * kt + 1][1]);
            ph[3] = cvt_h2(s[2 * kt + 1][2], s[2 * kt + 1][3]);
            #pragma unroll
            for (int p = 0; p < 8; p++) {
                uint32_t boff = (uint32_t)((p * 16 + brow) * SSTR + kt * 16 + bcol8) * 2;
                uint32_t vh0, vh1, vh2, vh3, vl0, vl1, vl2, vl3;
                LDSM_X4(vh0, vh1, vh2, vh3, smb + VHO + boff);
                LDSM_X4(vl0, vl1, vl2, vl3, smb + VLO + boff);
                mma_f16(o[2 * p], ph, vh0, vh1);
                mma_f16(o[2 * p], ph, vl0, vl1);
                mma_f16(o[2 * p + 1], ph, vh2, vh3);
                mma_f16(o[2 * p + 1], ph, vl2, vl3);
            }
        }
        __syncthreads();

        // ---- Prefetch V(it+1) ----
        if (it + 1 < iters) {
            const int nk0 = (it + 1) * 128;
            for (int i = tid; i < 2048; i += 256) {
                int d = i >> 4, c = (i & 15) << 3;
                uint32_t doff = (uint32_t)(d * SSTR + c) * 2;
                CP_ASYNC16(smb + VHO + doff, vh_g + vbase + (size_t)d * T + nk0 + c);
                CP_ASYNC16(smb + VLO + doff, vl_g + vbase + (size_t)d * T + nk0 + c);
            }
        }
        CP_COMMIT();
    }

    // ---- Epilogue: normalize, split bf16 hi/lo for O-proj ----
    const float inv0 = 1.0f / l0s;
    const float inv1 = 1.0f / l1s;
    #pragma unroll
    for (int nt = 0; nt < 16; nt++) {
        int dcol = head * HEAD_DIM + nt * 8 + tq * 2;
        float w00 = o[nt][0] * inv0, w01 = o[nt][1] * inv0;
        float w10 = o[nt][2] * inv1, w11 = o[nt][3] * inv1;
        __nv_bfloat16 h0, l0, h1, l1;
        split_bf(w00, h0, l0); split_bf(w01, h1, l1);
        *(uint32_t*)&attn_h[(size_t)grow0 * Q_SIZE + dcol] = pack_bf2(h0, h1);
        *(uint32_t*)&attn_l[(size_t)grow0 * Q_SIZE + dcol] = pack_bf2(l0, l1);
        split_bf(w10, h0, l0); split_bf(w11, h1, l1);
        *(uint32_t*)&attn_h[(size_t)grow1 * Q_SIZE + dcol] = pack_bf2(h0, h1);
        *(uint32_t*)&attn_l[(size_t)grow1 * Q_SIZE + dcol] = pack_bf2(l0, l1);
    }
}

// ---------------------------------------------------------------------------
// Launch
// ---------------------------------------------------------------------------
extern "C" void kernel_launch(void* const* d_in, const int* in_sizes, int n_in,
                              void* d_out, int out_size)
{
    const float* hidden = (const float*)d_in[0];
    const float* qkv_w  = (const float*)d_in[1];
    const float* q_nw   = (const float*)d_in[2];
    const float* k_nw   = (const float*)d_in[3];
    const float* o_w    = (const float*)d_in[4];
    const int*   pos    = (const int*)d_in[5];
    float* out = (float*)d_out;

    const int T = in_sizes[0] / HIDDEN;

    float* qkv;  cudaGetSymbolAddress((void**)&qkv,  g_qkv);
    __nv_bfloat16 *hid_h, *hid_l, *w1_h, *w1_l, *w2_h, *w2_l, *at_h, *at_l;
    __half *q_h, *q_l, *k_h, *k_l, *v_h, *v_l;
    cudaGetSymbolAddress((void**)&hid_h, g_hid_h);
    cudaGetSymbolAddress((void**)&hid_l, g_hid_l);
    cudaGetSymbolAddress((void**)&w1_h,  g_w1_h);
    cudaGetSymbolAddress((void**)&w1_l,  g_w1_l);
    cudaGetSymbolAddress((void**)&w2_h,  g_w2_h);
    cudaGetSymbolAddress((void**)&w2_l,  g_w2_l);
    cudaGetSymbolAddress((void**)&at_h,  g_at_h);
    cudaGetSymbolAddress((void**)&at_l,  g_at_l);
    cudaGetSymbolAddress((void**)&q_h,   g_q_h);
    cudaGetSymbolAddress((void**)&q_l,   g_q_l);
    cudaGetSymbolAddress((void**)&k_h,   g_k_h);
    cudaGetSymbolAddress((void**)&k_l,   g_k_l);
    cudaGetSymbolAddress((void**)&v_h,   g_v_h);
    cudaGetSymbolAddress((void**)&v_l,   g_v_l);

    cudaFuncSetAttribute(attn_mma, cudaFuncAttributeMaxDynamicSharedMemorySize,
                         ATT_SMEM);
    cudaFuncSetAttribute(gemm_bf16s, cudaFuncAttributeMaxDynamicSharedMemorySize,
                         GEMM_SMEM);

    // 0) Split inputs (bf16, for GEMMs)
    {
        int n4 = T * HIDDEN / 4;
        split_kernel<<<(n4 + 255) / 256, 256>>>(hidden, hid_h, hid_l, n4);
        n4 = QKV_COLS * HIDDEN / 4;
        split_kernel<<<(n4 + 255) / 256, 256>>>(qkv_w, w1_h, w1_l, n4);
        n4 = HIDDEN * Q_SIZE / 4;
        split_kernel<<<(n4 + 255) / 256, 256>>>(o_w, w2_h, w2_l, n4);
    }
    // 1) QKV projection
    {
        dim3 grid(QKV_COLS / XBN, T / XBM);
        gemm_bf16s<<<grid, 256, GEMM_SMEM>>>(hid_h, hid_l, w1_h, w1_l, qkv,
                                             T, QKV_COLS, HIDDEN);
    }
    // 2) Fused RMSNorm + RoPE + fp16 split (Q, K); transpose+split V
    {
        int warps = T * 24;
        int blocks = (warps + 7) / 8;
        normrope_split_kernel<<<blocks, 256>>>(qkv, q_nw, k_nw, pos,
                                               q_h, q_l, k_h, k_l, T);
        dim3 vg(T / 32, HEAD_DIM / 32, NUM_KV);
        vtrans_kernel<<<vg, dim3(32, 8)>>>(qkv, v_h, v_l, T);
    }
    // 3) Attention (fp16 HMMA flash)
    {
        dim3 grid(T / 128, NUM_HEADS);
        attn_mma<<<grid, 256, ATT_SMEM>>>(q_h, q_l, k_h, k_l, v_h, v_l,
                                          at_h, at_l, T);
    }
    // 4) Output projection
    {
        dim3 grid(HIDDEN / XBN, T / XBM);
        gemm_bf16s<<<grid, 256, GEMM_SMEM>>>(at_h, at_l, w2_h, w2_l, out,
                                             T, HIDDEN, HIDDEN);
    }
}

// round 8
// speedup vs baseline: 4.4455x; 1.2050x over previous
#include <cuda_runtime.h>
#include <cuda_bf16.h>
#include <cuda_fp16.h>
#include <math.h>
#include <float.h>
#include <cstdint>

// Problem constants
#define HIDDEN    2048
#define NUM_HEADS 16
#define NUM_KV    8
#define HEAD_DIM  128
#define Q_SIZE    (NUM_HEADS * HEAD_DIM)        // 2048
#define KV_SIZE   (NUM_KV * HEAD_DIM)           // 1024
#define QKV_COLS  (Q_SIZE + 2 * KV_SIZE)        // 4096
#define SCALE     0.08838834764831845f          // 128^-0.5
#define SCALE_L2E 0.12751985675839602f          // SCALE * log2(e)
#define RMS_EPS   1e-6f

#define MAX_T 4096

// Scratch (static device globals)
__device__ float g_qkv[(size_t)MAX_T * QKV_COLS];
__device__ __half g_hid[(size_t)MAX_T * HIDDEN];            // single fp16
__device__ __half g_w1_h[(size_t)QKV_COLS * HIDDEN];
__device__ __half g_w1_l[(size_t)QKV_COLS * HIDDEN];
__device__ __half g_w2_h[(size_t)HIDDEN * Q_SIZE];
__device__ __half g_w2_l[(size_t)HIDDEN * Q_SIZE];
__device__ __half g_at[(size_t)MAX_T * Q_SIZE];             // single fp16
__device__ __half g_q_h[(size_t)MAX_T * Q_SIZE];
__device__ __half g_q_l[(size_t)MAX_T * Q_SIZE];
__device__ __half g_k_h[(size_t)NUM_KV * MAX_T * HEAD_DIM];
__device__ __half g_k_l[(size_t)NUM_KV * MAX_T * HEAD_DIM];
__device__ __half g_v[(size_t)NUM_KV * HEAD_DIM * MAX_T];   // [kvh][d][t], single

// ===========================================================================
// Helpers
// ===========================================================================
__device__ __forceinline__ uint32_t smem_to_u32(const void* p) {
    uint32_t a;
    asm("{ .reg .u64 t; cvta.to.shared.u64 t, %1; cvt.u32.u64 %0, t; }"
        : "=r"(a) : "l"(p));
    return a;
}
__device__ __forceinline__ void split_h16(float x, __half& h, __half& l) {
    h = __float2half_rn(x);
    l = __float2half_rn(x - __half2float(h));
}
__device__ __forceinline__ float ex2f(float x) {
    float r;
    asm("ex2.approx.f32 %0, %1;" : "=f"(r) : "f"(x));
    return r;
}
// pack two fp32 -> f16x2 (lo = a, hi = b)
__device__ __forceinline__ uint32_t cvt_h2(float a, float b) {
    uint32_t r;
    asm("cvt.rn.f16x2.f32 %0, %1, %2;" : "=r"(r) : "f"(b), "f"(a));
    return r;
}
__device__ __forceinline__ uint32_t pack_h2(__half a, __half b) {
    __half2 t = __halves2half2(a, b);
    return *reinterpret_cast<uint32_t*>(&t);
}

// warp mma fp16: D(16x8,f32) += A(16x16) * B(16x8)
__device__ __forceinline__ void mma_f16(float* d, const uint32_t* a,
                                        uint32_t b0, uint32_t b1) {
    asm volatile(
        "mma.sync.aligned.m16n8k16.row.col.f32.f16.f16.f32 "
        "{%0,%1,%2,%3}, {%4,%5,%6,%7}, {%8,%9}, {%0,%1,%2,%3};"
        : "+f"(d[0]), "+f"(d[1]), "+f"(d[2]), "+f"(d[3])
        : "r"(a[0]), "r"(a[1]), "r"(a[2]), "r"(a[3]), "r"(b0), "r"(b1));
}

#define LDSM_X4(r0, r1, r2, r3, addr) \
    asm volatile("ldmatrix.sync.aligned.m8n8.x4.shared.b16 {%0,%1,%2,%3}, [%4];" \
        : "=r"(r0), "=r"(r1), "=r"(r2), "=r"(r3) : "r"(addr))

#define CP_ASYNC16(dst, src) \
    asm volatile("cp.async.cg.shared.global [%0], [%1], 16;" \
        :: "r"(dst), "l"(src))
#define CP_COMMIT() asm volatile("cp.async.commit_group;")
#define CP_WAIT(n)  asm volatile("cp.async.wait_group %0;" :: "n"(n))

// ---------------------------------------------------------------------------
// fp32 -> fp16 single convert (hidden)
// ---------------------------------------------------------------------------
__global__ __launch_bounds__(256) void cvt16_kernel(
    const float* __restrict__ src, __half* __restrict__ dst, int n4)
{
    int i = blockIdx.x * blockDim.x + threadIdx.x;
    if (i >= n4) return;
    float4 v = ((const float4*)src)[i];
    uint2 u;
    u.x = cvt_h2(v.x, v.y);
    u.y = cvt_h2(v.z, v.w);
    ((uint2*)dst)[i] = u;
}

// fp32 -> fp16 hi/lo split (weights)
__global__ __launch_bounds__(256) void split16_kernel(
    const float* __restrict__ src, __half* __restrict__ h,
    __half* __restrict__ l, int n4)
{
    int i = blockIdx.x * blockDim.x + threadIdx.x;
    if (i >= n4) return;
    float4 v = ((const float4*)src)[i];
    __half h0, h1, h2, h3, l0, l1, l2, l3;
    split_h16(v.x, h0, l0); split_h16(v.y, h1, l1);
    split_h16(v.z, h2, l2); split_h16(v.w, h3, l3);
    uint2 uh; uh.x = pack_h2(h0, h1); uh.y = pack_h2(h2, h3);
    uint2 ul; ul.x = pack_h2(l0, l1); ul.y = pack_h2(l2, l3);
    ((uint2*)h)[i] = uh;
    ((uint2*)l)[i] = ul;
}

// ---------------------------------------------------------------------------
// Fused RMSNorm + RoPE + fp16 hi/lo split for Q and K.
// ---------------------------------------------------------------------------
__global__ __launch_bounds__(256) void normrope_split_kernel(
    const float* __restrict__ qkv,
    const float* __restrict__ qw, const float* __restrict__ kw,
    const int* __restrict__ positions,
    __half* __restrict__ qh_g, __half* __restrict__ ql_g,
    __half* __restrict__ kh_g, __half* __restrict__ kl_g, int T)
{
    const int warp = (blockIdx.x * blockDim.x + threadIdx.x) >> 5;
    const int lane = threadIdx.x & 31;
    if (warp >= T * 24) return;
    const int t = warp / 24;
    const int h = warp % 24;

    const float* x = qkv + (size_t)t * QKV_COLS + h * HEAD_DIM;
    const float* nw = (h < 16) ? qw : kw;

    float v0 = x[lane], v1 = x[lane + 32], v2 = x[lane + 64], v3 = x[lane + 96];
    float ss = v0 * v0 + v1 * v1 + v2 * v2 + v3 * v3;
    #pragma unroll
    for (int o = 16; o; o >>= 1) ss += __shfl_xor_sync(0xffffffffu, ss, o);
    const float rn = rsqrtf(ss * (1.0f / HEAD_DIM) + RMS_EPS);

    float n0 = v0 * rn * nw[lane];
    float n1 = v1 * rn * nw[lane + 32];
    float n2 = v2 * rn * nw[lane + 64];
    float n3 = v3 * rn * nw[lane + 96];

    const double pos = (double)positions[t];
    const double LOG_THETA = 13.815510557964274;
    double f0 = exp(-((double)(2 * lane) / 128.0) * LOG_THETA);
    double f1 = exp(-((double)(2 * (lane + 32)) / 128.0) * LOG_THETA);
    double s0d, c0d, s1d, c1d;
    sincos(pos * f0, &s0d, &c0d);
    sincos(pos * f1, &s1d, &c1d);
    float c0 = (float)c0d, s0 = (float)s0d, c1 = (float)c1d, s1 = (float)s1d;

    float r0 = n0 * c0 - n2 * s0;
    float r2 = n2 * c0 + n0 * s0;
    float r1 = n1 * c1 - n3 * s1;
    float r3 = n3 * c1 + n1 * s1;

    __half h0, l0, h1, l1, h2, l2, h3, l3;
    split_h16(r0, h0, l0); split_h16(r1, h1, l1);
    split_h16(r2, h2, l2); split_h16(r3, h3, l3);

    __half *dh, *dl;
    size_t base;
    if (h < 16) {
        base = (size_t)t * Q_SIZE + h * HEAD_DIM;
        dh = qh_g; dl = ql_g;
    } else {
        base = (size_t)(h - 16) * T * HEAD_DIM + (size_t)t * HEAD_DIM;
        dh = kh_g; dl = kl_g;
    }
    dh[base + lane] = h0;      dl[base + lane] = l0;
    dh[base + lane + 32] = h1; dl[base + lane + 32] = l1;
    dh[base + lane + 64] = h2; dl[base + lane + 64] = l2;
    dh[base + lane + 96] = h3; dl[base + lane + 96] = l3;
}

// Transpose V -> [kvh][d][t], single fp16
__global__ void vtrans_kernel(
    const float* __restrict__ qkv, __half* __restrict__ vh, int T)
{
    __shared__ float tile[32][33];
    const int kvh = blockIdx.z;
    const int d0 = blockIdx.y * 32;
    const int t0 = blockIdx.x * 32;
    for (int j = threadIdx.y; j < 32; j += 8) {
        tile[j][threadIdx.x] = qkv[(size_t)(t0 + j) * QKV_COLS + Q_SIZE + KV_SIZE
                                   + kvh * HEAD_DIM + d0 + threadIdx.x];
    }
    __syncthreads();
    for (int j = threadIdx.y; j < 32; j += 8) {
        float v = tile[threadIdx.x][j];
        size_t o = (size_t)kvh * HEAD_DIM * T + (size_t)(d0 + j) * T + t0 + threadIdx.x;
        vh[o] = __float2half_rn(v);
    }
}

// ---------------------------------------------------------------------------
// fp16 HMMA GEMM, 2 combos: C[M,N] = A*Bh^T + A*Bl^T  (A single fp16)
// BM=BN=128, BK=32, 256 threads, cp.async double-buffered, 2 CTAs/SM.
// ---------------------------------------------------------------------------
#define XBM 128
#define XBN 128
#define XBK 32
#define XSTR 40
#define STAGE_E (XBM * XSTR)
#define GEMM_SMEM (6 * STAGE_E * 2)   // 61440 bytes (2 stages x 3 buffers)

__global__ __launch_bounds__(256, 2) void gemm_f16s(
    const __half* __restrict__ A,
    const __half* __restrict__ Bh, const __half* __restrict__ Bl,
    float* __restrict__ C, int M, int N, int K)
{
    extern __shared__ __half smg[];
    const uint32_t smb = smem_to_u32(smg);

    const int tid  = threadIdx.x;
    const int lane = tid & 31;
    const int wid  = tid >> 5;
    const int gid  = lane >> 2;
    const int tq   = lane & 3;
    const int wm   = (wid & 3) * 32;
    const int wn   = (wid >> 2) * 64;

    const int arow  = lane & 15;
    const int acol8 = (lane >> 4) << 3;
    const int brow  = ((lane >> 4) << 3) + (lane & 7);
    const int bcol8 = ((lane >> 3) & 1) << 3;

    const int bm = blockIdx.y * XBM;
    const int bn = blockIdx.x * XBN;

    #define G_ISSUE(stage, k0) do { \
        uint32_t sb0 = smb + (uint32_t)(stage) * 3 * STAGE_E * 2; \
        _Pragma("unroll") \
        for (int j = 0; j < 2; j++) { \
            int id = tid + j * 256; \
            int r = id >> 2, c = (id & 3) * 8; \
            size_t aoff = (size_t)(bm + r) * K + (k0) + c; \
            size_t boff = (size_t)(bn + r) * K + (k0) + c; \
            uint32_t doff = (uint32_t)(r * XSTR + c) * 2; \
            CP_ASYNC16(sb0 + doff, A + aoff); \
            CP_ASYNC16(sb0 + STAGE_E * 2 + doff, Bh + boff); \
            CP_ASYNC16(sb0 + 2 * STAGE_E * 2 + doff, Bl + boff); \
        } \
    } while (0)

    float acc[2][8][4] = {};

    G_ISSUE(0, 0);
    CP_COMMIT();

    int stage = 0;
    for (int k0 = 0; k0 < K; k0 += XBK, stage ^= 1) {
        if (k0 + XBK < K) {
            G_ISSUE(stage ^ 1, k0 + XBK);
            CP_COMMIT();
            CP_WAIT(1);
        } else {
            CP_WAIT(0);
        }
        __syncthreads();

        const uint32_t sA  = smb + (uint32_t)stage * 3 * STAGE_E * 2;
        const uint32_t sBh = sA + STAGE_E * 2;
        const uint32_t sBl = sBh + STAGE_E * 2;

        #pragma unroll
        for (int kk = 0; kk < XBK; kk += 16) {
            uint32_t a[2][4];
            #pragma unroll
            for (int mt = 0; mt < 2; mt++) {
                uint32_t aoff = (uint32_t)((wm + mt * 16 + arow) * XSTR + kk + acol8) * 2;
                LDSM_X4(a[mt][0], a[mt][1], a[mt][2], a[mt][3], sA + aoff);
            }
            #pragma unroll
            for (int p = 0; p < 4; p++) {
                uint32_t boff = (uint32_t)((wn + p * 16 + brow) * XSTR + kk + bcol8) * 2;
                uint32_t bh0, bh1, bh2, bh3, bl0, bl1, bl2, bl3;
                LDSM_X4(bh0, bh1, bh2, bh3, sBh + boff);
                LDSM_X4(bl0, bl1, bl2, bl3, sBl + boff);
                #pragma unroll
                for (int mt = 0; mt < 2; mt++) {
                    mma_f16(acc[mt][2 * p], a[mt], bh0, bh1);
                    mma_f16(acc[mt][2 * p], a[mt], bl0, bl1);
                    mma_f16(acc[mt][2 * p + 1], a[mt], bh2, bh3);
                    mma_f16(acc[mt][2 * p + 1], a[mt], bl2, bl3);
                }
            }
        }
        __syncthreads();
    }

    #pragma unroll
    for (int mt = 0; mt < 2; mt++) {
        int row = bm + wm + mt * 16 + gid;
        #pragma unroll
        for (int nt = 0; nt < 8; nt++) {
            int col = bn + wn + nt * 8 + tq * 2;
            *(float2*)&C[(size_t)row * N + col] =
                make_float2(acc[mt][nt][0], acc[mt][nt][1]);
            *(float2*)&C[(size_t)(row + 8) * N + col] =
                make_float2(acc[mt][nt][2], acc[mt][nt][3]);
        }
    }
}

// ---------------------------------------------------------------------------
// fp16 HMMA flash attention. QK: 3 combos. PV: 1 combo (P fp16 x V fp16).
// ---------------------------------------------------------------------------
#define SSTR 136
#define TILE_B (128 * SSTR * 2)
#define QHO (0 * TILE_B)
#define QLO (1 * TILE_B)
#define KHO (2 * TILE_B)
#define KLO (3 * TILE_B)
#define VHO (4 * TILE_B)
#define ATT_SMEM (5 * TILE_B)        // 174080 bytes

__global__ __launch_bounds__(256, 1) void attn_mma(
    const __half* __restrict__ qh_g, const __half* __restrict__ ql_g,
    const __half* __restrict__ kh_g, const __half* __restrict__ kl_g,
    const __half* __restrict__ v_g,
    __half* __restrict__ attn_out, int T)
{
    extern __shared__ char sm[];
    const uint32_t smb = smem_to_u32(sm);
    const int tid  = threadIdx.x;
    const int lane = tid & 31;
    const int wid  = tid >> 5;
    const int gid  = lane >> 2;
    const int tq   = lane & 3;

    const int qb   = (gridDim.x - 1) - blockIdx.x;
    const int head = blockIdx.y;
    const int kvh  = head >> 1;
    const int q0   = qb * 128;
    const int wrow = wid * 16;
    const int iters = qb + 1;

    const int arow  = lane & 15;
    const int acol8 = (lane >> 4) << 3;
    const int brow  = ((lane >> 4) << 3) + (lane & 7);
    const int bcol8 = ((lane >> 3) & 1) << 3;

    const size_t kbase = (size_t)kvh * T * HEAD_DIM;
    const size_t vbase = (size_t)kvh * HEAD_DIM * T;

    // ---- Prologue: prefetch K(0), V(0) ----
    for (int i = tid; i < 2048; i += 256) {
        int r = i >> 4, c = (i & 15) << 3;
        uint32_t doff = (uint32_t)(r * SSTR + c) * 2;
        CP_ASYNC16(smb + KHO + doff, kh_g + kbase + (size_t)r * HEAD_DIM + c);
        CP_ASYNC16(smb + KLO + doff, kl_g + kbase + (size_t)r * HEAD_DIM + c);
    }
    CP_COMMIT();
    for (int i = tid; i < 2048; i += 256) {
        int d = i >> 4, c = (i & 15) << 3;
        uint32_t doff = (uint32_t)(d * SSTR + c) * 2;
        CP_ASYNC16(smb + VHO + doff, v_g + vbase + (size_t)d * T + c);
    }
    CP_COMMIT();

    // ---- Stage Q ----
    for (int i = tid; i < 2048; i += 256) {
        int r = i >> 4, c = (i & 15) << 3;
        uint32_t doff = (uint32_t)(r * SSTR + c) * 2;
        size_t o = (size_t)(q0 + r) * Q_SIZE + head * HEAD_DIM + c;
        *(uint4*)(sm + QHO + doff) = *(const uint4*)&qh_g[o];
        *(uint4*)(sm + QLO + doff) = *(const uint4*)&ql_g[o];
    }
    __syncthreads();

    // ---- Persistent Q fragments ----
    uint32_t qh[8][4], ql[8][4];
    #pragma unroll
    for (int kt = 0; kt < 8; kt++) {
        uint32_t aoff = (uint32_t)((wrow + arow) * SSTR + kt * 16 + acol8) * 2;
        LDSM_X4(qh[kt][0], qh[kt][1], qh[kt][2], qh[kt][3], smb + QHO + aoff);
        LDSM_X4(ql[kt][0], ql[kt][1], ql[kt][2], ql[kt][3], smb + QLO + aoff);
    }

    const int grow0 = q0 + wrow + gid;
    const int grow1 = grow0 + 8;

    float m0 = -1e30f, m1 = -1e30f, l0s = 0.0f, l1s = 0.0f;
    float o[16][4] = {};

    for (int it = 0; it < iters; it++) {
        const int k0 = it * 128;

        CP_WAIT(1);      // K(it) ready
        __syncthreads();

        // ---- S = Q K^T (3 combos) ----
        float s[16][4];
        #pragma unroll
        for (int nt = 0; nt < 16; nt++)
            #pragma unroll
            for (int c = 0; c < 4; c++) s[nt][c] = 0.0f;

        #pragma unroll
        for (int kt = 0; kt < 8; kt++) {
            #pragma unroll
            for (int p = 0; p < 8; p++) {
                uint32_t boff = (uint32_t)((p * 16 + brow) * SSTR + kt * 16 + bcol8) * 2;
                uint32_t bh0, bh1, bh2, bh3, bl0, bl1, bl2, bl3;
                LDSM_X4(bh0, bh1, bh2, bh3, smb + KHO + boff);
                LDSM_X4(bl0, bl1, bl2, bl3, smb + KLO + boff);
                mma_f16(s[2 * p], qh[kt], bh0, bh1);
                mma_f16(s[2 * p], qh[kt], bl0, bl1);
                mma_f16(s[2 * p], ql[kt], bh0, bh1);
                mma_f16(s[2 * p + 1], qh[kt], bh2, bh3);
                mma_f16(s[2 * p + 1], qh[kt], bl2, bl3);
                mma_f16(s[2 * p + 1], ql[kt], bh2, bh3);
            }
        }
        __syncthreads();

        // ---- Prefetch K(it+1) ----
        if (it + 1 < iters) {
            const size_t ko = kbase + (size_t)(it + 1) * 128 * HEAD_DIM;
            for (int i = tid; i < 2048; i += 256) {
                int r = i >> 4, c = (i & 15) << 3;
                uint32_t doff = (uint32_t)(r * SSTR + c) * 2;
                CP_ASYNC16(smb + KHO + doff, kh_g + ko + (size_t)r * HEAD_DIM + c);
                CP_ASYNC16(smb + KLO + doff, kl_g + ko + (size_t)r * HEAD_DIM + c);
            }
        }
        CP_COMMIT();

        // ---- scale (log2-domain) + mask + online softmax ----
        const bool diag = (it == qb);
        float mx0 = m0, mx1 = m1;
        #pragma unroll
        for (int nt = 0; nt < 16; nt++) {
            int colb = k0 + nt * 8 + tq * 2;
            #pragma unroll
            for (int c = 0; c < 2; c++) {
                float v0 = s[nt][c] * SCALE_L2E;
                float v1 = s[nt][c + 2] * SCALE_L2E;
                if (diag && (colb + c > grow0)) v0 = -1e30f;
                if (diag && (colb + c > grow1)) v1 = -1e30f;
                s[nt][c] = v0; s[nt][c + 2] = v1;
                mx0 = fmaxf(mx0, v0); mx1 = fmaxf(mx1, v1);
            }
        }
        mx0 = fmaxf(mx0, __shfl_xor_sync(0xffffffffu, mx0, 1));
        mx0 = fmaxf(mx0, __shfl_xor_sync(0xffffffffu, mx0, 2));
        mx1 = fmaxf(mx1, __shfl_xor_sync(0xffffffffu, mx1, 1));
        mx1 = fmaxf(mx1, __shfl_xor_sync(0xffffffffu, mx1, 2));

        const float a0 = ex2f(m0 - mx0);
        const float a1 = ex2f(m1 - mx1);
        m0 = mx0; m1 = mx1;

        float sum0 = 0.0f, sum1 = 0.0f;
        #pragma unroll
        for (int nt = 0; nt < 16; nt++) {
            #pragma unroll
            for (int c = 0; c < 2; c++) {
                float p0 = ex2f(s[nt][c] - m0);
                float p1 = ex2f(s[nt][c + 2] - m1);
                s[nt][c] = p0; s[nt][c + 2] = p1;
                sum0 += p0; sum1 += p1;
            }
        }
        sum0 += __shfl_xor_sync(0xffffffffu, sum0, 1);
        sum0 += __shfl_xor_sync(0xffffffffu, sum0, 2);
        sum1 += __shfl_xor_sync(0xffffffffu, sum1, 1);
        sum1 += __shfl_xor_sync(0xffffffffu, sum1, 2);
        l0s = l0s * a0 + sum0;
        l1s = l1s * a1 + sum1;

        #pragma unroll
        for (int nt = 0; nt < 16; nt++) {
            o[nt][0] *= a0; o[nt][1] *= a0;
            o[nt][2] *= a1; o[nt][3] *= a1;
        }

        CP_WAIT(1);      // V(it) ready
        __syncthreads();

        // ---- O += P @ V (1 combo) ----
        #pragma unroll
        for (int kt = 0; kt < 8; kt++) {
            uint32_t ph[4];
            ph[0] = cvt_h2(s[2 * kt][0], s[2 * kt][1]);
            ph[1] = cvt_h2(s[2 * kt][2], s[2 * kt][3]);
            ph[2] = cvt_h2(s[2 * kt + 1][0], s[2 * kt + 1][1]);
            ph[3] = cvt_h2(s[2 * kt + 1][2], s[2 * kt + 1][3]);
            #pragma unroll
            for (int p = 0; p < 8; p++) {
                uint32_t boff = (uint32_t)((p * 16 + brow) * SSTR + kt * 16 + bcol8) * 2;
                uint32_t vh0, vh1, vh2, vh3;
                LDSM_X4(vh0, vh1, vh2, vh3, smb + VHO + boff);
                mma_f16(o[2 * p], ph, vh0, vh1);
                mma_f16(o[2 * p + 1], ph, vh2, vh3);
            }
        }
        __syncthreads();

        // ---- Prefetch V(it+1) ----
        if (it + 1 < iters) {
            const int nk0 = (it + 1) * 128;
            for (int i = tid; i < 2048; i += 256) {
                int d = i >> 4, c = (i & 15) << 3;
                uint32_t doff = (uint32_t)(d * SSTR + c) * 2;
                CP_ASYNC16(smb + VHO + doff, v_g + vbase + (size_t)d * T + nk0 + c);
            }
        }
        CP_COMMIT();
    }

    // ---- Epilogue: normalize, store single fp16 ----
    const float inv0 = 1.0f / l0s;
    const float inv1 = 1.0f / l1s;
    #pragma unroll
    for (int nt = 0; nt < 16; nt++) {
        int dcol = head * HEAD_DIM + nt * 8 + tq * 2;
        *(uint32_t*)&attn_out[(size_t)grow0 * Q_SIZE + dcol] =
            cvt_h2(o[nt][0] * inv0, o[nt][1] * inv0);
        *(uint32_t*)&attn_out[(size_t)grow1 * Q_SIZE + dcol] =
            cvt_h2(o[nt][2] * inv1, o[nt][3] * inv1);
    }
}

// ---------------------------------------------------------------------------
// Launch
// ---------------------------------------------------------------------------
extern "C" void kernel_launch(void* const* d_in, const int* in_sizes, int n_in,
                              void* d_out, int out_size)
{
    const float* hidden = (const float*)d_in[0];
    const float* qkv_w  = (const float*)d_in[1];
    const float* q_nw   = (const float*)d_in[2];
    const float* k_nw   = (const float*)d_in[3];
    const float* o_w    = (const float*)d_in[4];
    const int*   pos    = (const int*)d_in[5];
    float* out = (float*)d_out;

    const int T = in_sizes[0] / HIDDEN;

    float* qkv;  cudaGetSymbolAddress((void**)&qkv,  g_qkv);
    __half *hid, *w1_h, *w1_l, *w2_h, *w2_l, *at;
    __half *q_h, *q_l, *k_h, *k_l, *v;
    cudaGetSymbolAddress((void**)&hid,  g_hid);
    cudaGetSymbolAddress((void**)&w1_h, g_w1_h);
    cudaGetSymbolAddress((void**)&w1_l, g_w1_l);
    cudaGetSymbolAddress((void**)&w2_h, g_w2_h);
    cudaGetSymbolAddress((void**)&w2_l, g_w2_l);
    cudaGetSymbolAddress((void**)&at,   g_at);
    cudaGetSymbolAddress((void**)&q_h,  g_q_h);
    cudaGetSymbolAddress((void**)&q_l,  g_q_l);
    cudaGetSymbolAddress((void**)&k_h,  g_k_h);
    cudaGetSymbolAddress((void**)&k_l,  g_k_l);
    cudaGetSymbolAddress((void**)&v,    g_v);

    cudaFuncSetAttribute(attn_mma, cudaFuncAttributeMaxDynamicSharedMemorySize,
                         ATT_SMEM);
    cudaFuncSetAttribute(gemm_f16s, cudaFuncAttributeMaxDynamicSharedMemorySize,
                         GEMM_SMEM);

    // 0) Convert/split inputs
    {
        int n4 = T * HIDDEN / 4;
        cvt16_kernel<<<(n4 + 255) / 256, 256>>>(hidden, hid, n4);
        n4 = QKV_COLS * HIDDEN / 4;
        split16_kernel<<<(n4 + 255) / 256, 256>>>(qkv_w, w1_h, w1_l, n4);
        n4 = HIDDEN * Q_SIZE / 4;
        split16_kernel<<<(n4 + 255) / 256, 256>>>(o_w, w2_h, w2_l, n4);
    }
    // 1) QKV projection
    {
        dim3 grid(QKV_COLS / XBN, T / XBM);
        gemm_f16s<<<grid, 256, GEMM_SMEM>>>(hid, w1_h, w1_l, qkv,
                                            T, QKV_COLS, HIDDEN);
    }
    // 2) Fused RMSNorm + RoPE + split (Q, K); transpose V
    {
        int warps = T * 24;
        int blocks = (warps + 7) / 8;
        normrope_split_kernel<<<blocks, 256>>>(qkv, q_nw, k_nw, pos,
                                               q_h, q_l, k_h, k_l, T);
        dim3 vg(T / 32, HEAD_DIM / 32, NUM_KV);
        vtrans_kernel<<<vg, dim3(32, 8)>>>(qkv, v, T);
    }
    // 3) Attention
    {
        dim3 grid(T / 128, NUM_HEADS);
        attn_mma<<<grid, 256, ATT_SMEM>>>(q_h, q_l, k_h, k_l, v, at, T);
    }
    // 4) Output projection
    {
        dim3 grid(HIDDEN / XBN, T / XBM);
        gemm_f16s<<<grid, 256, GEMM_SMEM>>>(at, w2_h, w2_l, out,
                                            T, HIDDEN, HIDDEN);
    }
}

// round 9
// speedup vs baseline: 4.4789x; 1.0075x over previous
#include <cuda_runtime.h>
#include <cuda_bf16.h>
#include <cuda_fp16.h>
#include <math.h>
#include <float.h>
#include <cstdint>

// Problem constants
#define HIDDEN    2048
#define NUM_HEADS 16
#define NUM_KV    8
#define HEAD_DIM  128
#define Q_SIZE    (NUM_HEADS * HEAD_DIM)        // 2048
#define KV_SIZE   (NUM_KV * HEAD_DIM)           // 1024
#define QKV_COLS  (Q_SIZE + 2 * KV_SIZE)        // 4096
#define SCALE     0.08838834764831845f          // 128^-0.5
#define SCALE_L2E 0.12751985675839602f          // SCALE * log2(e)
#define RMS_EPS   1e-6f

#define MAX_T 4096

// Scratch (static device globals)
__device__ float g_qkv[(size_t)MAX_T * QKV_COLS];
__device__ __half g_hid[(size_t)MAX_T * HIDDEN];
__device__ __half g_w1_h[(size_t)QKV_COLS * HIDDEN];
__device__ __half g_w1_l[(size_t)QKV_COLS * HIDDEN];
__device__ __half g_w2_h[(size_t)HIDDEN * Q_SIZE];
__device__ __half g_w2_l[(size_t)HIDDEN * Q_SIZE];
__device__ __half g_at[(size_t)MAX_T * Q_SIZE];
__device__ __half g_q_h[(size_t)MAX_T * Q_SIZE];
__device__ __half g_q_l[(size_t)MAX_T * Q_SIZE];
__device__ __half g_k_h[(size_t)NUM_KV * MAX_T * HEAD_DIM];
__device__ __half g_k_l[(size_t)NUM_KV * MAX_T * HEAD_DIM];
__device__ __half g_v[(size_t)NUM_KV * HEAD_DIM * MAX_T];   // [kvh][d][t]

// ===========================================================================
// Helpers
// ===========================================================================
__device__ __forceinline__ uint32_t smem_to_u32(const void* p) {
    uint32_t a;
    asm("{ .reg .u64 t; cvta.to.shared.u64 t, %1; cvt.u32.u64 %0, t; }"
        : "=r"(a) : "l"(p));
    return a;
}
__device__ __forceinline__ void split_h16(float x, __half& h, __half& l) {
    h = __float2half_rn(x);
    l = __float2half_rn(x - __half2float(h));
}
__device__ __forceinline__ float ex2f(float x) {
    float r;
    asm("ex2.approx.f32 %0, %1;" : "=f"(r) : "f"(x));
    return r;
}
__device__ __forceinline__ uint32_t cvt_h2(float a, float b) {
    uint32_t r;
    asm("cvt.rn.f16x2.f32 %0, %1, %2;" : "=r"(r) : "f"(b), "f"(a));
    return r;
}
__device__ __forceinline__ uint32_t pack_h2(__half a, __half b) {
    __half2 t = __halves2half2(a, b);
    return *reinterpret_cast<uint32_t*>(&t);
}

__device__ __forceinline__ void mma_f16(float* d, const uint32_t* a,
                                        uint32_t b0, uint32_t b1) {
    asm volatile(
        "mma.sync.aligned.m16n8k16.row.col.f32.f16.f16.f32 "
        "{%0,%1,%2,%3}, {%4,%5,%6,%7}, {%8,%9}, {%0,%1,%2,%3};"
        : "+f"(d[0]), "+f"(d[1]), "+f"(d[2]), "+f"(d[3])
        : "r"(a[0]), "r"(a[1]), "r"(a[2]), "r"(a[3]), "r"(b0), "r"(b1));
}

#define LDSM_X4(r0, r1, r2, r3, addr) \
    asm volatile("ldmatrix.sync.aligned.m8n8.x4.shared.b16 {%0,%1,%2,%3}, [%4];" \
        : "=r"(r0), "=r"(r1), "=r"(r2), "=r"(r3) : "r"(addr))

#define CP_ASYNC16(dst, src) \
    asm volatile("cp.async.cg.shared.global [%0], [%1], 16;" \
        :: "r"(dst), "l"(src))
#define CP_COMMIT() asm volatile("cp.async.commit_group;")
#define CP_WAIT(n)  asm volatile("cp.async.wait_group %0;" :: "n"(n))

// ---------------------------------------------------------------------------
// Pre/post kernels (unchanged from R8)
// ---------------------------------------------------------------------------
__global__ __launch_bounds__(256) void cvt16_kernel(
    const float* __restrict__ src, __half* __restrict__ dst, int n4)
{
    int i = blockIdx.x * blockDim.x + threadIdx.x;
    if (i >= n4) return;
    float4 v = ((const float4*)src)[i];
    uint2 u;
    u.x = cvt_h2(v.x, v.y);
    u.y = cvt_h2(v.z, v.w);
    ((uint2*)dst)[i] = u;
}

__global__ __launch_bounds__(256) void split16_kernel(
    const float* __restrict__ src, __half* __restrict__ h,
    __half* __restrict__ l, int n4)
{
    int i = blockIdx.x * blockDim.x + threadIdx.x;
    if (i >= n4) return;
    float4 v = ((const float4*)src)[i];
    __half h0, h1, h2, h3, l0, l1, l2, l3;
    split_h16(v.x, h0, l0); split_h16(v.y, h1, l1);
    split_h16(v.z, h2, l2); split_h16(v.w, h3, l3);
    uint2 uh; uh.x = pack_h2(h0, h1); uh.y = pack_h2(h2, h3);
    uint2 ul; ul.x = pack_h2(l0, l1); ul.y = pack_h2(l2, l3);
    ((uint2*)h)[i] = uh;
    ((uint2*)l)[i] = ul;
}

__global__ __launch_bounds__(256) void normrope_split_kernel(
    const float* __restrict__ qkv,
    const float* __restrict__ qw, const float* __restrict__ kw,
    const int* __restrict__ positions,
    __half* __restrict__ qh_g, __half* __restrict__ ql_g,
    __half* __restrict__ kh_g, __half* __restrict__ kl_g, int T)
{
    const int warp = (blockIdx.x * blockDim.x + threadIdx.x) >> 5;
    const int lane = threadIdx.x & 31;
    if (warp >= T * 24) return;
    const int t = warp / 24;
    const int h = warp % 24;

    const float* x = qkv + (size_t)t * QKV_COLS + h * HEAD_DIM;
    const float* nw = (h < 16) ? qw : kw;

    float v0 = x[lane], v1 = x[lane + 32], v2 = x[lane + 64], v3 = x[lane + 96];
    float ss = v0 * v0 + v1 * v1 + v2 * v2 + v3 * v3;
    #pragma unroll
    for (int o = 16; o; o >>= 1) ss += __shfl_xor_sync(0xffffffffu, ss, o);
    const float rn = rsqrtf(ss * (1.0f / HEAD_DIM) + RMS_EPS);

    float n0 = v0 * rn * nw[lane];
    float n1 = v1 * rn * nw[lane + 32];
    float n2 = v2 * rn * nw[lane + 64];
    float n3 = v3 * rn * nw[lane + 96];

    const double pos = (double)positions[t];
    const double LOG_THETA = 13.815510557964274;
    double f0 = exp(-((double)(2 * lane) / 128.0) * LOG_THETA);
    double f1 = exp(-((double)(2 * (lane + 32)) / 128.0) * LOG_THETA);
    double s0d, c0d, s1d, c1d;
    sincos(pos * f0, &s0d, &c0d);
    sincos(pos * f1, &s1d, &c1d);
    float c0 = (float)c0d, s0 = (float)s0d, c1 = (float)c1d, s1 = (float)s1d;

    float r0 = n0 * c0 - n2 * s0;
    float r2 = n2 * c0 + n0 * s0;
    float r1 = n1 * c1 - n3 * s1;
    float r3 = n3 * c1 + n1 * s1;

    __half h0, l0, h1, l1, h2, l2, h3, l3;
    split_h16(r0, h0, l0); split_h16(r1, h1, l1);
    split_h16(r2, h2, l2); split_h16(r3, h3, l3);

    __half *dh, *dl;
    size_t base;
    if (h < 16) {
        base = (size_t)t * Q_SIZE + h * HEAD_DIM;
        dh = qh_g; dl = ql_g;
    } else {
        base = (size_t)(h - 16) * T * HEAD_DIM + (size_t)t * HEAD_DIM;
        dh = kh_g; dl = kl_g;
    }
    dh[base + lane] = h0;      dl[base + lane] = l0;
    dh[base + lane + 32] = h1; dl[base + lane + 32] = l1;
    dh[base + lane + 64] = h2; dl[base + lane + 64] = l2;
    dh[base + lane + 96] = h3; dl[base + lane + 96] = l3;
}

__global__ void vtrans_kernel(
    const float* __restrict__ qkv, __half* __restrict__ vh, int T)
{
    __shared__ float tile[32][33];
    const int kvh = blockIdx.z;
    const int d0 = blockIdx.y * 32;
    const int t0 = blockIdx.x * 32;
    for (int j = threadIdx.y; j < 32; j += 8) {
        tile[j][threadIdx.x] = qkv[(size_t)(t0 + j) * QKV_COLS + Q_SIZE + KV_SIZE
                                   + kvh * HEAD_DIM + d0 + threadIdx.x];
    }
    __syncthreads();
    for (int j = threadIdx.y; j < 32; j += 8) {
        float v = tile[threadIdx.x][j];
        size_t o = (size_t)kvh * HEAD_DIM * T + (size_t)(d0 + j) * T + t0 + threadIdx.x;
        vh[o] = __float2half_rn(v);
    }
}

// ---------------------------------------------------------------------------
// fp16 HMMA GEMM, 2 combos (unchanged from R8)
// ---------------------------------------------------------------------------
#define XBM 128
#define XBN 128
#define XBK 32
#define XSTR 40
#define STAGE_E (XBM * XSTR)
#define GEMM_SMEM (6 * STAGE_E * 2)

__global__ __launch_bounds__(256, 2) void gemm_f16s(
    const __half* __restrict__ A,
    const __half* __restrict__ Bh, const __half* __restrict__ Bl,
    float* __restrict__ C, int M, int N, int K)
{
    extern __shared__ __half smg[];
    const uint32_t smb = smem_to_u32(smg);

    const int tid  = threadIdx.x;
    const int lane = tid & 31;
    const int wid  = tid >> 5;
    const int gid  = lane >> 2;
    const int tq   = lane & 3;
    const int wm   = (wid & 3) * 32;
    const int wn   = (wid >> 2) * 64;

    const int arow  = lane & 15;
    const int acol8 = (lane >> 4) << 3;
    const int brow  = ((lane >> 4) << 3) + (lane & 7);
    const int bcol8 = ((lane >> 3) & 1) << 3;

    const int bm = blockIdx.y * XBM;
    const int bn = blockIdx.x * XBN;

    #define G_ISSUE(stage, k0) do { \
        uint32_t sb0 = smb + (uint32_t)(stage) * 3 * STAGE_E * 2; \
        _Pragma("unroll") \
        for (int j = 0; j < 2; j++) { \
            int id = tid + j * 256; \
            int r = id >> 2, c = (id & 3) * 8; \
            size_t aoff = (size_t)(bm + r) * K + (k0) + c; \
            size_t boff = (size_t)(bn + r) * K + (k0) + c; \
            uint32_t doff = (uint32_t)(r * XSTR + c) * 2; \
            CP_ASYNC16(sb0 + doff, A + aoff); \
            CP_ASYNC16(sb0 + STAGE_E * 2 + doff, Bh + boff); \
            CP_ASYNC16(sb0 + 2 * STAGE_E * 2 + doff, Bl + boff); \
        } \
    } while (0)

    float acc[2][8][4] = {};

    G_ISSUE(0, 0);
    CP_COMMIT();

    int stage = 0;
    for (int k0 = 0; k0 < K; k0 += XBK, stage ^= 1) {
        if (k0 + XBK < K) {
            G_ISSUE(stage ^ 1, k0 + XBK);
            CP_COMMIT();
            CP_WAIT(1);
        } else {
            CP_WAIT(0);
        }
        __syncthreads();

        const uint32_t sA  = smb + (uint32_t)stage * 3 * STAGE_E * 2;
        const uint32_t sBh = sA + STAGE_E * 2;
        const uint32_t sBl = sBh + STAGE_E * 2;

        #pragma unroll
        for (int kk = 0; kk < XBK; kk += 16) {
            uint32_t a[2][4];
            #pragma unroll
            for (int mt = 0; mt < 2; mt++) {
                uint32_t aoff = (uint32_t)((wm + mt * 16 + arow) * XSTR + kk + acol8) * 2;
                LDSM_X4(a[mt][0], a[mt][1], a[mt][2], a[mt][3], sA + aoff);
            }
            #pragma unroll
            for (int p = 0; p < 4; p++) {
                uint32_t boff = (uint32_t)((wn + p * 16 + brow) * XSTR + kk + bcol8) * 2;
                uint32_t bh0, bh1, bh2, bh3, bl0, bl1, bl2, bl3;
                LDSM_X4(bh0, bh1, bh2, bh3, sBh + boff);
                LDSM_X4(bl0, bl1, bl2, bl3, sBl + boff);
                #pragma unroll
                for (int mt = 0; mt < 2; mt++) {
                    mma_f16(acc[mt][2 * p], a[mt], bh0, bh1);
                    mma_f16(acc[mt][2 * p], a[mt], bl0, bl1);
                    mma_f16(acc[mt][2 * p + 1], a[mt], bh2, bh3);
                    mma_f16(acc[mt][2 * p + 1], a[mt], bl2, bl3);
                }
            }
        }
        __syncthreads();
    }

    #pragma unroll
    for (int mt = 0; mt < 2; mt++) {
        int row = bm + wm + mt * 16 + gid;
        #pragma unroll
        for (int nt = 0; nt < 8; nt++) {
            int col = bn + wn + nt * 8 + tq * 2;
            *(float2*)&C[(size_t)row * N + col] =
                make_float2(acc[mt][nt][0], acc[mt][nt][1]);
            *(float2*)&C[(size_t)(row + 8) * N + col] =
                make_float2(acc[mt][nt][2], acc[mt][nt][3]);
        }
    }
}

// ---------------------------------------------------------------------------
// fp16 HMMA flash attention — fully double-buffered, ONE sync per iteration.
// Buffers: K0h K0l K1h K1l V0 V1 (Q staged through K1 in prologue).
// Schedule: wait group(it) -> sync -> prefetch(it+1) -> QK/softmax/PV.
// ---------------------------------------------------------------------------
#define SSTR 136
#define TILE_B (128 * SSTR * 2)      // 34816 bytes
#define ATT_SMEM (6 * TILE_B)        // 208896 bytes

__global__ __launch_bounds__(256, 1) void attn_mma(
    const __half* __restrict__ qh_g, const __half* __restrict__ ql_g,
    const __half* __restrict__ kh_g, const __half* __restrict__ kl_g,
    const __half* __restrict__ v_g,
    __half* __restrict__ attn_out, int T)
{
    extern __shared__ char sm[];
    const uint32_t smb = smem_to_u32(sm);
    const int tid  = threadIdx.x;
    const int lane = tid & 31;
    const int wid  = tid >> 5;
    const int gid  = lane >> 2;
    const int tq   = lane & 3;

    const int qb   = (gridDim.x - 1) - blockIdx.x;
    const int head = blockIdx.y;
    const int kvh  = head >> 1;
    const int q0   = qb * 128;
    const int wrow = wid * 16;
    const int iters = qb + 1;

    const int arow  = lane & 15;
    const int acol8 = (lane >> 4) << 3;
    const int brow  = ((lane >> 4) << 3) + (lane & 7);
    const int bcol8 = ((lane >> 3) & 1) << 3;

    const size_t kbase = (size_t)kvh * T * HEAD_DIM;
    const size_t vbase = (size_t)kvh * HEAD_DIM * T;

    // Buffer bases: stage s: Kh = s*2, Kl = s*2+1; V = 4+s
    // Prefetch group for iteration `itn` into stage itn&1
    #define ATT_PREFETCH(itn) do { \
        const int st_ = (itn) & 1; \
        const uint32_t khb_ = smb + (uint32_t)(st_ * 2) * TILE_B; \
        const uint32_t klb_ = khb_ + TILE_B; \
        const uint32_t vb_  = smb + (uint32_t)(4 + st_) * TILE_B; \
        const size_t ko_ = kbase + (size_t)(itn) * 128 * HEAD_DIM; \
        const size_t vo_ = vbase + (size_t)(itn) * 128; \
        for (int i = tid; i < 2048; i += 256) { \
            int r_ = i >> 4, c_ = (i & 15) << 3; \
            uint32_t doff_ = (uint32_t)(r_ * SSTR + c_) * 2; \
            CP_ASYNC16(khb_ + doff_, kh_g + ko_ + (size_t)r_ * HEAD_DIM + c_); \
            CP_ASYNC16(klb_ + doff_, kl_g + ko_ + (size_t)r_ * HEAD_DIM + c_); \
            CP_ASYNC16(vb_ + doff_, v_g + vo_ + (size_t)r_ * T + c_); \
        } \
        CP_COMMIT(); \
    } while (0)

    // ---- Prologue: prefetch group 0 (K(0),V(0) -> stage 0) ----
    ATT_PREFETCH(0);

    // Stage Q through stage-1 K buffers (plain loads)
    {
        const uint32_t qhb = smb + 2u * TILE_B;   // K1h
        const uint32_t qlb = smb + 3u * TILE_B;   // K1l
        for (int i = tid; i < 2048; i += 256) {
            int r = i >> 4, c = (i & 15) << 3;
            uint32_t doff = (uint32_t)(r * SSTR + c) * 2;
            size_t o = (size_t)(q0 + r) * Q_SIZE + head * HEAD_DIM + c;
            *(uint4*)(sm + (qhb - smb) + doff) = *(const uint4*)&qh_g[o];
            *(uint4*)(sm + (qlb - smb) + doff) = *(const uint4*)&ql_g[o];
        }
        __syncthreads();

        // Persistent Q fragments
        // (declared below; fill here)
    }

    uint32_t qh[8][4], ql[8][4];
    {
        const uint32_t qhb = smb + 2u * TILE_B;
        const uint32_t qlb = smb + 3u * TILE_B;
        #pragma unroll
        for (int kt = 0; kt < 8; kt++) {
            uint32_t aoff = (uint32_t)((wrow + arow) * SSTR + kt * 16 + acol8) * 2;
            LDSM_X4(qh[kt][0], qh[kt][1], qh[kt][2], qh[kt][3], qhb + aoff);
            LDSM_X4(ql[kt][0], ql[kt][1], ql[kt][2], ql[kt][3], qlb + aoff);
        }
    }
    // NOTE: no sync here — the first loop sync (it=0) orders frag-build
    // before prefetch(1) overwrites the Q staging buffers.

    const int grow0 = q0 + wrow + gid;
    const int grow1 = grow0 + 8;

    float m0 = -1e30f, m1 = -1e30f, l0s = 0.0f, l1s = 0.0f;
    float o[16][4] = {};

    for (int it = 0; it < iters; it++) {
        const int k0 = it * 128;
        const int st = it & 1;
        const uint32_t kh_b = smb + (uint32_t)(st * 2) * TILE_B;
        const uint32_t kl_b = kh_b + TILE_B;
        const uint32_t v_b  = smb + (uint32_t)(4 + st) * TILE_B;

        CP_WAIT(0);        // group(it) complete (only group in flight)
        __syncthreads();   // visibility + all warps done with stage it^1

        if (it + 1 < iters) ATT_PREFETCH(it + 1);   // into stage (it+1)&1

        // ---- S = Q K^T (3 combos) ----
        float s[16][4];
        #pragma unroll
        for (int nt = 0; nt < 16; nt++)
            #pragma unroll
            for (int c = 0; c < 4; c++) s[nt][c] = 0.0f;

        #pragma unroll
        for (int kt = 0; kt < 8; kt++) {
            #pragma unroll
            for (int p = 0; p < 8; p++) {
                uint32_t boff = (uint32_t)((p * 16 + brow) * SSTR + kt * 16 + bcol8) * 2;
                uint32_t bh0, bh1, bh2, bh3, bl0, bl1, bl2, bl3;
                LDSM_X4(bh0, bh1, bh2, bh3, kh_b + boff);
                LDSM_X4(bl0, bl1, bl2, bl3, kl_b + boff);
                mma_f16(s[2 * p], qh[kt], bh0, bh1);
                mma_f16(s[2 * p], qh[kt], bl0, bl1);
                mma_f16(s[2 * p], ql[kt], bh0, bh1);
                mma_f16(s[2 * p + 1], qh[kt], bh2, bh3);
                mma_f16(s[2 * p + 1], qh[kt], bl2, bl3);
                mma_f16(s[2 * p + 1], ql[kt], bh2, bh3);
            }
        }

        // ---- scale (log2-domain) + mask + online softmax ----
        const bool diag = (it == qb);
        float mx0 = m0, mx1 = m1;
        #pragma unroll
        for (int nt = 0; nt < 16; nt++) {
            int colb = k0 + nt * 8 + tq * 2;
            #pragma unroll
            for (int c = 0; c < 2; c++) {
                float v0 = s[nt][c] * SCALE_L2E;
                float v1 = s[nt][c + 2] * SCALE_L2E;
                if (diag && (colb + c > grow0)) v0 = -1e30f;
                if (diag && (colb + c > grow1)) v1 = -1e30f;
                s[nt][c] = v0; s[nt][c + 2] = v1;
                mx0 = fmaxf(mx0, v0); mx1 = fmaxf(mx1, v1);
            }
        }
        mx0 = fmaxf(mx0, __shfl_xor_sync(0xffffffffu, mx0, 1));
        mx0 = fmaxf(mx0, __shfl_xor_sync(0xffffffffu, mx0, 2));
        mx1 = fmaxf(mx1, __shfl_xor_sync(0xffffffffu, mx1, 1));
        mx1 = fmaxf(mx1, __shfl_xor_sync(0xffffffffu, mx1, 2));

        const float a0 = ex2f(m0 - mx0);
        const float a1 = ex2f(m1 - mx1);
        m0 = mx0; m1 = mx1;

        float sum0 = 0.0f, sum1 = 0.0f;
        #pragma unroll
        for (int nt = 0; nt < 16; nt++) {
            #pragma unroll
            for (int c = 0; c < 2; c++) {
                float p0 = ex2f(s[nt][c] - m0);
                float p1 = ex2f(s[nt][c + 2] - m1);
                s[nt][c] = p0; s[nt][c + 2] = p1;
                sum0 += p0; sum1 += p1;
            }
        }
        sum0 += __shfl_xor_sync(0xffffffffu, sum0, 1);
        sum0 += __shfl_xor_sync(0xffffffffu, sum0, 2);
        sum1 += __shfl_xor_sync(0xffffffffu, sum1, 1);
        sum1 += __shfl_xor_sync(0xffffffffu, sum1, 2);
        l0s = l0s * a0 + sum0;
        l1s = l1s * a1 + sum1;

        #pragma unroll
        for (int nt = 0; nt < 16; nt++) {
            o[nt][0] *= a0; o[nt][1] *= a0;
            o[nt][2] *= a1; o[nt][3] *= a1;
        }

        // ---- O += P @ V (1 combo) ----
        #pragma unroll
        for (int kt = 0; kt < 8; kt++) {
            uint32_t ph[4];
            ph[0] = cvt_h2(s[2 * kt][0], s[2 * kt][1]);
            ph[1] = cvt_h2(s[2 * kt][2], s[2 * kt][3]);
            ph[2] = cvt_h2(s[2 * kt + 1][0], s[2 * kt + 1][1]);
            ph[3] = cvt_h2(s[2 * kt + 1][2], s[2 * kt + 1][3]);
            #pragma unroll
            for (int p = 0; p < 8; p++) {
                uint32_t boff = (uint32_t)((p * 16 + brow) * SSTR + kt * 16 + bcol8) * 2;
                uint32_t vh0, vh1, vh2, vh3;
                LDSM_X4(vh0, vh1, vh2, vh3, v_b + boff);
                mma_f16(o[2 * p], ph, vh0, vh1);
                mma_f16(o[2 * p + 1], ph, vh2, vh3);
            }
        }
    }

    // ---- Epilogue: normalize, store single fp16 ----
    const float inv0 = 1.0f / l0s;
    const float inv1 = 1.0f / l1s;
    #pragma unroll
    for (int nt = 0; nt < 16; nt++) {
        int dcol = head * HEAD_DIM + nt * 8 + tq * 2;
        *(uint32_t*)&attn_out[(size_t)grow0 * Q_SIZE + dcol] =
            cvt_h2(o[nt][0] * inv0, o[nt][1] * inv0);
        *(uint32_t*)&attn_out[(size_t)grow1 * Q_SIZE + dcol] =
            cvt_h2(o[nt][2] * inv1, o[nt][3] * inv1);
    }
}

// ---------------------------------------------------------------------------
// Launch
// ---------------------------------------------------------------------------
extern "C" void kernel_launch(void* const* d_in, const int* in_sizes, int n_in,
                              void* d_out, int out_size)
{
    const float* hidden = (const float*)d_in[0];
    const float* qkv_w  = (const float*)d_in[1];
    const float* q_nw   = (const float*)d_in[2];
    const float* k_nw   = (const float*)d_in[3];
    const float* o_w    = (const float*)d_in[4];
    const int*   pos    = (const int*)d_in[5];
    float* out = (float*)d_out;

    const int T = in_sizes[0] / HIDDEN;

    float* qkv;  cudaGetSymbolAddress((void**)&qkv,  g_qkv);
    __half *hid, *w1_h, *w1_l, *w2_h, *w2_l, *at;
    __half *q_h, *q_l, *k_h, *k_l, *v;
    cudaGetSymbolAddress((void**)&hid,  g_hid);
    cudaGetSymbolAddress((void**)&w1_h, g_w1_h);
    cudaGetSymbolAddress((void**)&w1_l, g_w1_l);
    cudaGetSymbolAddress((void**)&w2_h, g_w2_h);
    cudaGetSymbolAddress((void**)&w2_l, g_w2_l);
    cudaGetSymbolAddress((void**)&at,   g_at);
    cudaGetSymbolAddress((void**)&q_h,  g_q_h);
    cudaGetSymbolAddress((void**)&q_l,  g_q_l);
    cudaGetSymbolAddress((void**)&k_h,  g_k_h);
    cudaGetSymbolAddress((void**)&k_l,  g_k_l);
    cudaGetSymbolAddress((void**)&v,    g_v);

    cudaFuncSetAttribute(attn_mma, cudaFuncAttributeMaxDynamicSharedMemorySize,
                         ATT_SMEM);
    cudaFuncSetAttribute(gemm_f16s, cudaFuncAttributeMaxDynamicSharedMemorySize,
                         GEMM_SMEM);

    // 0) Convert/split inputs
    {
        int n4 = T * HIDDEN / 4;
        cvt16_kernel<<<(n4 + 255) / 256, 256>>>(hidden, hid, n4);
        n4 = QKV_COLS * HIDDEN / 4;
        split16_kernel<<<(n4 + 255) / 256, 256>>>(qkv_w, w1_h, w1_l, n4);
        n4 = HIDDEN * Q_SIZE / 4;
        split16_kernel<<<(n4 + 255) / 256, 256>>>(o_w, w2_h, w2_l, n4);
    }
    // 1) QKV projection
    {
        dim3 grid(QKV_COLS / XBN, T / XBM);
        gemm_f16s<<<grid, 256, GEMM_SMEM>>>(hid, w1_h, w1_l, qkv,
                                            T, QKV_COLS, HIDDEN);
    }
    // 2) Fused RMSNorm + RoPE + split (Q, K); transpose V
    {
        int warps = T * 24;
        int blocks = (warps + 7) / 8;
        normrope_split_kernel<<<blocks, 256>>>(qkv, q_nw, k_nw, pos,
                                               q_h, q_l, k_h, k_l, T);
        dim3 vg(T / 32, HEAD_DIM / 32, NUM_KV);
        vtrans_kernel<<<vg, dim3(32, 8)>>>(qkv, v, T);
    }
    // 3) Attention
    {
        dim3 grid(T / 128, NUM_HEADS);
        attn_mma<<<grid, 256, ATT_SMEM>>>(q_h, q_l, k_h, k_l, v, at, T);
    }
    // 4) Output projection
    {
        dim3 grid(HIDDEN / XBN, T / XBM);
        gemm_f16s<<<grid, 256, GEMM_SMEM>>>(at, w2_h, w2_l, out,
                                            T, HIDDEN, HIDDEN);
    }
}

// round 10
// speedup vs baseline: 4.5222x; 1.0097x over previous
#include <cuda_runtime.h>
#include <cuda_bf16.h>
#include <cuda_fp16.h>
#include <math.h>
#include <float.h>
#include <cstdint>

// Problem constants
#define HIDDEN    2048
#define NUM_HEADS 16
#define NUM_KV    8
#define HEAD_DIM  128
#define Q_SIZE    (NUM_HEADS * HEAD_DIM)        // 2048
#define KV_SIZE   (NUM_KV * HEAD_DIM)           // 1024
#define QKV_COLS  (Q_SIZE + 2 * KV_SIZE)        // 4096
#define SCALE     0.08838834764831845f          // 128^-0.5
#define SCALE_L2E 0.12751985675839602f          // SCALE * log2(e)
#define RMS_EPS   1e-6f

#define MAX_T 4096

// Scratch (static device globals)
__device__ float g_qkv[(size_t)MAX_T * QKV_COLS];
__device__ __half g_hid[(size_t)MAX_T * HIDDEN];
__device__ __half g_w1_h[(size_t)QKV_COLS * HIDDEN];
__device__ __half g_w1_l[(size_t)QKV_COLS * HIDDEN];
__device__ __half g_w2_h[(size_t)HIDDEN * Q_SIZE];
__device__ __half g_w2_l[(size_t)HIDDEN * Q_SIZE];
__device__ __half g_at[(size_t)MAX_T * Q_SIZE];
__device__ __half g_q_h[(size_t)MAX_T * Q_SIZE];
__device__ __half g_q_l[(size_t)MAX_T * Q_SIZE];
__device__ __half g_k_h[(size_t)NUM_KV * MAX_T * HEAD_DIM];
__device__ __half g_k_l[(size_t)NUM_KV * MAX_T * HEAD_DIM];
__device__ __half g_v[(size_t)NUM_KV * HEAD_DIM * MAX_T];   // [kvh][d][t]

// ===========================================================================
// Helpers
// ===========================================================================
__device__ __forceinline__ uint32_t smem_to_u32(const void* p) {
    uint32_t a;
    asm("{ .reg .u64 t; cvta.to.shared.u64 t, %1; cvt.u32.u64 %0, t; }"
        : "=r"(a) : "l"(p));
    return a;
}
__device__ __forceinline__ void split_h16(float x, __half& h, __half& l) {
    h = __float2half_rn(x);
    l = __float2half_rn(x - __half2float(h));
}
__device__ __forceinline__ float ex2f(float x) {
    float r;
    asm("ex2.approx.f32 %0, %1;" : "=f"(r) : "f"(x));
    return r;
}
__device__ __forceinline__ uint32_t cvt_h2(float a, float b) {
    uint32_t r;
    asm("cvt.rn.f16x2.f32 %0, %1, %2;" : "=r"(r) : "f"(b), "f"(a));
    return r;
}
__device__ __forceinline__ uint32_t pack_h2(__half a, __half b) {
    __half2 t = __halves2half2(a, b);
    return *reinterpret_cast<uint32_t*>(&t);
}

__device__ __forceinline__ void mma_f16(float* d, const uint32_t* a,
                                        uint32_t b0, uint32_t b1) {
    asm volatile(
        "mma.sync.aligned.m16n8k16.row.col.f32.f16.f16.f32 "
        "{%0,%1,%2,%3}, {%4,%5,%6,%7}, {%8,%9}, {%0,%1,%2,%3};"
        : "+f"(d[0]), "+f"(d[1]), "+f"(d[2]), "+f"(d[3])
        : "r"(a[0]), "r"(a[1]), "r"(a[2]), "r"(a[3]), "r"(b0), "r"(b1));
}

#define LDSM_X4(r0, r1, r2, r3, addr) \
    asm volatile("ldmatrix.sync.aligned.m8n8.x4.shared.b16 {%0,%1,%2,%3}, [%4];" \
        : "=r"(r0), "=r"(r1), "=r"(r2), "=r"(r3) : "r"(addr))

#define CP_ASYNC16(dst, src) \
    asm volatile("cp.async.cg.shared.global [%0], [%1], 16;" \
        :: "r"(dst), "l"(src))
#define CP_COMMIT() asm volatile("cp.async.commit_group;")
#define CP_WAIT(n)  asm volatile("cp.async.wait_group %0;" :: "n"(n))

// ---------------------------------------------------------------------------
// Pre/post kernels (unchanged)
// ---------------------------------------------------------------------------
__global__ __launch_bounds__(256) void cvt16_kernel(
    const float* __restrict__ src, __half* __restrict__ dst, int n4)
{
    int i = blockIdx.x * blockDim.x + threadIdx.x;
    if (i >= n4) return;
    float4 v = ((const float4*)src)[i];
    uint2 u;
    u.x = cvt_h2(v.x, v.y);
    u.y = cvt_h2(v.z, v.w);
    ((uint2*)dst)[i] = u;
}

__global__ __launch_bounds__(256) void split16_kernel(
    const float* __restrict__ src, __half* __restrict__ h,
    __half* __restrict__ l, int n4)
{
    int i = blockIdx.x * blockDim.x + threadIdx.x;
    if (i >= n4) return;
    float4 v = ((const float4*)src)[i];
    __half h0, h1, h2, h3, l0, l1, l2, l3;
    split_h16(v.x, h0, l0); split_h16(v.y, h1, l1);
    split_h16(v.z, h2, l2); split_h16(v.w, h3, l3);
    uint2 uh; uh.x = pack_h2(h0, h1); uh.y = pack_h2(h2, h3);
    uint2 ul; ul.x = pack_h2(l0, l1); ul.y = pack_h2(l2, l3);
    ((uint2*)h)[i] = uh;
    ((uint2*)l)[i] = ul;
}

__global__ __launch_bounds__(256) void normrope_split_kernel(
    const float* __restrict__ qkv,
    const float* __restrict__ qw, const float* __restrict__ kw,
    const int* __restrict__ positions,
    __half* __restrict__ qh_g, __half* __restrict__ ql_g,
    __half* __restrict__ kh_g, __half* __restrict__ kl_g, int T)
{
    const int warp = (blockIdx.x * blockDim.x + threadIdx.x) >> 5;
    const int lane = threadIdx.x & 31;
    if (warp >= T * 24) return;
    const int t = warp / 24;
    const int h = warp % 24;

    const float* x = qkv + (size_t)t * QKV_COLS + h * HEAD_DIM;
    const float* nw = (h < 16) ? qw : kw;

    float v0 = x[lane], v1 = x[lane + 32], v2 = x[lane + 64], v3 = x[lane + 96];
    float ss = v0 * v0 + v1 * v1 + v2 * v2 + v3 * v3;
    #pragma unroll
    for (int o = 16; o; o >>= 1) ss += __shfl_xor_sync(0xffffffffu, ss, o);
    const float rn = rsqrtf(ss * (1.0f / HEAD_DIM) + RMS_EPS);

    float n0 = v0 * rn * nw[lane];
    float n1 = v1 * rn * nw[lane + 32];
    float n2 = v2 * rn * nw[lane + 64];
    float n3 = v3 * rn * nw[lane + 96];

    const double pos = (double)positions[t];
    const double LOG_THETA = 13.815510557964274;
    double f0 = exp(-((double)(2 * lane) / 128.0) * LOG_THETA);
    double f1 = exp(-((double)(2 * (lane + 32)) / 128.0) * LOG_THETA);
    double s0d, c0d, s1d, c1d;
    sincos(pos * f0, &s0d, &c0d);
    sincos(pos * f1, &s1d, &c1d);
    float c0 = (float)c0d, s0 = (float)s0d, c1 = (float)c1d, s1 = (float)s1d;

    float r0 = n0 * c0 - n2 * s0;
    float r2 = n2 * c0 + n0 * s0;
    float r1 = n1 * c1 - n3 * s1;
    float r3 = n3 * c1 + n1 * s1;

    __half h0, l0, h1, l1, h2, l2, h3, l3;
    split_h16(r0, h0, l0); split_h16(r1, h1, l1);
    split_h16(r2, h2, l2); split_h16(r3, h3, l3);

    __half *dh, *dl;
    size_t base;
    if (h < 16) {
        base = (size_t)t * Q_SIZE + h * HEAD_DIM;
        dh = qh_g; dl = ql_g;
    } else {
        base = (size_t)(h - 16) * T * HEAD_DIM + (size_t)t * HEAD_DIM;
        dh = kh_g; dl = kl_g;
    }
    dh[base + lane] = h0;      dl[base + lane] = l0;
    dh[base + lane + 32] = h1; dl[base + lane + 32] = l1;
    dh[base + lane + 64] = h2; dl[base + lane + 64] = l2;
    dh[base + lane + 96] = h3; dl[base + lane + 96] = l3;
}

__global__ void vtrans_kernel(
    const float* __restrict__ qkv, __half* __restrict__ vh, int T)
{
    __shared__ float tile[32][33];
    const int kvh = blockIdx.z;
    const int d0 = blockIdx.y * 32;
    const int t0 = blockIdx.x * 32;
    for (int j = threadIdx.y; j < 32; j += 8) {
        tile[j][threadIdx.x] = qkv[(size_t)(t0 + j) * QKV_COLS + Q_SIZE + KV_SIZE
                                   + kvh * HEAD_DIM + d0 + threadIdx.x];
    }
    __syncthreads();
    for (int j = threadIdx.y; j < 32; j += 8) {
        float v = tile[threadIdx.x][j];
        size_t o = (size_t)kvh * HEAD_DIM * T + (size_t)(d0 + j) * T + t0 + threadIdx.x;
        vh[o] = __float2half_rn(v);
    }
}

// ---------------------------------------------------------------------------
// fp16 HMMA GEMM, 2 combos (unchanged)
// ---------------------------------------------------------------------------
#define XBM 128
#define XBN 128
#define XBK 32
#define XSTR 40
#define STAGE_E (XBM * XSTR)
#define GEMM_SMEM (6 * STAGE_E * 2)

__global__ __launch_bounds__(256, 2) void gemm_f16s(
    const __half* __restrict__ A,
    const __half* __restrict__ Bh, const __half* __restrict__ Bl,
    float* __restrict__ C, int M, int N, int K)
{
    extern __shared__ __half smg[];
    const uint32_t smb = smem_to_u32(smg);

    const int tid  = threadIdx.x;
    const int lane = tid & 31;
    const int wid  = tid >> 5;
    const int gid  = lane >> 2;
    const int tq   = lane & 3;
    const int wm   = (wid & 3) * 32;
    const int wn   = (wid >> 2) * 64;

    const int arow  = lane & 15;
    const int acol8 = (lane >> 4) << 3;
    const int brow  = ((lane >> 4) << 3) + (lane & 7);
    const int bcol8 = ((lane >> 3) & 1) << 3;

    const int bm = blockIdx.y * XBM;
    const int bn = blockIdx.x * XBN;

    #define G_ISSUE(stage, k0) do { \
        uint32_t sb0 = smb + (uint32_t)(stage) * 3 * STAGE_E * 2; \
        _Pragma("unroll") \
        for (int j = 0; j < 2; j++) { \
            int id = tid + j * 256; \
            int r = id >> 2, c = (id & 3) * 8; \
            size_t aoff = (size_t)(bm + r) * K + (k0) + c; \
            size_t boff = (size_t)(bn + r) * K + (k0) + c; \
            uint32_t doff = (uint32_t)(r * XSTR + c) * 2; \
            CP_ASYNC16(sb0 + doff, A + aoff); \
            CP_ASYNC16(sb0 + STAGE_E * 2 + doff, Bh + boff); \
            CP_ASYNC16(sb0 + 2 * STAGE_E * 2 + doff, Bl + boff); \
        } \
    } while (0)

    float acc[2][8][4] = {};

    G_ISSUE(0, 0);
    CP_COMMIT();

    int stage = 0;
    for (int k0 = 0; k0 < K; k0 += XBK, stage ^= 1) {
        if (k0 + XBK < K) {
            G_ISSUE(stage ^ 1, k0 + XBK);
            CP_COMMIT();
            CP_WAIT(1);
        } else {
            CP_WAIT(0);
        }
        __syncthreads();

        const uint32_t sA  = smb + (uint32_t)stage * 3 * STAGE_E * 2;
        const uint32_t sBh = sA + STAGE_E * 2;
        const uint32_t sBl = sBh + STAGE_E * 2;

        #pragma unroll
        for (int kk = 0; kk < XBK; kk += 16) {
            uint32_t a[2][4];
            #pragma unroll
            for (int mt = 0; mt < 2; mt++) {
                uint32_t aoff = (uint32_t)((wm + mt * 16 + arow) * XSTR + kk + acol8) * 2;
                LDSM_X4(a[mt][0], a[mt][1], a[mt][2], a[mt][3], sA + aoff);
            }
            #pragma unroll
            for (int p = 0; p < 4; p++) {
                uint32_t boff = (uint32_t)((wn + p * 16 + brow) * XSTR + kk + bcol8) * 2;
                uint32_t bh0, bh1, bh2, bh3, bl0, bl1, bl2, bl3;
                LDSM_X4(bh0, bh1, bh2, bh3, sBh + boff);
                LDSM_X4(bl0, bl1, bl2, bl3, sBl + boff);
                #pragma unroll
                for (int mt = 0; mt < 2; mt++) {
                    mma_f16(acc[mt][2 * p], a[mt], bh0, bh1);
                    mma_f16(acc[mt][2 * p], a[mt], bl0, bl1);
                    mma_f16(acc[mt][2 * p + 1], a[mt], bh2, bh3);
                    mma_f16(acc[mt][2 * p + 1], a[mt], bl2, bl3);
                }
            }
        }
        __syncthreads();
    }

    #pragma unroll
    for (int mt = 0; mt < 2; mt++) {
        int row = bm + wm + mt * 16 + gid;
        #pragma unroll
        for (int nt = 0; nt < 8; nt++) {
            int col = bn + wn + nt * 8 + tq * 2;
            *(float2*)&C[(size_t)row * N + col] =
                make_float2(acc[mt][nt][0], acc[mt][nt][1]);
            *(float2*)&C[(size_t)(row + 8) * N + col] =
                make_float2(acc[mt][nt][2], acc[mt][nt][3]);
        }
    }
}

// ---------------------------------------------------------------------------
// fp16 HMMA flash attention — 64-row q blocks, 64-row kv tiles, 128 threads
// (4 warps x 16 rows), double-buffered, ONE sync/iter, 2 CTAs/SM.
// ---------------------------------------------------------------------------
#define AQB 64                          // q rows per CTA
#define AKB 64                          // kv rows per tile
#define SSTR 136                        // K tile row stride (128 d + 8 pad)
#define VSTR 72                         // V tile row stride (64 t + 8 pad)
#define KT_B (AKB * SSTR * 2)           // 17408 B per K buffer
#define VT_B (HEAD_DIM * VSTR * 2)      // 18432 B per V buffer
// layout: K0h K0l K1h K1l V0 V1
#define OFF_K(s)  ((uint32_t)(s) * 2u * KT_B)
#define OFF_KL(s) (OFF_K(s) + KT_B)
#define OFF_V(s)  (4u * KT_B + (uint32_t)(s) * VT_B)
#define ATT_SMEM  (4 * KT_B + 2 * VT_B) // 106496 B

__global__ __launch_bounds__(128, 2) void attn_mma(
    const __half* __restrict__ qh_g, const __half* __restrict__ ql_g,
    const __half* __restrict__ kh_g, const __half* __restrict__ kl_g,
    const __half* __restrict__ v_g,
    __half* __restrict__ attn_out, int T)
{
    extern __shared__ char sm[];
    const uint32_t smb = smem_to_u32(sm);
    const int tid  = threadIdx.x;
    const int lane = tid & 31;
    const int wid  = tid >> 5;          // 0..3
    const int gid  = lane >> 2;
    const int tq   = lane & 3;

    const int qb   = (gridDim.x - 1) - blockIdx.x;   // big blocks first
    const int head = blockIdx.y;
    const int kvh  = head >> 1;
    const int q0   = qb * AQB;
    const int wrow = wid * 16;
    const int iters = qb + 1;

    const int arow  = lane & 15;
    const int acol8 = (lane >> 4) << 3;
    const int brow  = ((lane >> 4) << 3) + (lane & 7);
    const int bcol8 = ((lane >> 3) & 1) << 3;

    const size_t kbase = (size_t)kvh * T * HEAD_DIM;
    const size_t vbase = (size_t)kvh * HEAD_DIM * T;

    // Prefetch group for kv tile `itn` into stage itn&1.
    // K: 64 rows x 128 d (hi+lo). V: 128 d-rows x 64 t.
    #define ATT_PREFETCH(itn) do { \
        const int st_ = (itn) & 1; \
        const uint32_t khb_ = smb + OFF_K(st_); \
        const uint32_t klb_ = smb + OFF_KL(st_); \
        const uint32_t vb_  = smb + OFF_V(st_); \
        const size_t ko_ = kbase + (size_t)(itn) * AKB * HEAD_DIM; \
        const size_t vo_ = vbase + (size_t)(itn) * AKB; \
        for (int i = tid; i < 1024; i += 128) { \
            int r_ = i >> 4, c_ = (i & 15) << 3; \
            uint32_t doff_ = (uint32_t)(r_ * SSTR + c_) * 2; \
            CP_ASYNC16(khb_ + doff_, kh_g + ko_ + (size_t)r_ * HEAD_DIM + c_); \
            CP_ASYNC16(klb_ + doff_, kl_g + ko_ + (size_t)r_ * HEAD_DIM + c_); \
            int d_ = i >> 3, vc_ = (i & 7) << 3; \
            uint32_t vdoff_ = (uint32_t)(d_ * VSTR + vc_) * 2; \
            CP_ASYNC16(vb_ + vdoff_, v_g + vo_ + (size_t)d_ * T + vc_); \
        } \
        CP_COMMIT(); \
    } while (0)

    // ---- Prologue: prefetch tile 0 into stage 0 ----
    ATT_PREFETCH(0);

    // Stage Q (64 x 128 hi/lo) through stage-1 K buffers
    {
        const uint32_t qhb = smb + OFF_K(1);
        const uint32_t qlb = smb + OFF_KL(1);
        for (int i = tid; i < 1024; i += 128) {
            int r = i >> 4, c = (i & 15) << 3;
            uint32_t doff = (uint32_t)(r * SSTR + c) * 2;
            size_t o = (size_t)(q0 + r) * Q_SIZE + head * HEAD_DIM + c;
            *(uint4*)(sm + (qhb - smb) + doff) = *(const uint4*)&qh_g[o];
            *(uint4*)(sm + (qlb - smb) + doff) = *(const uint4*)&ql_g[o];
        }
        __syncthreads();
    }

    uint32_t qh[8][4], ql[8][4];
    {
        const uint32_t qhb = smb + OFF_K(1);
        const uint32_t qlb = smb + OFF_KL(1);
        #pragma unroll
        for (int kt = 0; kt < 8; kt++) {
            uint32_t aoff = (uint32_t)((wrow + arow) * SSTR + kt * 16 + acol8) * 2;
            LDSM_X4(qh[kt][0], qh[kt][1], qh[kt][2], qh[kt][3], qhb + aoff);
            LDSM_X4(ql[kt][0], ql[kt][1], ql[kt][2], ql[kt][3], qlb + aoff);
        }
    }
    // First loop sync (it=0) orders frag-build before prefetch(1) overwrites.

    const int grow0 = q0 + wrow + gid;
    const int grow1 = grow0 + 8;

    float m0 = -1e30f, m1 = -1e30f, l0s = 0.0f, l1s = 0.0f;
    float o[16][4] = {};

    for (int it = 0; it < iters; it++) {
        const int k0 = it * AKB;
        const int st = it & 1;
        const uint32_t kh_b = smb + OFF_K(st);
        const uint32_t kl_b = smb + OFF_KL(st);
        const uint32_t v_b  = smb + OFF_V(st);

        CP_WAIT(0);
        __syncthreads();

        if (it + 1 < iters) ATT_PREFETCH(it + 1);

        // ---- S = Q K^T (3 combos): warp 16 x 64 ----
        float s[8][4];
        #pragma unroll
        for (int nt = 0; nt < 8; nt++)
            #pragma unroll
            for (int c = 0; c < 4; c++) s[nt][c] = 0.0f;

        #pragma unroll
        for (int kt = 0; kt < 8; kt++) {
            #pragma unroll
            for (int p = 0; p < 4; p++) {
                uint32_t boff = (uint32_t)((p * 16 + brow) * SSTR + kt * 16 + bcol8) * 2;
                uint32_t bh0, bh1, bh2, bh3, bl0, bl1, bl2, bl3;
                LDSM_X4(bh0, bh1, bh2, bh3, kh_b + boff);
                LDSM_X4(bl0, bl1, bl2, bl3, kl_b + boff);
                mma_f16(s[2 * p], qh[kt], bh0, bh1);
                mma_f16(s[2 * p], qh[kt], bl0, bl1);
                mma_f16(s[2 * p], ql[kt], bh0, bh1);
                mma_f16(s[2 * p + 1], qh[kt], bh2, bh3);
                mma_f16(s[2 * p + 1], qh[kt], bl2, bl3);
                mma_f16(s[2 * p + 1], ql[kt], bh2, bh3);
            }
        }

        // ---- scale (log2-domain) + mask + online softmax ----
        const bool diag = (it == qb);
        float mx0 = m0, mx1 = m1;
        #pragma unroll
        for (int nt = 0; nt < 8; nt++) {
            int colb = k0 + nt * 8 + tq * 2;
            #pragma unroll
            for (int c = 0; c < 2; c++) {
                float v0 = s[nt][c] * SCALE_L2E;
                float v1 = s[nt][c + 2] * SCALE_L2E;
                if (diag && (colb + c > grow0)) v0 = -1e30f;
                if (diag && (colb + c > grow1)) v1 = -1e30f;
                s[nt][c] = v0; s[nt][c + 2] = v1;
                mx0 = fmaxf(mx0, v0); mx1 = fmaxf(mx1, v1);
            }
        }
        mx0 = fmaxf(mx0, __shfl_xor_sync(0xffffffffu, mx0, 1));
        mx0 = fmaxf(mx0, __shfl_xor_sync(0xffffffffu, mx0, 2));
        mx1 = fmaxf(mx1, __shfl_xor_sync(0xffffffffu, mx1, 1));
        mx1 = fmaxf(mx1, __shfl_xor_sync(0xffffffffu, mx1, 2));

        const float a0 = ex2f(m0 - mx0);
        const float a1 = ex2f(m1 - mx1);
        m0 = mx0; m1 = mx1;

        float sum0 = 0.0f, sum1 = 0.0f;
        #pragma unroll
        for (int nt = 0; nt < 8; nt++) {
            #pragma unroll
            for (int c = 0; c < 2; c++) {
                float p0 = ex2f(s[nt][c] - m0);
                float p1 = ex2f(s[nt][c + 2] - m1);
                s[nt][c] = p0; s[nt][c + 2] = p1;
                sum0 += p0; sum1 += p1;
            }
        }
        sum0 += __shfl_xor_sync(0xffffffffu, sum0, 1);
        sum0 += __shfl_xor_sync(0xffffffffu, sum0, 2);
        sum1 += __shfl_xor_sync(0xffffffffu, sum1, 1);
        sum1 += __shfl_xor_sync(0xffffffffu, sum1, 2);
        l0s = l0s * a0 + sum0;
        l1s = l1s * a1 + sum1;

        #pragma unroll
        for (int nt = 0; nt < 16; nt++) {
            o[nt][0] *= a0; o[nt][1] *= a0;
            o[nt][2] *= a1; o[nt][3] *= a1;
        }

        // ---- O += P @ V (1 combo): P 16x64, Vt 64x128 ----
        #pragma unroll
        for (int kt = 0; kt < 4; kt++) {
            uint32_t ph[4];
            ph[0] = cvt_h2(s[2 * kt][0], s[2 * kt][1]);
            ph[1] = cvt_h2(s[2 * kt][2], s[2 * kt][3]);
            ph[2] = cvt_h2(s[2 * kt + 1][0], s[2 * kt + 1][1]);
            ph[3] = cvt_h2(s[2 * kt + 1][2], s[2 * kt + 1][3]);
            #pragma unroll
            for (int p = 0; p < 8; p++) {
                uint32_t boff = (uint32_t)((p * 16 + brow) * VSTR + kt * 16 + bcol8) * 2;
                uint32_t vh0, vh1, vh2, vh3;
                LDSM_X4(vh0, vh1, vh2, vh3, v_b + boff);
                mma_f16(o[2 * p], ph, vh0, vh1);
                mma_f16(o[2 * p + 1], ph, vh2, vh3);
            }
        }
    }

    // ---- Epilogue: normalize, store single fp16 ----
    const float inv0 = 1.0f / l0s;
    const float inv1 = 1.0f / l1s;
    #pragma unroll
    for (int nt = 0; nt < 16; nt++) {
        int dcol = head * HEAD_DIM + nt * 8 + tq * 2;
        *(uint32_t*)&attn_out[(size_t)grow0 * Q_SIZE + dcol] =
            cvt_h2(o[nt][0] * inv0, o[nt][1] * inv0);
        *(uint32_t*)&attn_out[(size_t)grow1 * Q_SIZE + dcol] =
            cvt_h2(o[nt][2] * inv1, o[nt][3] * inv1);
    }
}

// ---------------------------------------------------------------------------
// Launch
// ---------------------------------------------------------------------------
extern "C" void kernel_launch(void* const* d_in, const int* in_sizes, int n_in,
                              void* d_out, int out_size)
{
    const float* hidden = (const float*)d_in[0];
    const float* qkv_w  = (const float*)d_in[1];
    const float* q_nw   = (const float*)d_in[2];
    const float* k_nw   = (const float*)d_in[3];
    const float* o_w    = (const float*)d_in[4];
    const int*   pos    = (const int*)d_in[5];
    float* out = (float*)d_out;

    const int T = in_sizes[0] / HIDDEN;

    float* qkv;  cudaGetSymbolAddress((void**)&qkv,  g_qkv);
    __half *hid, *w1_h, *w1_l, *w2_h, *w2_l, *at;
    __half *q_h, *q_l, *k_h, *k_l, *v;
    cudaGetSymbolAddress((void**)&hid,  g_hid);
    cudaGetSymbolAddress((void**)&w1_h, g_w1_h);
    cudaGetSymbolAddress((void**)&w1_l, g_w1_l);
    cudaGetSymbolAddress((void**)&w2_h, g_w2_h);
    cudaGetSymbolAddress((void**)&w2_l, g_w2_l);
    cudaGetSymbolAddress((void**)&at,   g_at);
    cudaGetSymbolAddress((void**)&q_h,  g_q_h);
    cudaGetSymbolAddress((void**)&q_l,  g_q_l);
    cudaGetSymbolAddress((void**)&k_h,  g_k_h);
    cudaGetSymbolAddress((void**)&k_l,  g_k_l);
    cudaGetSymbolAddress((void**)&v,    g_v);

    cudaFuncSetAttribute(attn_mma, cudaFuncAttributeMaxDynamicSharedMemorySize,
                         ATT_SMEM);
    cudaFuncSetAttribute(gemm_f16s, cudaFuncAttributeMaxDynamicSharedMemorySize,
                         GEMM_SMEM);

    // 0) Convert/split inputs
    {
        int n4 = T * HIDDEN / 4;
        cvt16_kernel<<<(n4 + 255) / 256, 256>>>(hidden, hid, n4);
        n4 = QKV_COLS * HIDDEN / 4;
        split16_kernel<<<(n4 + 255) / 256, 256>>>(qkv_w, w1_h, w1_l, n4);
        n4 = HIDDEN * Q_SIZE / 4;
        split16_kernel<<<(n4 + 255) / 256, 256>>>(o_w, w2_h, w2_l, n4);
    }
    // 1) QKV projection
    {
        dim3 grid(QKV_COLS / XBN, T / XBM);
        gemm_f16s<<<grid, 256, GEMM_SMEM>>>(hid, w1_h, w1_l, qkv,
                                            T, QKV_COLS, HIDDEN);
    }
    // 2) Fused RMSNorm + RoPE + split (Q, K); transpose V
    {
        int warps = T * 24;
        int blocks = (warps + 7) / 8;
        normrope_split_kernel<<<blocks, 256>>>(qkv, q_nw, k_nw, pos,
                                               q_h, q_l, k_h, k_l, T);
        dim3 vg(T / 32, HEAD_DIM / 32, NUM_KV);
        vtrans_kernel<<<vg, dim3(32, 8)>>>(qkv, v, T);
    }
    // 3) Attention (64-row q blocks, 2 CTAs/SM)
    {
        dim3 grid(T / AQB, NUM_HEADS);
        attn_mma<<<grid, 128, ATT_SMEM>>>(q_h, q_l, k_h, k_l, v, at, T);
    }
    // 4) Output projection
    {
        dim3 grid(HIDDEN / XBN, T / XBM);
        gemm_f16s<<<grid, 256, GEMM_SMEM>>>(at, w2_h, w2_l, out,
                                            T, HIDDEN, HIDDEN);
    }
}

// round 11
// speedup vs baseline: 4.6777x; 1.0344x over previous
#include <cuda_runtime.h>
#include <cuda_bf16.h>
#include <cuda_fp16.h>
#include <math.h>
#include <float.h>
#include <cstdint>

// Problem constants
#define HIDDEN    2048
#define NUM_HEADS 16
#define NUM_KV    8
#define HEAD_DIM  128
#define Q_SIZE    (NUM_HEADS * HEAD_DIM)        // 2048
#define KV_SIZE   (NUM_KV * HEAD_DIM)           // 1024
#define QKV_COLS  (Q_SIZE + 2 * KV_SIZE)        // 4096
#define SCALE     0.08838834764831845f          // 128^-0.5
#define SCALE_L2E 0.12751985675839602f          // SCALE * log2(e)
#define RMS_EPS   1e-6f

#define MAX_T 4096

// Scratch (static device globals)
__device__ float g_qkv[(size_t)MAX_T * QKV_COLS];
__device__ __half g_hid[(size_t)MAX_T * HIDDEN];
__device__ __half g_w1_h[(size_t)QKV_COLS * HIDDEN];
__device__ __half g_w1_l[(size_t)QKV_COLS * HIDDEN];
__device__ __half g_w2_h[(size_t)HIDDEN * Q_SIZE];
__device__ __half g_w2_l[(size_t)HIDDEN * Q_SIZE];
__device__ __half g_at[(size_t)MAX_T * Q_SIZE];
__device__ __half g_q[(size_t)MAX_T * Q_SIZE];              // single fp16 Q
__device__ __half g_k_h[(size_t)NUM_KV * MAX_T * HEAD_DIM];
__device__ __half g_k_l[(size_t)NUM_KV * MAX_T * HEAD_DIM];
__device__ __half g_v[(size_t)NUM_KV * HEAD_DIM * MAX_T];   // [kvh][d][t]

// ===========================================================================
// Helpers
// ===========================================================================
__device__ __forceinline__ uint32_t smem_to_u32(const void* p) {
    uint32_t a;
    asm("{ .reg .u64 t; cvta.to.shared.u64 t, %1; cvt.u32.u64 %0, t; }"
        : "=r"(a) : "l"(p));
    return a;
}
__device__ __forceinline__ void split_h16(float x, __half& h, __half& l) {
    h = __float2half_rn(x);
    l = __float2half_rn(x - __half2float(h));
}
__device__ __forceinline__ float ex2f(float x) {
    float r;
    asm("ex2.approx.f32 %0, %1;" : "=f"(r) : "f"(x));
    return r;
}
__device__ __forceinline__ uint32_t cvt_h2(float a, float b) {
    uint32_t r;
    asm("cvt.rn.f16x2.f32 %0, %1, %2;" : "=r"(r) : "f"(b), "f"(a));
    return r;
}
__device__ __forceinline__ uint32_t pack_h2(__half a, __half b) {
    __half2 t = __halves2half2(a, b);
    return *reinterpret_cast<uint32_t*>(&t);
}

__device__ __forceinline__ void mma_f16(float* d, const uint32_t* a,
                                        uint32_t b0, uint32_t b1) {
    asm volatile(
        "mma.sync.aligned.m16n8k16.row.col.f32.f16.f16.f32 "
        "{%0,%1,%2,%3}, {%4,%5,%6,%7}, {%8,%9}, {%0,%1,%2,%3};"
        : "+f"(d[0]), "+f"(d[1]), "+f"(d[2]), "+f"(d[3])
        : "r"(a[0]), "r"(a[1]), "r"(a[2]), "r"(a[3]), "r"(b0), "r"(b1));
}

#define LDSM_X4(r0, r1, r2, r3, addr) \
    asm volatile("ldmatrix.sync.aligned.m8n8.x4.shared.b16 {%0,%1,%2,%3}, [%4];" \
        : "=r"(r0), "=r"(r1), "=r"(r2), "=r"(r3) : "r"(addr))

#define CP_ASYNC16(dst, src) \
    asm volatile("cp.async.cg.shared.global [%0], [%1], 16;" \
        :: "r"(dst), "l"(src))
#define CP_COMMIT() asm volatile("cp.async.commit_group;")
#define CP_WAIT(n)  asm volatile("cp.async.wait_group %0;" :: "n"(n))

// ---------------------------------------------------------------------------
// Pre/post kernels
// ---------------------------------------------------------------------------
__global__ __launch_bounds__(256) void cvt16_kernel(
    const float* __restrict__ src, __half* __restrict__ dst, int n4)
{
    int i = blockIdx.x * blockDim.x + threadIdx.x;
    if (i >= n4) return;
    float4 v = ((const float4*)src)[i];
    uint2 u;
    u.x = cvt_h2(v.x, v.y);
    u.y = cvt_h2(v.z, v.w);
    ((uint2*)dst)[i] = u;
}

__global__ __launch_bounds__(256) void split16_kernel(
    const float* __restrict__ src, __half* __restrict__ h,
    __half* __restrict__ l, int n4)
{
    int i = blockIdx.x * blockDim.x + threadIdx.x;
    if (i >= n4) return;
    float4 v = ((const float4*)src)[i];
    __half h0, h1, h2, h3, l0, l1, l2, l3;
    split_h16(v.x, h0, l0); split_h16(v.y, h1, l1);
    split_h16(v.z, h2, l2); split_h16(v.w, h3, l3);
    uint2 uh; uh.x = pack_h2(h0, h1); uh.y = pack_h2(h2, h3);
    uint2 ul; ul.x = pack_h2(l0, l1); ul.y = pack_h2(l2, l3);
    ((uint2*)h)[i] = uh;
    ((uint2*)l)[i] = ul;
}

// Fused RMSNorm + RoPE. Q -> single fp16; K -> fp16 hi/lo.
__global__ __launch_bounds__(256) void normrope_split_kernel(
    const float* __restrict__ qkv,
    const float* __restrict__ qw, const float* __restrict__ kw,
    const int* __restrict__ positions,
    __half* __restrict__ q_g,
    __half* __restrict__ kh_g, __half* __restrict__ kl_g, int T)
{
    const int warp = (blockIdx.x * blockDim.x + threadIdx.x) >> 5;
    const int lane = threadIdx.x & 31;
    if (warp >= T * 24) return;
    const int t = warp / 24;
    const int h = warp % 24;

    const float* x = qkv + (size_t)t * QKV_COLS + h * HEAD_DIM;
    const float* nw = (h < 16) ? qw : kw;

    float v0 = x[lane], v1 = x[lane + 32], v2 = x[lane + 64], v3 = x[lane + 96];
    float ss = v0 * v0 + v1 * v1 + v2 * v2 + v3 * v3;
    #pragma unroll
    for (int o = 16; o; o >>= 1) ss += __shfl_xor_sync(0xffffffffu, ss, o);
    const float rn = rsqrtf(ss * (1.0f / HEAD_DIM) + RMS_EPS);

    float n0 = v0 * rn * nw[lane];
    float n1 = v1 * rn * nw[lane + 32];
    float n2 = v2 * rn * nw[lane + 64];
    float n3 = v3 * rn * nw[lane + 96];

    const double pos = (double)positions[t];
    const double LOG_THETA = 13.815510557964274;
    double f0 = exp(-((double)(2 * lane) / 128.0) * LOG_THETA);
    double f1 = exp(-((double)(2 * (lane + 32)) / 128.0) * LOG_THETA);
    double s0d, c0d, s1d, c1d;
    sincos(pos * f0, &s0d, &c0d);
    sincos(pos * f1, &s1d, &c1d);
    float c0 = (float)c0d, s0 = (float)s0d, c1 = (float)c1d, s1 = (float)s1d;

    float r0 = n0 * c0 - n2 * s0;
    float r2 = n2 * c0 + n0 * s0;
    float r1 = n1 * c1 - n3 * s1;
    float r3 = n3 * c1 + n1 * s1;

    if (h < 16) {
        size_t base = (size_t)t * Q_SIZE + h * HEAD_DIM;
        q_g[base + lane]      = __float2half_rn(r0);
        q_g[base + lane + 32] = __float2half_rn(r1);
        q_g[base + lane + 64] = __float2half_rn(r2);
        q_g[base + lane + 96] = __float2half_rn(r3);
    } else {
        size_t base = (size_t)(h - 16) * T * HEAD_DIM + (size_t)t * HEAD_DIM;
        __half h0, l0, h1, l1, h2, l2, h3, l3;
        split_h16(r0, h0, l0); split_h16(r1, h1, l1);
        split_h16(r2, h2, l2); split_h16(r3, h3, l3);
        kh_g[base + lane] = h0;      kl_g[base + lane] = l0;
        kh_g[base + lane + 32] = h1; kl_g[base + lane + 32] = l1;
        kh_g[base + lane + 64] = h2; kl_g[base + lane + 64] = l2;
        kh_g[base + lane + 96] = h3; kl_g[base + lane + 96] = l3;
    }
}

__global__ void vtrans_kernel(
    const float* __restrict__ qkv, __half* __restrict__ vh, int T)
{
    __shared__ float tile[32][33];
    const int kvh = blockIdx.z;
    const int d0 = blockIdx.y * 32;
    const int t0 = blockIdx.x * 32;
    for (int j = threadIdx.y; j < 32; j += 8) {
        tile[j][threadIdx.x] = qkv[(size_t)(t0 + j) * QKV_COLS + Q_SIZE + KV_SIZE
                                   + kvh * HEAD_DIM + d0 + threadIdx.x];
    }
    __syncthreads();
    for (int j = threadIdx.y; j < 32; j += 8) {
        float v = tile[threadIdx.x][j];
        size_t o = (size_t)kvh * HEAD_DIM * T + (size_t)(d0 + j) * T + t0 + threadIdx.x;
        vh[o] = __float2half_rn(v);
    }
}

// ---------------------------------------------------------------------------
// fp16 HMMA GEMM, 2 combos (unchanged)
// ---------------------------------------------------------------------------
#define XBM 128
#define XBN 128
#define XBK 32
#define XSTR 40
#define STAGE_E (XBM * XSTR)
#define GEMM_SMEM (6 * STAGE_E * 2)

__global__ __launch_bounds__(256, 2) void gemm_f16s(
    const __half* __restrict__ A,
    const __half* __restrict__ Bh, const __half* __restrict__ Bl,
    float* __restrict__ C, int M, int N, int K)
{
    extern __shared__ __half smg[];
    const uint32_t smb = smem_to_u32(smg);

    const int tid  = threadIdx.x;
    const int lane = tid & 31;
    const int wid  = tid >> 5;
    const int gid  = lane >> 2;
    const int tq   = lane & 3;
    const int wm   = (wid & 3) * 32;
    const int wn   = (wid >> 2) * 64;

    const int arow  = lane & 15;
    const int acol8 = (lane >> 4) << 3;
    const int brow  = ((lane >> 4) << 3) + (lane & 7);
    const int bcol8 = ((lane >> 3) & 1) << 3;

    const int bm = blockIdx.y * XBM;
    const int bn = blockIdx.x * XBN;

    #define G_ISSUE(stage, k0) do { \
        uint32_t sb0 = smb + (uint32_t)(stage) * 3 * STAGE_E * 2; \
        _Pragma("unroll") \
        for (int j = 0; j < 2; j++) { \
            int id = tid + j * 256; \
            int r = id >> 2, c = (id & 3) * 8; \
            size_t aoff = (size_t)(bm + r) * K + (k0) + c; \
            size_t boff = (size_t)(bn + r) * K + (k0) + c; \
            uint32_t doff = (uint32_t)(r * XSTR + c) * 2; \
            CP_ASYNC16(sb0 + doff, A + aoff); \
            CP_ASYNC16(sb0 + STAGE_E * 2 + doff, Bh + boff); \
            CP_ASYNC16(sb0 + 2 * STAGE_E * 2 + doff, Bl + boff); \
        } \
    } while (0)

    float acc[2][8][4] = {};

    G_ISSUE(0, 0);
    CP_COMMIT();

    int stage = 0;
    for (int k0 = 0; k0 < K; k0 += XBK, stage ^= 1) {
        if (k0 + XBK < K) {
            G_ISSUE(stage ^ 1, k0 + XBK);
            CP_COMMIT();
            CP_WAIT(1);
        } else {
            CP_WAIT(0);
        }
        __syncthreads();

        const uint32_t sA  = smb + (uint32_t)stage * 3 * STAGE_E * 2;
        const uint32_t sBh = sA + STAGE_E * 2;
        const uint32_t sBl = sBh + STAGE_E * 2;

        #pragma unroll
        for (int kk = 0; kk < XBK; kk += 16) {
            uint32_t a[2][4];
            #pragma unroll
            for (int mt = 0; mt < 2; mt++) {
                uint32_t aoff = (uint32_t)((wm + mt * 16 + arow) * XSTR + kk + acol8) * 2;
                LDSM_X4(a[mt][0], a[mt][1], a[mt][2], a[mt][3], sA + aoff);
            }
            #pragma unroll
            for (int p = 0; p < 4; p++) {
                uint32_t boff = (uint32_t)((wn + p * 16 + brow) * XSTR + kk + bcol8) * 2;
                uint32_t bh0, bh1, bh2, bh3, bl0, bl1, bl2, bl3;
                LDSM_X4(bh0, bh1, bh2, bh3, sBh + boff);
                LDSM_X4(bl0, bl1, bl2, bl3, sBl + boff);
                #pragma unroll
                for (int mt = 0; mt < 2; mt++) {
                    mma_f16(acc[mt][2 * p], a[mt], bh0, bh1);
                    mma_f16(acc[mt][2 * p], a[mt], bl0, bl1);
                    mma_f16(acc[mt][2 * p + 1], a[mt], bh2, bh3);
                    mma_f16(acc[mt][2 * p + 1], a[mt], bl2, bl3);
                }
            }
        }
        __syncthreads();
    }

    #pragma unroll
    for (int mt = 0; mt < 2; mt++) {
        int row = bm + wm + mt * 16 + gid;
        #pragma unroll
        for (int nt = 0; nt < 8; nt++) {
            int col = bn + wn + nt * 8 + tq * 2;
            *(float2*)&C[(size_t)row * N + col] =
                make_float2(acc[mt][nt][0], acc[mt][nt][1]);
            *(float2*)&C[(size_t)(row + 8) * N + col] =
                make_float2(acc[mt][nt][2], acc[mt][nt][3]);
        }
    }
}

// ---------------------------------------------------------------------------
// fp16 HMMA flash attention — q block 64, kv tile 32, 128 threads,
// 3 CTAs/SM (12 warps/SM). QK 2 combos (Q single fp16 x K hi/lo);
// PV 1 combo. Double-buffered, one sync per iteration.
// ---------------------------------------------------------------------------
#define AQB 64                          // q rows per CTA
#define AKB 32                          // kv rows per tile
#define SSTR 136                        // K row stride (128 d + 8 pad)
#define VSTR 40                         // V row stride (32 t + 8 pad)
#define KT_B (AKB * SSTR * 2)           // 8704 B per K buffer
#define VT_B (HEAD_DIM * VSTR * 2)      // 10240 B per V buffer
// layout: K0h K0l K1h K1l V0 V1
#define OFF_K(s)  ((uint32_t)(s) * 2u * KT_B)
#define OFF_KL(s) (OFF_K(s) + KT_B)
#define OFF_V(s)  (4u * KT_B + (uint32_t)(s) * VT_B)
#define ATT_SMEM  (4 * KT_B + 2 * VT_B) // 55296 B

__global__ __launch_bounds__(128, 3) void attn_mma(
    const __half* __restrict__ q_g,
    const __half* __restrict__ kh_g, const __half* __restrict__ kl_g,
    const __half* __restrict__ v_g,
    __half* __restrict__ attn_out, int T)
{
    extern __shared__ char sm[];
    const uint32_t smb = smem_to_u32(sm);
    const int tid  = threadIdx.x;
    const int lane = tid & 31;
    const int wid  = tid >> 5;          // 0..3
    const int gid  = lane >> 2;
    const int tq   = lane & 3;

    const int qb   = (gridDim.x - 1) - blockIdx.x;   // big blocks first
    const int head = blockIdx.y;
    const int kvh  = head >> 1;
    const int q0   = qb * AQB;
    const int wrow = wid * 16;
    const int iters = 2 * qb + 2;

    const int arow  = lane & 15;
    const int acol8 = (lane >> 4) << 3;
    const int brow  = ((lane >> 4) << 3) + (lane & 7);
    const int bcol8 = ((lane >> 3) & 1) << 3;

    const size_t kbase = (size_t)kvh * T * HEAD_DIM;
    const size_t vbase = (size_t)kvh * HEAD_DIM * T;

    // Prefetch kv tile `itn` into stage itn&1.
    // K: 32 rows x 128 d (hi+lo) = 512 uint4 each. V: 128 d x 32 t = 512 uint4.
    #define ATT_PREFETCH(itn) do { \
        const int st_ = (itn) & 1; \
        const uint32_t khb_ = smb + OFF_K(st_); \
        const uint32_t klb_ = smb + OFF_KL(st_); \
        const uint32_t vb_  = smb + OFF_V(st_); \
        const size_t ko_ = kbase + (size_t)(itn) * AKB * HEAD_DIM; \
        const size_t vo_ = vbase + (size_t)(itn) * AKB; \
        for (int i = tid; i < 512; i += 128) { \
            int r_ = i >> 4, c_ = (i & 15) << 3; \
            uint32_t doff_ = (uint32_t)(r_ * SSTR + c_) * 2; \
            CP_ASYNC16(khb_ + doff_, kh_g + ko_ + (size_t)r_ * HEAD_DIM + c_); \
            CP_ASYNC16(klb_ + doff_, kl_g + ko_ + (size_t)r_ * HEAD_DIM + c_); \
            int d_ = i >> 2, vc_ = (i & 3) << 3; \
            uint32_t vdoff_ = (uint32_t)(d_ * VSTR + vc_) * 2; \
            CP_ASYNC16(vb_ + vdoff_, v_g + vo_ + (size_t)d_ * T + vc_); \
        } \
        CP_COMMIT(); \
    } while (0)

    // ---- Prologue: prefetch tile 0 into stage 0 ----
    ATT_PREFETCH(0);

    // Stage Q (64 x 128, single fp16) through stage-1 K region (17408 B)
    {
        const uint32_t qsb = smb + OFF_K(1);
        for (int i = tid; i < 512; i += 128) {
            int r = i >> 3, c = (i & 7) << 4;   // 64 rows x 8 chunks of 16
            uint32_t doff = (uint32_t)(r * SSTR + c) * 2;
            size_t o = (size_t)(q0 + r) * Q_SIZE + head * HEAD_DIM + c;
            *(uint4*)(sm + (qsb - smb) + doff)      = *(const uint4*)&q_g[o];
            *(uint4*)(sm + (qsb - smb) + doff + 16) = *(const uint4*)&q_g[o + 8];
        }
        __syncthreads();
    }

    uint32_t qh[8][4];
    {
        const uint32_t qsb = smb + OFF_K(1);
        #pragma unroll
        for (int kt = 0; kt < 8; kt++) {
            uint32_t aoff = (uint32_t)((wrow + arow) * SSTR + kt * 16 + acol8) * 2;
            LDSM_X4(qh[kt][0], qh[kt][1], qh[kt][2], qh[kt][3], qsb + aoff);
        }
    }
    // First loop sync (it=0) orders frag-build before prefetch(1) overwrites.

    const int grow0 = q0 + wrow + gid;
    const int grow1 = grow0 + 8;

    float m0 = -1e30f, m1 = -1e30f, l0s = 0.0f, l1s = 0.0f;
    float o[16][4] = {};

    for (int it = 0; it < iters; it++) {
        const int k0 = it * AKB;
        const int st = it & 1;
        const uint32_t kh_b = smb + OFF_K(st);
        const uint32_t kl_b = smb + OFF_KL(st);
        const uint32_t v_b  = smb + OFF_V(st);

        CP_WAIT(0);
        __syncthreads();

        if (it + 1 < iters) ATT_PREFETCH(it + 1);

        // ---- S = Q K^T (2 combos): warp 16 x 32 ----
        float s[4][4];
        #pragma unroll
        for (int nt = 0; nt < 4; nt++)
            #pragma unroll
            for (int c = 0; c < 4; c++) s[nt][c] = 0.0f;

        #pragma unroll
        for (int kt = 0; kt < 8; kt++) {
            #pragma unroll
            for (int p = 0; p < 2; p++) {
                uint32_t boff = (uint32_t)((p * 16 + brow) * SSTR + kt * 16 + bcol8) * 2;
                uint32_t bh0, bh1, bh2, bh3, bl0, bl1, bl2, bl3;
                LDSM_X4(bh0, bh1, bh2, bh3, kh_b + boff);
                LDSM_X4(bl0, bl1, bl2, bl3, kl_b + boff);
                mma_f16(s[2 * p], qh[kt], bh0, bh1);
                mma_f16(s[2 * p], qh[kt], bl0, bl1);
                mma_f16(s[2 * p + 1], qh[kt], bh2, bh3);
                mma_f16(s[2 * p + 1], qh[kt], bl2, bl3);
            }
        }

        // ---- scale (log2-domain) + mask + online softmax ----
        const bool diag = (it >= 2 * qb);
        float mx0 = m0, mx1 = m1;
        #pragma unroll
        for (int nt = 0; nt < 4; nt++) {
            int colb = k0 + nt * 8 + tq * 2;
            #pragma unroll
            for (int c = 0; c < 2; c++) {
                float v0 = s[nt][c] * SCALE_L2E;
                float v1 = s[nt][c + 2] * SCALE_L2E;
                if (diag && (colb + c > grow0)) v0 = -1e30f;
                if (diag && (colb + c > grow1)) v1 = -1e30f;
                s[nt][c] = v0; s[nt][c + 2] = v1;
                mx0 = fmaxf(mx0, v0); mx1 = fmaxf(mx1, v1);
            }
        }
        mx0 = fmaxf(mx0, __shfl_xor_sync(0xffffffffu, mx0, 1));
        mx0 = fmaxf(mx0, __shfl_xor_sync(0xffffffffu, mx0, 2));
        mx1 = fmaxf(mx1, __shfl_xor_sync(0xffffffffu, mx1, 1));
        mx1 = fmaxf(mx1, __shfl_xor_sync(0xffffffffu, mx1, 2));

        const float a0 = ex2f(m0 - mx0);
        const float a1 = ex2f(m1 - mx1);
        m0 = mx0; m1 = mx1;

        float sum0 = 0.0f, sum1 = 0.0f;
        #pragma unroll
        for (int nt = 0; nt < 4; nt++) {
            #pragma unroll
            for (int c = 0; c < 2; c++) {
                float p0 = ex2f(s[nt][c] - m0);
                float p1 = ex2f(s[nt][c + 2] - m1);
                s[nt][c] = p0; s[nt][c + 2] = p1;
                sum0 += p0; sum1 += p1;
            }
        }
        sum0 += __shfl_xor_sync(0xffffffffu, sum0, 1);
        sum0 += __shfl_xor_sync(0xffffffffu, sum0, 2);
        sum1 += __shfl_xor_sync(0xffffffffu, sum1, 1);
        sum1 += __shfl_xor_sync(0xffffffffu, sum1, 2);
        l0s = l0s * a0 + sum0;
        l1s = l1s * a1 + sum1;

        #pragma unroll
        for (int nt = 0; nt < 16; nt++) {
            o[nt][0] *= a0; o[nt][1] *= a0;
            o[nt][2] *= a1; o[nt][3] *= a1;
        }

        // ---- O += P @ V (1 combo): P 16x32, Vt 32x128 ----
        #pragma unroll
        for (int kt = 0; kt < 2; kt++) {
            uint32_t ph[4];
            ph[0] = cvt_h2(s[2 * kt][0], s[2 * kt][1]);
            ph[1] = cvt_h2(s[2 * kt][2], s[2 * kt][3]);
            ph[2] = cvt_h2(s[2 * kt + 1][0], s[2 * kt + 1][1]);
            ph[3] = cvt_h2(s[2 * kt + 1][2], s[2 * kt + 1][3]);
            #pragma unroll
            for (int p = 0; p < 8; p++) {
                uint32_t boff = (uint32_t)((p * 16 + brow) * VSTR + kt * 16 + bcol8) * 2;
                uint32_t vh0, vh1, vh2, vh3;
                LDSM_X4(vh0, vh1, vh2, vh3, v_b + boff);
                mma_f16(o[2 * p], ph, vh0, vh1);
                mma_f16(o[2 * p + 1], ph, vh2, vh3);
            }
        }
    }

    // ---- Epilogue: normalize, store single fp16 ----
    const float inv0 = 1.0f / l0s;
    const float inv1 = 1.0f / l1s;
    #pragma unroll
    for (int nt = 0; nt < 16; nt++) {
        int dcol = head * HEAD_DIM + nt * 8 + tq * 2;
        *(uint32_t*)&attn_out[(size_t)grow0 * Q_SIZE + dcol] =
            cvt_h2(o[nt][0] * inv0, o[nt][1] * inv0);
        *(uint32_t*)&attn_out[(size_t)grow1 * Q_SIZE + dcol] =
            cvt_h2(o[nt][2] * inv1, o[nt][3] * inv1);
    }
}

// ---------------------------------------------------------------------------
// Launch
// ---------------------------------------------------------------------------
extern "C" void kernel_launch(void* const* d_in, const int* in_sizes, int n_in,
                              void* d_out, int out_size)
{
    const float* hidden = (const float*)d_in[0];
    const float* qkv_w  = (const float*)d_in[1];
    const float* q_nw   = (const float*)d_in[2];
    const float* k_nw   = (const float*)d_in[3];
    const float* o_w    = (const float*)d_in[4];
    const int*   pos    = (const int*)d_in[5];
    float* out = (float*)d_out;

    const int T = in_sizes[0] / HIDDEN;

    float* qkv;  cudaGetSymbolAddress((void**)&qkv,  g_qkv);
    __half *hid, *w1_h, *w1_l, *w2_h, *w2_l, *at;
    __half *q, *k_h, *k_l, *v;
    cudaGetSymbolAddress((void**)&hid,  g_hid);
    cudaGetSymbolAddress((void**)&w1_h, g_w1_h);
    cudaGetSymbolAddress((void**)&w1_l, g_w1_l);
    cudaGetSymbolAddress((void**)&w2_h, g_w2_h);
    cudaGetSymbolAddress((void**)&w2_l, g_w2_l);
    cudaGetSymbolAddress((void**)&at,   g_at);
    cudaGetSymbolAddress((void**)&q,    g_q);
    cudaGetSymbolAddress((void**)&k_h,  g_k_h);
    cudaGetSymbolAddress((void**)&k_l,  g_k_l);
    cudaGetSymbolAddress((void**)&v,    g_v);

    cudaFuncSetAttribute(attn_mma, cudaFuncAttributeMaxDynamicSharedMemorySize,
                         ATT_SMEM);
    cudaFuncSetAttribute(gemm_f16s, cudaFuncAttributeMaxDynamicSharedMemorySize,
                         GEMM_SMEM);

    // 0) Convert/split inputs
    {
        int n4 = T * HIDDEN / 4;
        cvt16_kernel<<<(n4 + 255) / 256, 256>>>(hidden, hid, n4);
        n4 = QKV_COLS * HIDDEN / 4;
        split16_kernel<<<(n4 + 255) / 256, 256>>>(qkv_w, w1_h, w1_l, n4);
        n4 = HIDDEN * Q_SIZE / 4;
        split16_kernel<<<(n4 + 255) / 256, 256>>>(o_w, w2_h, w2_l, n4);
    }
    // 1) QKV projection
    {
        dim3 grid(QKV_COLS / XBN, T / XBM);
        gemm_f16s<<<grid, 256, GEMM_SMEM>>>(hid, w1_h, w1_l, qkv,
                                            T, QKV_COLS, HIDDEN);
    }
    // 2) Fused RMSNorm + RoPE + split (Q single, K hi/lo); transpose V
    {
        int warps = T * 24;
        int blocks = (warps + 7) / 8;
        normrope_split_kernel<<<blocks, 256>>>(qkv, q_nw, k_nw, pos,
                                               q, k_h, k_l, T);
        dim3 vg(T / 32, HEAD_DIM / 32, NUM_KV);
        vtrans_kernel<<<vg, dim3(32, 8)>>>(qkv, v, T);
    }
    // 3) Attention (q64 x kv32, 3 CTAs/SM)
    {
        dim3 grid(T / AQB, NUM_HEADS);
        attn_mma<<<grid, 128, ATT_SMEM>>>(q, k_h, k_l, v, at, T);
    }
    // 4) Output projection
    {
        dim3 grid(HIDDEN / XBN, T / XBM);
        gemm_f16s<<<grid, 256, GEMM_SMEM>>>(at, w2_h, w2_l, out,
                                            T, HIDDEN, HIDDEN);
    }
}